// round 10
// baseline (speedup 1.0000x reference)
#include <cuda_runtime.h>
#include <cuda_fp16.h>
#include <math.h>

#define NN 100000
#define MM 800000
#define KK 6
#define HH 64
#define NHD 4
#define DHD 16
#define NBLK 98   // ceil(NN/1024)
#define WSTR 66   // padded transposed-weight row stride (floats)

typedef unsigned long long ull;

// ---------------- packed f32x2 helpers (sm_103a FFMA2 path) ----------------
__device__ __forceinline__ ull pack2(float lo, float hi) {
    ull r;
    asm("mov.b64 %0, {%1, %2};" : "=l"(r) : "f"(lo), "f"(hi));
    return r;
}
__device__ __forceinline__ void ffma2(ull& d, ull a, ull b) {
    asm("fma.rn.f32x2 %0, %1, %2, %0;" : "+l"(d) : "l"(a), "l"(b));
}
__device__ __forceinline__ float2 unpack2(ull v) {
    float lo, hi;
    asm("mov.b64 {%0, %1}, %2;" : "=f"(lo), "=f"(hi) : "l"(v));
    return make_float2(lo, hi);
}
__device__ __forceinline__ float hsum2(ull v) {
    float2 p = unpack2(v);
    return p.x + p.y;
}
__device__ __forceinline__ float hsum4(ull a, ull b) {
    float2 pa = unpack2(a), pb = unpack2(b);
    return (pa.x + pa.y) + (pb.x + pb.y);
}
// streaming 16-bit store (evict-first: kv is write-once/read-once)
__device__ __forceinline__ void sth_cs(__half* p, float v) {
    unsigned short u = __half_as_ushort(__float2half(v));
    asm volatile("st.global.cs.u16 [%0], %1;" :: "l"(p), "h"(u) : "memory");
}

// ---------------- scratch (device globals; allocation-free) ----------------
__device__ __half g_hh[NN * KK * HH];     // hs = tanh(proj)*dinv, fp16 (76.8 MB)
__device__ __half g_kvh[NN * KK * 128];   // per (n,k): [k(64)|v(64)] fp16 (153.6 MB)
__device__ float g_h2r5[NN * HH];         // post-GCN relu, row k=5 (residual + q input)
__device__ float g_pa[NN * HH];
__device__ float g_pb[NN * HH];
__device__ float g_dinv[NN];
__device__ int   g_counts[NN];
__device__ int   g_rowstart[NN + 1];
__device__ int   g_cursor[NN];
__device__ int   g_srclist[MM];
// decoupled-lookback scan state (reset every replay by k_init)
__device__ volatile int g_statev[NBLK];
__device__ volatile int g_aggv[NBLK];
__device__ volatile int g_incv[NBLK];

// ---------------- init (zeros all cross-replay state) ----------------
__global__ void k_init() {
    int i = blockIdx.x * blockDim.x + threadIdx.x;
    if (i < NN) g_counts[i] = 0;
    if (i < NBLK) g_statev[i] = 0;
    if (i == 0) g_rowstart[NN] = MM;
}

__global__ void k_count(const int* __restrict__ ei) {
    int e = blockIdx.x * blockDim.x + threadIdx.x;
    if (e < MM) atomicAdd(&g_counts[ei[MM + e]], 1);
}

// ---------------- single-pass scan (decoupled lookback; 98 tiles co-resident) -------
__global__ __launch_bounds__(1024) void k_scanall() {
    __shared__ int warpsums[32];
    __shared__ int exoff_s;
    int t = threadIdx.x, lane = t & 31, w = t >> 5;
    int bid = blockIdx.x;
    int i = bid * 1024 + t;
    int v0 = (i < NN) ? g_counts[i] : 0;
    if (i < NN) g_dinv[i] = rsqrtf((float)v0 + 1.0f);
    int v = v0;
#pragma unroll
    for (int off = 1; off < 32; off <<= 1) {
        int x = __shfl_up_sync(0xffffffffu, v, off);
        if (lane >= off) v += x;
    }
    if (lane == 31) warpsums[w] = v;
    __syncthreads();
    if (w == 0) {
        int s = warpsums[lane];
#pragma unroll
        for (int off = 1; off < 32; off <<= 1) {
            int x = __shfl_up_sync(0xffffffffu, s, off);
            if (lane >= off) s += x;
        }
        warpsums[lane] = s;
    }
    __syncthreads();
    int incl = v + (w > 0 ? warpsums[w - 1] : 0);
    if (t == 0) {
        int tot = warpsums[31];
        g_aggv[bid] = tot;
        __threadfence();
        g_statev[bid] = 1;
        int exc = 0;
        if (bid > 0) {
            int p = bid - 1;
            while (true) {
                int st;
                do { st = g_statev[p]; } while (st == 0);
                if (st == 2) { exc += g_incv[p]; break; }
                exc += g_aggv[p];
                if (--p < 0) break;
            }
        }
        g_incv[bid] = exc + tot;
        __threadfence();
        g_statev[bid] = 2;
        exoff_s = exc;
    }
    __syncthreads();
    if (i < NN) {
        int excl = exoff_s + incl - v0;
        g_rowstart[i] = excl;
        g_cursor[i]   = excl;
    }
}

__global__ void k_fill(const int* __restrict__ ei) {
    int e = blockIdx.x * blockDim.x + threadIdx.x;
    if (e < MM) {
        int d = ei[MM + e];
        int p = atomicAdd(&g_cursor[d], 1);
        g_srclist[p] = ei[e];
    }
}

// ---------------- projection (+ inline ck): hs = tanh(dot12 + ck)*dinv, fp16 --------
__global__ __launch_bounds__(256) void k_projck(
    const float* __restrict__ x, const float* __restrict__ W_proj,
    const float* __restrict__ b_proj, const float* __restrict__ u,
    const float* __restrict__ u_seq) {
    __shared__ float Wp12[12 * HH];
    __shared__ float cks[KK * HH];
    int t = threadIdx.x;
    for (int i = t; i < 12 * HH; i += 256) Wp12[i] = W_proj[i];
    if (t < HH) {
        int c = t;
        float base = b_proj[c];
#pragma unroll
        for (int j = 0; j < 11; j++) base += u[j] * W_proj[(12 + j) * HH + c];
#pragma unroll
        for (int k = 0; k < KK; k++) {
            float val = base;
#pragma unroll
            for (int j = 0; j < 5; j++) val += u_seq[k * 5 + j] * W_proj[(23 + j) * HH + c];
            cks[k * HH + c] = val;
        }
    }
    __syncthreads();
    int g = t >> 6, c = t & 63;
    int n = blockIdx.x * 4 + g;
    float dn = g_dinv[n];
    float s = 0.f;
#pragma unroll
    for (int j = 0; j < 12; j++) s += __ldg(&x[n * 12 + j]) * Wp12[j * HH + c];
    int base = n * (KK * HH) + c;
#pragma unroll
    for (int k = 0; k < KK; k++)
        g_hh[base + k * HH] = __float2half(tanhf(s + cks[k * HH + c]) * dn);
}

// ---------------- fused AGGREGATE + GCN + KV (warp per node, 2 CTAs/SM) -------------
struct __align__(16) SG {
    float Wgt[HH * WSTR];       // Wgt[c*66+j] = W_gcn[j][c]
    float Wkvt[128 * WSTR];     // Wkvt[c*66+j] = [Wk|Wv][j][c]
    float arow[12][KK][HH];
    float h2s[12][KK][HH];
    float bg[HH], bkv[128];
};

__global__ __launch_bounds__(384, 2) void k_gcnqkv(
    const float* __restrict__ W_gcn, const float* __restrict__ b_gcn,
    const float* __restrict__ Wk, const float* __restrict__ bk,
    const float* __restrict__ Wv, const float* __restrict__ bv) {
    extern __shared__ char smem_raw[];
    SG& s = *reinterpret_cast<SG*>(smem_raw);
    int t = threadIdx.x, w = t >> 5, l = t & 31;
    for (int i = t; i < HH * HH; i += 384) {
        int j = i >> 6, c = i & 63;
        s.Wgt[c * WSTR + j] = W_gcn[i];
        s.Wkvt[c * WSTR + j] = Wk[i];
        s.Wkvt[(c + 64) * WSTR + j] = Wv[i];
    }
    if (t < HH) { s.bg[t] = b_gcn[t]; s.bkv[t] = bk[t]; s.bkv[64 + t] = bv[t]; }
    __syncthreads();
    const int c0 = l, c1 = l + 32;
    const __half2* hh2 = (const __half2*)g_hh;
    for (int n = blockIdx.x * 12 + w; n < NN; n += gridDim.x * 12) {
        // stage 0: aggregate (4-way unrolled gather)
        {
            float dn = g_dinv[n];
            int s0 = g_rowstart[n], s1 = g_rowstart[n + 1];
            float2 acc[KK];
#pragma unroll
            for (int r = 0; r < KK; r++)
                acc[r] = __half22float2(hh2[(n * KK + r) * 32 + l]);
            int i = s0;
            for (; i + 3 < s1; i += 4) {
                const __half2* pa = hh2 + g_srclist[i]     * (KK * 32) + l;
                const __half2* pb = hh2 + g_srclist[i + 1] * (KK * 32) + l;
                const __half2* pc = hh2 + g_srclist[i + 2] * (KK * 32) + l;
                const __half2* pd = hh2 + g_srclist[i + 3] * (KK * 32) + l;
#pragma unroll
                for (int r = 0; r < KK; r++) {
                    float2 va = __half22float2(pa[r * 32]);
                    float2 vb = __half22float2(pb[r * 32]);
                    float2 vc = __half22float2(pc[r * 32]);
                    float2 vd = __half22float2(pd[r * 32]);
                    acc[r].x += (va.x + vb.x) + (vc.x + vd.x);
                    acc[r].y += (va.y + vb.y) + (vc.y + vd.y);
                }
            }
            for (; i < s1; i++) {
                const __half2* pa = hh2 + g_srclist[i] * (KK * 32) + l;
#pragma unroll
                for (int r = 0; r < KK; r++) {
                    float2 va = __half22float2(pa[r * 32]);
                    acc[r].x += va.x;
                    acc[r].y += va.y;
                }
            }
#pragma unroll
            for (int r = 0; r < KK; r++) {
                s.arow[w][r][2 * l]     = acc[r].x * dn;
                s.arow[w][r][2 * l + 1] = acc[r].y * dn;
            }
        }
        __syncwarp();
        // stage 1: h2 = relu(agg @ Wg + bg)
        {
            ull acc[KK][2];
#pragma unroll
            for (int r = 0; r < KK; r++) { acc[r][0] = 0ull; acc[r][1] = 0ull; }
#pragma unroll
            for (int j2 = 0; j2 < 32; j2++) {
                ull w0 = *(const ull*)&s.Wgt[c0 * WSTR + 2 * j2];
                ull w1 = *(const ull*)&s.Wgt[c1 * WSTR + 2 * j2];
#pragma unroll
                for (int r = 0; r < KK; r++) {
                    ull av = *(const ull*)&s.arow[w][r][2 * j2];
                    ffma2(acc[r][0], av, w0);
                    ffma2(acc[r][1], av, w1);
                }
            }
#pragma unroll
            for (int r = 0; r < KK; r++) {
                float h0 = fmaxf(hsum2(acc[r][0]) + s.bg[c0], 0.f);
                float h1 = fmaxf(hsum2(acc[r][1]) + s.bg[c1], 0.f);
                s.h2s[w][r][c0] = h0;
                s.h2s[w][r][c1] = h1;
                if (r == KK - 1) {
                    g_h2r5[n * HH + c0] = h0;
                    g_h2r5[n * HH + c1] = h1;
                }
            }
        }
        __syncwarp();
        // stage 2: kv = h2 @ [Wk|Wv] + b -> fp16 global, 2 halves of 3 rows (reg diet)
#pragma unroll
        for (int rh = 0; rh < 2; rh++) {
            ull acc[3][4];
#pragma unroll
            for (int r = 0; r < 3; r++)
#pragma unroll
                for (int q = 0; q < 4; q++) acc[r][q] = 0ull;
#pragma unroll
            for (int j2 = 0; j2 < 32; j2++) {
                ull w0 = *(const ull*)&s.Wkvt[(l)      * WSTR + 2 * j2];
                ull w1 = *(const ull*)&s.Wkvt[(l + 32) * WSTR + 2 * j2];
                ull w2 = *(const ull*)&s.Wkvt[(l + 64) * WSTR + 2 * j2];
                ull w3 = *(const ull*)&s.Wkvt[(l + 96) * WSTR + 2 * j2];
#pragma unroll
                for (int r = 0; r < 3; r++) {
                    ull hv = *(const ull*)&s.h2s[w][rh * 3 + r][2 * j2];
                    ffma2(acc[r][0], hv, w0);
                    ffma2(acc[r][1], hv, w1);
                    ffma2(acc[r][2], hv, w2);
                    ffma2(acc[r][3], hv, w3);
                }
            }
#pragma unroll
            for (int r = 0; r < 3; r++) {
                __half* kvp = &g_kvh[(n * KK + rh * 3 + r) * 128];
                sth_cs(kvp + l,      hsum2(acc[r][0]) + s.bkv[l]);
                sth_cs(kvp + l + 32, hsum2(acc[r][1]) + s.bkv[l + 32]);
                sth_cs(kvp + l + 64, hsum2(acc[r][2]) + s.bkv[l + 64]);
                sth_cs(kvp + l + 96, hsum2(acc[r][3]) + s.bkv[l + 96]);
            }
        }
    }
}

// ---- fused Q + attention + LN1 + FF + LN2 + decoder-precompute (512 thr, 16 warps) --
#define AW 16
struct __align__(16) SAF {
    float Wqt[HH * WSTR];
    float Wot[HH * WSTR];
    float W1t[128 * WSTR];
    float W2t[HH * 130];
    float Wat[HH * WSTR];
    float Wbt[HH * WSTR];
    float kv[AW][KK * 128];
    float qv[AW][HH];
    float ao[AW][HH];
    float hm[AW][HH];
    float z1[AW][2 * HH];
    float aw[AW][NHD * KK];
    float bq[HH], bo[HH], g1[HH], b1[HH], bb2[HH], g2[HH], be2[HH], b1d[HH];
    float bb1[2 * HH];
};

__global__ __launch_bounds__(512) void k_attnff(
    const float* __restrict__ Wq, const float* __restrict__ bq,
    const float* __restrict__ Wo, const float* __restrict__ bo,
    const float* __restrict__ ln1g, const float* __restrict__ ln1b,
    const float* __restrict__ W_ff1, const float* __restrict__ b_ff1,
    const float* __restrict__ W_ff2, const float* __restrict__ b_ff2,
    const float* __restrict__ ln2g, const float* __restrict__ ln2b,
    const float* __restrict__ Wd1, const float* __restrict__ bd1) {
    extern __shared__ char smem_raw[];
    SAF& s = *reinterpret_cast<SAF*>(smem_raw);
    int t = threadIdx.x, w = t >> 5, l = t & 31;
    for (int i = t; i < HH * HH; i += 512) {
        int j = i >> 6, c = i & 63;
        s.Wqt[c * WSTR + j] = Wq[i];
        s.Wot[c * WSTR + j] = Wo[i];
        s.Wat[c * WSTR + j] = Wd1[i];
        s.Wbt[c * WSTR + j] = Wd1[HH * HH + i];
    }
    for (int i = t; i < HH * 128; i += 512) {
        int j = i >> 7, c = i & 127;
        s.W1t[c * WSTR + j] = W_ff1[i];
    }
    for (int i = t; i < 128 * HH; i += 512) {
        int j = i >> 6, c = i & 63;
        s.W2t[c * 130 + j] = W_ff2[i];
    }
    if (t < HH) {
        s.bq[t] = bq[t]; s.bo[t] = bo[t]; s.g1[t] = ln1g[t]; s.b1[t] = ln1b[t];
        s.bb2[t] = b_ff2[t]; s.g2[t] = ln2g[t]; s.be2[t] = ln2b[t];
        s.b1d[t] = bd1[t];
    }
    if (t < 2 * HH) s.bb1[t] = b_ff1[t];
    __syncthreads();
    const int c0 = l, c1 = l + 32;
    int c2 = 2 * l, c4 = 4 * l;
    for (int n = blockIdx.x * AW + w; n < NN; n += gridDim.x * AW) {
        // load h2row5 (residual + q input) and kv (fp16 streaming -> fp32 smem)
        float r50 = g_h2r5[n * HH + c0];
        float r51 = g_h2r5[n * HH + c1];
        s.hm[w][c0] = r50; s.hm[w][c1] = r51;
#pragma unroll
        for (int r = 0; r < KK; r++) {
            ull raw = __ldcs((const ull*)&g_kvh[(n * KK + r) * 128 + c4]);
            __half2 h0 = *(__half2*)&raw;
            __half2 h1 = *((__half2*)&raw + 1);
            float2 f0 = __half22float2(h0), f1 = __half22float2(h1);
            *(float4*)&s.kv[w][r * 128 + c4] = make_float4(f0.x, f0.y, f1.x, f1.y);
        }
        __syncwarp();
        // q = h2row5 @ Wq + bq (4 chains)
        {
            ull q0a = 0ull, q0b = 0ull, q1a = 0ull, q1b = 0ull;
#pragma unroll
            for (int j2 = 0; j2 < 16; j2++) {
                ull hva = *(const ull*)&s.hm[w][2 * j2];
                ull hvb = *(const ull*)&s.hm[w][2 * j2 + 32];
                ffma2(q0a, hva, *(const ull*)&s.Wqt[c0 * WSTR + 2 * j2]);
                ffma2(q0b, hvb, *(const ull*)&s.Wqt[c0 * WSTR + 2 * j2 + 32]);
                ffma2(q1a, hva, *(const ull*)&s.Wqt[c1 * WSTR + 2 * j2]);
                ffma2(q1b, hvb, *(const ull*)&s.Wqt[c1 * WSTR + 2 * j2 + 32]);
            }
            s.qv[w][c0] = hsum4(q0a, q0b) + s.bq[c0];
            s.qv[w][c1] = hsum4(q1a, q1b) + s.bq[c1];
        }
        __syncwarp();
        // scores
        float sc = 0.f;
        int hh = l / KK, kk = l - hh * KK;
        if (l < NHD * KK) {
#pragma unroll
            for (int d = 0; d < DHD; d++)
                sc += s.qv[w][hh * DHD + d] * s.kv[w][kk * 128 + hh * DHD + d];
            sc *= 0.25f;
        }
        float mysc[KK];
#pragma unroll
        for (int j = 0; j < KK; j++)
            mysc[j] = __shfl_sync(0xffffffffu, sc, (l & 3) * KK + j);
        if (l < NHD) {
            float mx = mysc[0];
#pragma unroll
            for (int j = 1; j < KK; j++) mx = fmaxf(mx, mysc[j]);
            float sum = 0.f;
#pragma unroll
            for (int j = 0; j < KK; j++) { mysc[j] = expf(mysc[j] - mx); sum += mysc[j]; }
            float inv = 1.0f / sum;
#pragma unroll
            for (int j = 0; j < KK; j++) s.aw[w][l * KK + j] = mysc[j] * inv;
        }
        __syncwarp();
        // AV
        int hd = l >> 3;
        float a0 = 0.f, a1 = 0.f;
#pragma unroll
        for (int j = 0; j < KK; j++) {
            float wgt = s.aw[w][hd * KK + j];
            float2 vv = *(const float2*)&s.kv[w][j * 128 + 64 + c2];
            a0 += wgt * vv.x; a1 += wgt * vv.y;
        }
        s.ao[w][c2] = a0; s.ao[w][c2 + 1] = a1;
        __syncwarp();
        // Wo GEMV (4 chains) + residual + LN1
        ull o0a = 0ull, o0b = 0ull, o1a = 0ull, o1b = 0ull;
#pragma unroll
        for (int j2 = 0; j2 < 16; j2++) {
            ull ava = *(const ull*)&s.ao[w][2 * j2];
            ull avb = *(const ull*)&s.ao[w][2 * j2 + 32];
            ffma2(o0a, ava, *(const ull*)&s.Wot[c0 * WSTR + 2 * j2]);
            ffma2(o0b, avb, *(const ull*)&s.Wot[c0 * WSTR + 2 * j2 + 32]);
            ffma2(o1a, ava, *(const ull*)&s.Wot[c1 * WSTR + 2 * j2]);
            ffma2(o1b, avb, *(const ull*)&s.Wot[c1 * WSTR + 2 * j2 + 32]);
        }
        float y0 = r50 + hsum4(o0a, o0b) + s.bo[c0];
        float y1 = r51 + hsum4(o1a, o1b) + s.bo[c1];
        float s1 = y0 + y1, s2 = y0 * y0 + y1 * y1;
#pragma unroll
        for (int off = 16; off > 0; off >>= 1) {
            s1 += __shfl_xor_sync(0xffffffffu, s1, off);
            s2 += __shfl_xor_sync(0xffffffffu, s2, off);
        }
        float m = s1 * (1.0f / HH);
        float var = s2 * (1.0f / HH) - m * m;
        float rstd = rsqrtf(var + 1e-5f);
        float hm0 = (y0 - m) * rstd * s.g1[c0] + s.b1[c0];
        float hm1 = (y1 - m) * rstd * s.g1[c1] + s.b1[c1];
        __syncwarp();
        s.hm[w][c0] = hm0; s.hm[w][c1] = hm1;
        __syncwarp();
        // FF1 (4 chains of 32)
        {
            ull f0 = 0ull, f1 = 0ull, f2 = 0ull, f3 = 0ull;
#pragma unroll
            for (int j2 = 0; j2 < 32; j2++) {
                ull hv = *(const ull*)&s.hm[w][2 * j2];
                ffma2(f0, hv, *(const ull*)&s.W1t[(l)      * WSTR + 2 * j2]);
                ffma2(f1, hv, *(const ull*)&s.W1t[(l + 32) * WSTR + 2 * j2]);
                ffma2(f2, hv, *(const ull*)&s.W1t[(l + 64) * WSTR + 2 * j2]);
                ffma2(f3, hv, *(const ull*)&s.W1t[(l + 96) * WSTR + 2 * j2]);
            }
            s.z1[w][l]      = fmaxf(hsum2(f0) + s.bb1[l], 0.f);
            s.z1[w][l + 32] = fmaxf(hsum2(f1) + s.bb1[l + 32], 0.f);
            s.z1[w][l + 64] = fmaxf(hsum2(f2) + s.bb1[l + 64], 0.f);
            s.z1[w][l + 96] = fmaxf(hsum2(f3) + s.bb1[l + 96], 0.f);
        }
        __syncwarp();
        // FF2 (4 chains of 32) + residual + LN2
        ull g0a = 0ull, g0b = 0ull, g1a = 0ull, g1b = 0ull;
#pragma unroll
        for (int j2 = 0; j2 < 32; j2++) {
            ull zva = *(const ull*)&s.z1[w][2 * j2];
            ull zvb = *(const ull*)&s.z1[w][2 * j2 + 64];
            ffma2(g0a, zva, *(const ull*)&s.W2t[c0 * 130 + 2 * j2]);
            ffma2(g0b, zvb, *(const ull*)&s.W2t[c0 * 130 + 2 * j2 + 64]);
            ffma2(g1a, zva, *(const ull*)&s.W2t[c1 * 130 + 2 * j2]);
            ffma2(g1b, zvb, *(const ull*)&s.W2t[c1 * 130 + 2 * j2 + 64]);
        }
        float u0 = hm0 + hsum4(g0a, g0b) + s.bb2[c0];
        float u1 = hm1 + hsum4(g1a, g1b) + s.bb2[c1];
        float t1 = u0 + u1, t2 = u0 * u0 + u1 * u1;
#pragma unroll
        for (int off = 16; off > 0; off >>= 1) {
            t1 += __shfl_xor_sync(0xffffffffu, t1, off);
            t2 += __shfl_xor_sync(0xffffffffu, t2, off);
        }
        float m2 = t1 * (1.0f / HH);
        float var2 = t2 * (1.0f / HH) - m2 * m2;
        float rstd2 = rsqrtf(var2 + 1e-5f);
        float hf0 = (u0 - m2) * rstd2 * s.g2[c0] + s.be2[c0];
        float hf1 = (u1 - m2) * rstd2 * s.g2[c1] + s.be2[c1];
        __syncwarp();
        // decoder precompute (share hf via z1 buffer; 4 chains of 32 already)
        s.z1[w][c0] = hf0; s.z1[w][c1] = hf1;
        __syncwarp();
        ull pa0 = 0ull, pa1 = 0ull, pb0 = 0ull, pb1 = 0ull;
#pragma unroll
        for (int j2 = 0; j2 < 32; j2++) {
            ull v = *(const ull*)&s.z1[w][2 * j2];
            ffma2(pa0, v, *(const ull*)&s.Wat[c0 * WSTR + 2 * j2]);
            ffma2(pa1, v, *(const ull*)&s.Wat[c1 * WSTR + 2 * j2]);
            ffma2(pb0, v, *(const ull*)&s.Wbt[c0 * WSTR + 2 * j2]);
            ffma2(pb1, v, *(const ull*)&s.Wbt[c1 * WSTR + 2 * j2]);
        }
        g_pa[n * HH + c0] = hsum2(pa0);
        g_pa[n * HH + c1] = hsum2(pa1);
        g_pb[n * HH + c0] = hsum2(pb0) + s.b1d[c0];
        g_pb[n * HH + c1] = hsum2(pb1) + s.b1d[c1];
        __syncwarp();
    }
}

// ---------------- edge decoder (factorized, FFMA2 W2) ----------------
struct __align__(16) SDec3 {
    float z1[8][HH];      // offset 0 (8B-aligned) — required for LDS.64
    float2 W2p[32][32];
    float W1c[5 * HH];
    float W1d[4 * HH];
    float W3[32];
    float b2[32];
    float b3;
};

__global__ __launch_bounds__(256) void k_dec(
    const int* __restrict__ ei,
    const float* __restrict__ edge_attr, const float* __restrict__ edge_seq,
    const float* __restrict__ Wd1,
    const float* __restrict__ Wd2, const float* __restrict__ bd2,
    const float* __restrict__ Wd3, const float* __restrict__ bd3,
    float* __restrict__ out) {
    extern __shared__ char smem_raw[];
    SDec3& s = *reinterpret_cast<SDec3*>(smem_raw);
    int t = threadIdx.x, w = t >> 5, l = t & 31;
    for (int i = t; i < 5 * HH; i += 256) s.W1c[i] = Wd1[(2 * HH) * HH + i];
    for (int i = t; i < 4 * HH; i += 256) s.W1d[i] = Wd1[(2 * HH + 5) * HH + i];
    for (int i = t; i < 1024; i += 256) {
        int j = i >> 5, ll = i & 31;
        s.W2p[j][ll] = make_float2(Wd2[(2 * j) * 32 + ll], Wd2[(2 * j + 1) * 32 + ll]);
    }
    if (t < 32) { s.W3[t] = Wd3[t]; s.b2[t] = bd2[t]; }
    if (t == 0) s.b3 = bd3[0];
    __syncthreads();
    float* z1 = s.z1[w];
    int c = 2 * l;
    for (int e = blockIdx.x * 8 + w; e < MM; e += gridDim.x * 8) {
        int src = ei[e], dst = ei[MM + e];
        float2 pav = *(const float2*)&g_pa[src * HH + c];
        float2 pbv = *(const float2*)&g_pb[dst * HH + c];
        float zx = pav.x + pbv.x, zy = pav.y + pbv.y;
#pragma unroll
        for (int j = 0; j < 5; j++) {
            float ev = __ldcs(&edge_attr[e * 5 + j]);
            float2 wv = *(const float2*)&s.W1c[j * HH + c];
            zx += ev * wv.x; zy += ev * wv.y;
        }
#pragma unroll
        for (int j = 0; j < 4; j++) {
            float ev = __ldcs(&edge_seq[e * (KK * 4) + (KK - 1) * 4 + j]);
            float2 wv = *(const float2*)&s.W1d[j * HH + c];
            zx += ev * wv.x; zy += ev * wv.y;
        }
        z1[c] = fmaxf(zx, 0.f);
        z1[c + 1] = fmaxf(zy, 0.f);
        __syncwarp();
        ull acc = pack2(s.b2[l], 0.f);
#pragma unroll
        for (int j = 0; j < 32; j++) {
            ull z2 = *(const ull*)&z1[2 * j];
            ull w2 = *(const ull*)&s.W2p[j][l];
            ffma2(acc, z2, w2);
        }
        float2 av = unpack2(acc);
        float a2 = fmaxf(av.x + av.y, 0.f);
        float p = a2 * s.W3[l];
#pragma unroll
        for (int off = 16; off > 0; off >>= 1) p += __shfl_down_sync(0xffffffffu, p, off);
        if (l == 0) out[e] = p + s.b3;
        __syncwarp();
    }
}

// ---------------- launch ----------------
extern "C" void kernel_launch(void* const* d_in, const int* in_sizes, int n_in,
                              void* d_out, int out_size) {
    const float* x        = (const float*)d_in[0];
    const int*   ei       = (const int*)  d_in[1];
    const float* eattr    = (const float*)d_in[2];
    const float* u        = (const float*)d_in[3];
    const float* eseq     = (const float*)d_in[4];
    const float* useq     = (const float*)d_in[5];
    const float* W_proj   = (const float*)d_in[6];
    const float* b_proj   = (const float*)d_in[7];
    const float* W_gcn    = (const float*)d_in[8];
    const float* b_gcn    = (const float*)d_in[9];
    const float* Wq       = (const float*)d_in[10];
    const float* bq       = (const float*)d_in[11];
    const float* Wk       = (const float*)d_in[12];
    const float* bk       = (const float*)d_in[13];
    const float* Wv       = (const float*)d_in[14];
    const float* bv       = (const float*)d_in[15];
    const float* Wo       = (const float*)d_in[16];
    const float* bo       = (const float*)d_in[17];
    const float* ln1g     = (const float*)d_in[18];
    const float* ln1b     = (const float*)d_in[19];
    const float* W_ff1    = (const float*)d_in[20];
    const float* b_ff1    = (const float*)d_in[21];
    const float* W_ff2    = (const float*)d_in[22];
    const float* b_ff2    = (const float*)d_in[23];
    const float* ln2g     = (const float*)d_in[24];
    const float* ln2b     = (const float*)d_in[25];
    const float* Wd1      = (const float*)d_in[26];
    const float* bd1      = (const float*)d_in[27];
    const float* Wd2      = (const float*)d_in[28];
    const float* bd2      = (const float*)d_in[29];
    const float* Wd3      = (const float*)d_in[30];
    const float* bd3      = (const float*)d_in[31];
    float* out = (float*)d_out;

    cudaFuncSetAttribute(k_gcnqkv, cudaFuncAttributeMaxDynamicSharedMemorySize, (int)sizeof(SG));
    cudaFuncSetAttribute(k_attnff, cudaFuncAttributeMaxDynamicSharedMemorySize, (int)sizeof(SAF));
    cudaFuncSetAttribute(k_dec,    cudaFuncAttributeMaxDynamicSharedMemorySize, (int)sizeof(SDec3));

    k_init<<<(NN + 255) / 256, 256>>>();
    k_count<<<(MM + 255) / 256, 256>>>(ei);
    k_scanall<<<NBLK, 1024>>>();
    k_fill<<<(MM + 255) / 256, 256>>>(ei);
    k_projck<<<NN / 4, 256>>>(x, W_proj, b_proj, u, useq);
    k_gcnqkv<<<1184, 384, sizeof(SG)>>>(W_gcn, b_gcn, Wk, bk, Wv, bv);
    k_attnff<<<592, 512, sizeof(SAF)>>>(Wq, bq, Wo, bo, ln1g, ln1b, W_ff1, b_ff1,
                                        W_ff2, b_ff2, ln2g, ln2b, Wd1, bd1);
    k_dec<<<2048, 256, sizeof(SDec3)>>>(ei, eattr, eseq, Wd1, Wd2, bd2, Wd3, bd3, out);
}

// round 11
// speedup vs baseline: 1.5930x; 1.5930x over previous
#include <cuda_runtime.h>
#include <cuda_fp16.h>
#include <math.h>

#define NN 100000
#define MM 800000
#define KK 6
#define HH 64
#define NHD 4
#define DHD 16
#define NBLK 98   // ceil(NN/1024)
#define WSTR 66   // padded transposed-weight row stride (floats)

typedef unsigned long long ull;

// ---------------- packed f32x2 helpers (sm_103a FFMA2 path) ----------------
__device__ __forceinline__ ull pack2(float lo, float hi) {
    ull r;
    asm("mov.b64 %0, {%1, %2};" : "=l"(r) : "f"(lo), "f"(hi));
    return r;
}
__device__ __forceinline__ void ffma2(ull& d, ull a, ull b) {
    asm("fma.rn.f32x2 %0, %1, %2, %0;" : "+l"(d) : "l"(a), "l"(b));
}
__device__ __forceinline__ float2 unpack2(ull v) {
    float lo, hi;
    asm("mov.b64 {%0, %1}, %2;" : "=f"(lo), "=f"(hi) : "l"(v));
    return make_float2(lo, hi);
}
__device__ __forceinline__ float hsum2(ull v) {
    float2 p = unpack2(v);
    return p.x + p.y;
}
__device__ __forceinline__ float hsum4(ull a, ull b) {
    float2 pa = unpack2(a), pb = unpack2(b);
    return (pa.x + pa.y) + (pb.x + pb.y);
}

// ---------------- scratch (device globals; allocation-free) ----------------
__device__ __half g_hh[NN * KK * HH];    // hs = tanh(proj)*dinv, fp16 (76.8 MB)
__device__ float g_h2r5[NN * HH];        // post-GCN relu, row k=5 only (residual)
__device__ float g_kv[NN * KK * 2 * HH]; // per (n,k) row: [k(64) | v(64)] fp32
__device__ float g_q[NN * HH];           // q of row k=5
__device__ float g_pa[NN * HH];
__device__ float g_pb[NN * HH];
__device__ float g_dinv[NN];
__device__ int   g_counts[NN];
__device__ int   g_rowstart[NN + 1];
__device__ int   g_cursor[NN];
__device__ int   g_srclist[MM];
// decoupled-lookback scan state (reset every replay by k_init)
__device__ volatile int g_statev[NBLK];
__device__ volatile int g_aggv[NBLK];
__device__ volatile int g_incv[NBLK];

// ---------------- init (zeros all cross-replay state) ----------------
__global__ void k_init() {
    int i = blockIdx.x * blockDim.x + threadIdx.x;
    if (i < NN) g_counts[i] = 0;
    if (i < NBLK) g_statev[i] = 0;
    if (i == 0) g_rowstart[NN] = MM;
}

__global__ void k_count(const int* __restrict__ ei) {
    int e = blockIdx.x * blockDim.x + threadIdx.x;
    if (e < MM) atomicAdd(&g_counts[ei[MM + e]], 1);
}

// ---------------- single-pass scan (decoupled lookback; 98 tiles co-resident) -------
__global__ __launch_bounds__(1024) void k_scanall() {
    __shared__ int warpsums[32];
    __shared__ int exoff_s;
    int t = threadIdx.x, lane = t & 31, w = t >> 5;
    int bid = blockIdx.x;
    int i = bid * 1024 + t;
    int v0 = (i < NN) ? g_counts[i] : 0;
    if (i < NN) g_dinv[i] = rsqrtf((float)v0 + 1.0f);
    int v = v0;
#pragma unroll
    for (int off = 1; off < 32; off <<= 1) {
        int x = __shfl_up_sync(0xffffffffu, v, off);
        if (lane >= off) v += x;
    }
    if (lane == 31) warpsums[w] = v;
    __syncthreads();
    if (w == 0) {
        int s = warpsums[lane];
#pragma unroll
        for (int off = 1; off < 32; off <<= 1) {
            int x = __shfl_up_sync(0xffffffffu, s, off);
            if (lane >= off) s += x;
        }
        warpsums[lane] = s;
    }
    __syncthreads();
    int incl = v + (w > 0 ? warpsums[w - 1] : 0);
    if (t == 0) {
        int tot = warpsums[31];
        g_aggv[bid] = tot;
        __threadfence();
        g_statev[bid] = 1;
        int exc = 0;
        if (bid > 0) {
            int p = bid - 1;
            while (true) {
                int st;
                do { st = g_statev[p]; } while (st == 0);
                if (st == 2) { exc += g_incv[p]; break; }
                exc += g_aggv[p];
                if (--p < 0) break;
            }
        }
        g_incv[bid] = exc + tot;
        __threadfence();
        g_statev[bid] = 2;
        exoff_s = exc;
    }
    __syncthreads();
    if (i < NN) {
        int excl = exoff_s + incl - v0;
        g_rowstart[i] = excl;
        g_cursor[i]   = excl;
    }
}

__global__ void k_fill(const int* __restrict__ ei) {
    int e = blockIdx.x * blockDim.x + threadIdx.x;
    if (e < MM) {
        int d = ei[MM + e];
        int p = atomicAdd(&g_cursor[d], 1);
        g_srclist[p] = ei[e];
    }
}

// ---------------- projection (+ inline ck): hs = tanh(dot12 + ck)*dinv, fp16 --------
__global__ __launch_bounds__(256) void k_projck(
    const float* __restrict__ x, const float* __restrict__ W_proj,
    const float* __restrict__ b_proj, const float* __restrict__ u,
    const float* __restrict__ u_seq) {
    __shared__ float Wp12[12 * HH];
    __shared__ float cks[KK * HH];
    int t = threadIdx.x;
    for (int i = t; i < 12 * HH; i += 256) Wp12[i] = W_proj[i];
    if (t < HH) {
        int c = t;
        float base = b_proj[c];
#pragma unroll
        for (int j = 0; j < 11; j++) base += u[j] * W_proj[(12 + j) * HH + c];
#pragma unroll
        for (int k = 0; k < KK; k++) {
            float val = base;
#pragma unroll
            for (int j = 0; j < 5; j++) val += u_seq[k * 5 + j] * W_proj[(23 + j) * HH + c];
            cks[k * HH + c] = val;
        }
    }
    __syncthreads();
    int g = t >> 6, c = t & 63;
    int n = blockIdx.x * 4 + g;
    float dn = g_dinv[n];
    float s = 0.f;
#pragma unroll
    for (int j = 0; j < 12; j++) s += __ldg(&x[n * 12 + j]) * Wp12[j * HH + c];
    int base = n * (KK * HH) + c;
#pragma unroll
    for (int k = 0; k < KK; k++)
        g_hh[base + k * HH] = __float2half(tanhf(s + cks[k * HH + c]) * dn);
}

// ---------------- fused AGGREGATE + GCN + KV + Q (warp per node) ----------------
struct __align__(16) SG {
    float Wgt[HH * WSTR];       // Wgt[c*66+j] = W_gcn[j][c]
    float Wkvt[128 * WSTR];     // Wkvt[c*66+j] = [Wk|Wv][j][c]
    float Wqt[HH * WSTR];
    float arow[12][KK][HH];
    float h2s[12][KK][HH];
    float bg[HH], bkv[128], bq[HH];
};

__global__ __launch_bounds__(384) void k_gcnqkv(
    const float* __restrict__ W_gcn, const float* __restrict__ b_gcn,
    const float* __restrict__ Wk, const float* __restrict__ bk,
    const float* __restrict__ Wv, const float* __restrict__ bv,
    const float* __restrict__ Wq, const float* __restrict__ bq) {
    extern __shared__ char smem_raw[];
    SG& s = *reinterpret_cast<SG*>(smem_raw);
    int t = threadIdx.x, w = t >> 5, l = t & 31;
    for (int i = t; i < HH * HH; i += 384) {
        int j = i >> 6, c = i & 63;
        s.Wgt[c * WSTR + j] = W_gcn[i];
        s.Wqt[c * WSTR + j] = Wq[i];
        s.Wkvt[c * WSTR + j] = Wk[i];
        s.Wkvt[(c + 64) * WSTR + j] = Wv[i];
    }
    if (t < HH) { s.bg[t] = b_gcn[t]; s.bq[t] = bq[t]; s.bkv[t] = bk[t]; s.bkv[64 + t] = bv[t]; }
    __syncthreads();
    const int c0 = l, c1 = l + 32;
    const __half2* hh2 = (const __half2*)g_hh;
    for (int n = blockIdx.x * 12 + w; n < NN; n += gridDim.x * 12) {
        // stage 0: aggregate (4-way unrolled gather)
        {
            float dn = g_dinv[n];
            int s0 = g_rowstart[n], s1 = g_rowstart[n + 1];
            float2 acc[KK];
#pragma unroll
            for (int r = 0; r < KK; r++)
                acc[r] = __half22float2(hh2[(n * KK + r) * 32 + l]);
            int i = s0;
            for (; i + 3 < s1; i += 4) {
                const __half2* pa = hh2 + g_srclist[i]     * (KK * 32) + l;
                const __half2* pb = hh2 + g_srclist[i + 1] * (KK * 32) + l;
                const __half2* pc = hh2 + g_srclist[i + 2] * (KK * 32) + l;
                const __half2* pd = hh2 + g_srclist[i + 3] * (KK * 32) + l;
#pragma unroll
                for (int r = 0; r < KK; r++) {
                    float2 va = __half22float2(pa[r * 32]);
                    float2 vb = __half22float2(pb[r * 32]);
                    float2 vc = __half22float2(pc[r * 32]);
                    float2 vd = __half22float2(pd[r * 32]);
                    acc[r].x += (va.x + vb.x) + (vc.x + vd.x);
                    acc[r].y += (va.y + vb.y) + (vc.y + vd.y);
                }
            }
            for (; i < s1; i++) {
                const __half2* pa = hh2 + g_srclist[i] * (KK * 32) + l;
#pragma unroll
                for (int r = 0; r < KK; r++) {
                    float2 va = __half22float2(pa[r * 32]);
                    acc[r].x += va.x;
                    acc[r].y += va.y;
                }
            }
#pragma unroll
            for (int r = 0; r < KK; r++) {
                s.arow[w][r][2 * l]     = acc[r].x * dn;
                s.arow[w][r][2 * l + 1] = acc[r].y * dn;
            }
        }
        __syncwarp();
        // stage 1: h2 = relu(agg @ Wg + bg) — cols (l, l+32), 6 rows, packed j-pairs
        {
            ull acc[KK][2];
#pragma unroll
            for (int r = 0; r < KK; r++) { acc[r][0] = 0ull; acc[r][1] = 0ull; }
#pragma unroll
            for (int j2 = 0; j2 < 32; j2++) {
                ull w0 = *(const ull*)&s.Wgt[c0 * WSTR + 2 * j2];
                ull w1 = *(const ull*)&s.Wgt[c1 * WSTR + 2 * j2];
#pragma unroll
                for (int r = 0; r < KK; r++) {
                    ull av = *(const ull*)&s.arow[w][r][2 * j2];
                    ffma2(acc[r][0], av, w0);
                    ffma2(acc[r][1], av, w1);
                }
            }
#pragma unroll
            for (int r = 0; r < KK; r++) {
                float h0 = fmaxf(hsum2(acc[r][0]) + s.bg[c0], 0.f);
                float h1 = fmaxf(hsum2(acc[r][1]) + s.bg[c1], 0.f);
                s.h2s[w][r][c0] = h0;
                s.h2s[w][r][c1] = h1;
                if (r == KK - 1) {
                    g_h2r5[n * HH + c0] = h0;
                    g_h2r5[n * HH + c1] = h1;
                }
            }
        }
        __syncwarp();
        // stage 2: kv = h2 @ [Wk|Wv] + b — 4 cols/lane, 6 rows, fp32 float4 stores
        {
            ull acc[KK][4];
#pragma unroll
            for (int r = 0; r < KK; r++)
#pragma unroll
                for (int q = 0; q < 4; q++) acc[r][q] = 0ull;
#pragma unroll
            for (int j2 = 0; j2 < 32; j2++) {
                ull w0 = *(const ull*)&s.Wkvt[(l)      * WSTR + 2 * j2];
                ull w1 = *(const ull*)&s.Wkvt[(l + 32) * WSTR + 2 * j2];
                ull w2 = *(const ull*)&s.Wkvt[(l + 64) * WSTR + 2 * j2];
                ull w3 = *(const ull*)&s.Wkvt[(l + 96) * WSTR + 2 * j2];
#pragma unroll
                for (int r = 0; r < KK; r++) {
                    ull hv = *(const ull*)&s.h2s[w][r][2 * j2];
                    ffma2(acc[r][0], hv, w0);
                    ffma2(acc[r][1], hv, w1);
                    ffma2(acc[r][2], hv, w2);
                    ffma2(acc[r][3], hv, w3);
                }
            }
#pragma unroll
            for (int r = 0; r < KK; r++) {
                float* kvp = &g_kv[(n * KK + r) * 128];
                kvp[l]      = hsum2(acc[r][0]) + s.bkv[l];
                kvp[l + 32] = hsum2(acc[r][1]) + s.bkv[l + 32];
                kvp[l + 64] = hsum2(acc[r][2]) + s.bkv[l + 64];
                kvp[l + 96] = hsum2(acc[r][3]) + s.bkv[l + 96];
            }
        }
        // stage 3: q = h2row5 @ Wq + bq
        {
            ull a0 = 0ull, a1 = 0ull;
#pragma unroll
            for (int j2 = 0; j2 < 32; j2++) {
                ull hv = *(const ull*)&s.h2s[w][KK - 1][2 * j2];
                ull w0 = *(const ull*)&s.Wqt[c0 * WSTR + 2 * j2];
                ull w1 = *(const ull*)&s.Wqt[c1 * WSTR + 2 * j2];
                ffma2(a0, hv, w0);
                ffma2(a1, hv, w1);
            }
            g_q[n * HH + c0] = hsum2(a0) + s.bq[c0];
            g_q[n * HH + c1] = hsum2(a1) + s.bq[c1];
        }
        __syncwarp();
    }
}

// ---- fused attention tail + LN1 + FF + LN2 + decoder-precompute (warp per node) ----
struct __align__(16) SAF {
    float Wot[HH * WSTR];
    float W1t[128 * WSTR];
    float W2t[HH * 130];
    float Wat[HH * WSTR];
    float Wbt[HH * WSTR];
    float kv[12][KK * 128];
    float qv[12][HH];
    float ao[12][HH];
    float hm[12][HH];
    float z1[12][2 * HH];
    float aw[12][NHD * KK];
    float bo[HH], g1[HH], b1[HH], bb2[HH], g2[HH], be2[HH], b1d[HH];
    float bb1[2 * HH];
};

__global__ __launch_bounds__(384) void k_attnff(
    const float* __restrict__ Wo, const float* __restrict__ bo,
    const float* __restrict__ ln1g, const float* __restrict__ ln1b,
    const float* __restrict__ W_ff1, const float* __restrict__ b_ff1,
    const float* __restrict__ W_ff2, const float* __restrict__ b_ff2,
    const float* __restrict__ ln2g, const float* __restrict__ ln2b,
    const float* __restrict__ Wd1, const float* __restrict__ bd1) {
    extern __shared__ char smem_raw[];
    SAF& s = *reinterpret_cast<SAF*>(smem_raw);
    int t = threadIdx.x, w = t >> 5, l = t & 31;
    for (int i = t; i < HH * HH; i += 384) {
        int j = i >> 6, c = i & 63;
        s.Wot[c * WSTR + j] = Wo[i];
        s.Wat[c * WSTR + j] = Wd1[i];
        s.Wbt[c * WSTR + j] = Wd1[HH * HH + i];
    }
    for (int i = t; i < HH * 128; i += 384) {
        int j = i >> 7, c = i & 127;
        s.W1t[c * WSTR + j] = W_ff1[i];
    }
    for (int i = t; i < 128 * HH; i += 384) {
        int j = i >> 6, c = i & 63;
        s.W2t[c * 130 + j] = W_ff2[i];
    }
    if (t < HH) {
        s.bo[t] = bo[t]; s.g1[t] = ln1g[t]; s.b1[t] = ln1b[t];
        s.bb2[t] = b_ff2[t]; s.g2[t] = ln2g[t]; s.be2[t] = ln2b[t];
        s.b1d[t] = bd1[t];
    }
    if (t < 2 * HH) s.bb1[t] = b_ff1[t];
    __syncthreads();
    const int c0 = l, c1 = l + 32;
    int c2 = 2 * l, c4 = 4 * l;
    for (int n = blockIdx.x * 12 + w; n < NN; n += gridDim.x * 12) {
        // load q and kv (streaming: read-once data)
        s.qv[w][l]      = __ldcs(&g_q[n * HH + l]);
        s.qv[w][l + 32] = __ldcs(&g_q[n * HH + 32 + l]);
#pragma unroll
        for (int r = 0; r < KK; r++) {
            float4 v = __ldcs((const float4*)&g_kv[(n * KK + r) * 128 + c4]);
            *(float4*)&s.kv[w][r * 128 + c4] = v;
        }
        __syncwarp();
        // scores
        float sc = 0.f;
        int hh = l / KK, kk = l - hh * KK;
        if (l < NHD * KK) {
#pragma unroll
            for (int d = 0; d < DHD; d++)
                sc += s.qv[w][hh * DHD + d] * s.kv[w][kk * 128 + hh * DHD + d];
            sc *= 0.25f;
        }
        float mysc[KK];
#pragma unroll
        for (int j = 0; j < KK; j++)
            mysc[j] = __shfl_sync(0xffffffffu, sc, (l & 3) * KK + j);
        if (l < NHD) {
            float mx = mysc[0];
#pragma unroll
            for (int j = 1; j < KK; j++) mx = fmaxf(mx, mysc[j]);
            float sum = 0.f;
#pragma unroll
            for (int j = 0; j < KK; j++) { mysc[j] = expf(mysc[j] - mx); sum += mysc[j]; }
            float inv = 1.0f / sum;
#pragma unroll
            for (int j = 0; j < KK; j++) s.aw[w][l * KK + j] = mysc[j] * inv;
        }
        __syncwarp();
        // AV
        int hd = l >> 3;
        float a0 = 0.f, a1 = 0.f;
#pragma unroll
        for (int j = 0; j < KK; j++) {
            float wgt = s.aw[w][hd * KK + j];
            float2 vv = *(const float2*)&s.kv[w][j * 128 + 64 + c2];
            a0 += wgt * vv.x; a1 += wgt * vv.y;
        }
        s.ao[w][c2] = a0; s.ao[w][c2 + 1] = a1;
        __syncwarp();
        // Wo GEMV (4 chains) + residual + LN1
        ull o0a = 0ull, o0b = 0ull, o1a = 0ull, o1b = 0ull;
#pragma unroll
        for (int j2 = 0; j2 < 16; j2++) {
            ull ava = *(const ull*)&s.ao[w][2 * j2];
            ull avb = *(const ull*)&s.ao[w][2 * j2 + 32];
            ffma2(o0a, ava, *(const ull*)&s.Wot[c0 * WSTR + 2 * j2]);
            ffma2(o0b, avb, *(const ull*)&s.Wot[c0 * WSTR + 2 * j2 + 32]);
            ffma2(o1a, ava, *(const ull*)&s.Wot[c1 * WSTR + 2 * j2]);
            ffma2(o1b, avb, *(const ull*)&s.Wot[c1 * WSTR + 2 * j2 + 32]);
        }
        float y0 = g_h2r5[n * HH + c0] + hsum4(o0a, o0b) + s.bo[c0];
        float y1 = g_h2r5[n * HH + c1] + hsum4(o1a, o1b) + s.bo[c1];
        float s1 = y0 + y1, s2 = y0 * y0 + y1 * y1;
#pragma unroll
        for (int off = 16; off > 0; off >>= 1) {
            s1 += __shfl_xor_sync(0xffffffffu, s1, off);
            s2 += __shfl_xor_sync(0xffffffffu, s2, off);
        }
        float m = s1 * (1.0f / HH);
        float var = s2 * (1.0f / HH) - m * m;
        float rstd = rsqrtf(var + 1e-5f);
        float hm0 = (y0 - m) * rstd * s.g1[c0] + s.b1[c0];
        float hm1 = (y1 - m) * rstd * s.g1[c1] + s.b1[c1];
        s.hm[w][c0] = hm0; s.hm[w][c1] = hm1;
        __syncwarp();
        // FF1 (4 chains): z1 = relu(hm @ W1 + b1)
        {
            ull f0 = 0ull, f1 = 0ull, f2 = 0ull, f3 = 0ull;
#pragma unroll
            for (int j2 = 0; j2 < 32; j2++) {
                ull hv = *(const ull*)&s.hm[w][2 * j2];
                ffma2(f0, hv, *(const ull*)&s.W1t[(l)      * WSTR + 2 * j2]);
                ffma2(f1, hv, *(const ull*)&s.W1t[(l + 32) * WSTR + 2 * j2]);
                ffma2(f2, hv, *(const ull*)&s.W1t[(l + 64) * WSTR + 2 * j2]);
                ffma2(f3, hv, *(const ull*)&s.W1t[(l + 96) * WSTR + 2 * j2]);
            }
            s.z1[w][l]      = fmaxf(hsum2(f0) + s.bb1[l], 0.f);
            s.z1[w][l + 32] = fmaxf(hsum2(f1) + s.bb1[l + 32], 0.f);
            s.z1[w][l + 64] = fmaxf(hsum2(f2) + s.bb1[l + 64], 0.f);
            s.z1[w][l + 96] = fmaxf(hsum2(f3) + s.bb1[l + 96], 0.f);
        }
        __syncwarp();
        // FF2 (4 chains) + residual + LN2
        ull g0a = 0ull, g0b = 0ull, g1a = 0ull, g1b = 0ull;
#pragma unroll
        for (int j2 = 0; j2 < 32; j2++) {
            ull zva = *(const ull*)&s.z1[w][2 * j2];
            ull zvb = *(const ull*)&s.z1[w][2 * j2 + 64];
            ffma2(g0a, zva, *(const ull*)&s.W2t[c0 * 130 + 2 * j2]);
            ffma2(g0b, zvb, *(const ull*)&s.W2t[c0 * 130 + 2 * j2 + 64]);
            ffma2(g1a, zva, *(const ull*)&s.W2t[c1 * 130 + 2 * j2]);
            ffma2(g1b, zvb, *(const ull*)&s.W2t[c1 * 130 + 2 * j2 + 64]);
        }
        float u0 = hm0 + hsum4(g0a, g0b) + s.bb2[c0];
        float u1 = hm1 + hsum4(g1a, g1b) + s.bb2[c1];
        float t1 = u0 + u1, t2 = u0 * u0 + u1 * u1;
#pragma unroll
        for (int off = 16; off > 0; off >>= 1) {
            t1 += __shfl_xor_sync(0xffffffffu, t1, off);
            t2 += __shfl_xor_sync(0xffffffffu, t2, off);
        }
        float m2 = t1 * (1.0f / HH);
        float var2 = t2 * (1.0f / HH) - m2 * m2;
        float rstd2 = rsqrtf(var2 + 1e-5f);
        float hf0 = (u0 - m2) * rstd2 * s.g2[c0] + s.be2[c0];
        float hf1 = (u1 - m2) * rstd2 * s.g2[c1] + s.be2[c1];
        __syncwarp();
        // decoder precompute (share hf via z1 buffer; 4 independent chains)
        s.z1[w][c0] = hf0; s.z1[w][c1] = hf1;
        __syncwarp();
        ull pa0 = 0ull, pa1 = 0ull, pb0 = 0ull, pb1 = 0ull;
#pragma unroll
        for (int j2 = 0; j2 < 32; j2++) {
            ull v = *(const ull*)&s.z1[w][2 * j2];
            ffma2(pa0, v, *(const ull*)&s.Wat[c0 * WSTR + 2 * j2]);
            ffma2(pa1, v, *(const ull*)&s.Wat[c1 * WSTR + 2 * j2]);
            ffma2(pb0, v, *(const ull*)&s.Wbt[c0 * WSTR + 2 * j2]);
            ffma2(pb1, v, *(const ull*)&s.Wbt[c1 * WSTR + 2 * j2]);
        }
        g_pa[n * HH + c0] = hsum2(pa0);
        g_pa[n * HH + c1] = hsum2(pa1);
        g_pb[n * HH + c0] = hsum2(pb0) + s.b1d[c0];
        g_pb[n * HH + c1] = hsum2(pb1) + s.b1d[c1];
        __syncwarp();
    }
}

// ---------------- edge decoder (factorized, FFMA2 W2) ----------------
struct __align__(16) SDec3 {
    float z1[8][HH];      // offset 0 (8B-aligned) — required for LDS.64
    float2 W2p[32][32];
    float W1c[5 * HH];
    float W1d[4 * HH];
    float W3[32];
    float b2[32];
    float b3;
};

__global__ __launch_bounds__(256) void k_dec(
    const int* __restrict__ ei,
    const float* __restrict__ edge_attr, const float* __restrict__ edge_seq,
    const float* __restrict__ Wd1,
    const float* __restrict__ Wd2, const float* __restrict__ bd2,
    const float* __restrict__ Wd3, const float* __restrict__ bd3,
    float* __restrict__ out) {
    extern __shared__ char smem_raw[];
    SDec3& s = *reinterpret_cast<SDec3*>(smem_raw);
    int t = threadIdx.x, w = t >> 5, l = t & 31;
    for (int i = t; i < 5 * HH; i += 256) s.W1c[i] = Wd1[(2 * HH) * HH + i];
    for (int i = t; i < 4 * HH; i += 256) s.W1d[i] = Wd1[(2 * HH + 5) * HH + i];
    for (int i = t; i < 1024; i += 256) {
        int j = i >> 5, ll = i & 31;
        s.W2p[j][ll] = make_float2(Wd2[(2 * j) * 32 + ll], Wd2[(2 * j + 1) * 32 + ll]);
    }
    if (t < 32) { s.W3[t] = Wd3[t]; s.b2[t] = bd2[t]; }
    if (t == 0) s.b3 = bd3[0];
    __syncthreads();
    float* z1 = s.z1[w];
    int c = 2 * l;
    for (int e = blockIdx.x * 8 + w; e < MM; e += gridDim.x * 8) {
        int src = ei[e], dst = ei[MM + e];
        float2 pav = *(const float2*)&g_pa[src * HH + c];
        float2 pbv = *(const float2*)&g_pb[dst * HH + c];
        float zx = pav.x + pbv.x, zy = pav.y + pbv.y;
#pragma unroll
        for (int j = 0; j < 5; j++) {
            float ev = __ldcs(&edge_attr[e * 5 + j]);
            float2 wv = *(const float2*)&s.W1c[j * HH + c];
            zx += ev * wv.x; zy += ev * wv.y;
        }
#pragma unroll
        for (int j = 0; j < 4; j++) {
            float ev = __ldcs(&edge_seq[e * (KK * 4) + (KK - 1) * 4 + j]);
            float2 wv = *(const float2*)&s.W1d[j * HH + c];
            zx += ev * wv.x; zy += ev * wv.y;
        }
        z1[c] = fmaxf(zx, 0.f);
        z1[c + 1] = fmaxf(zy, 0.f);
        __syncwarp();
        ull acc = pack2(s.b2[l], 0.f);
#pragma unroll
        for (int j = 0; j < 32; j++) {
            ull z2 = *(const ull*)&z1[2 * j];
            ull w2 = *(const ull*)&s.W2p[j][l];
            ffma2(acc, z2, w2);
        }
        float2 av = unpack2(acc);
        float a2 = fmaxf(av.x + av.y, 0.f);
        float p = a2 * s.W3[l];
#pragma unroll
        for (int off = 16; off > 0; off >>= 1) p += __shfl_down_sync(0xffffffffu, p, off);
        if (l == 0) out[e] = p + s.b3;
        __syncwarp();
    }
}

// ---------------- launch ----------------
extern "C" void kernel_launch(void* const* d_in, const int* in_sizes, int n_in,
                              void* d_out, int out_size) {
    const float* x        = (const float*)d_in[0];
    const int*   ei       = (const int*)  d_in[1];
    const float* eattr    = (const float*)d_in[2];
    const float* u        = (const float*)d_in[3];
    const float* eseq     = (const float*)d_in[4];
    const float* useq     = (const float*)d_in[5];
    const float* W_proj   = (const float*)d_in[6];
    const float* b_proj   = (const float*)d_in[7];
    const float* W_gcn    = (const float*)d_in[8];
    const float* b_gcn    = (const float*)d_in[9];
    const float* Wq       = (const float*)d_in[10];
    const float* bq       = (const float*)d_in[11];
    const float* Wk       = (const float*)d_in[12];
    const float* bk       = (const float*)d_in[13];
    const float* Wv       = (const float*)d_in[14];
    const float* bv       = (const float*)d_in[15];
    const float* Wo       = (const float*)d_in[16];
    const float* bo       = (const float*)d_in[17];
    const float* ln1g     = (const float*)d_in[18];
    const float* ln1b     = (const float*)d_in[19];
    const float* W_ff1    = (const float*)d_in[20];
    const float* b_ff1    = (const float*)d_in[21];
    const float* W_ff2    = (const float*)d_in[22];
    const float* b_ff2    = (const float*)d_in[23];
    const float* ln2g     = (const float*)d_in[24];
    const float* ln2b     = (const float*)d_in[25];
    const float* Wd1      = (const float*)d_in[26];
    const float* bd1      = (const float*)d_in[27];
    const float* Wd2      = (const float*)d_in[28];
    const float* bd2      = (const float*)d_in[29];
    const float* Wd3      = (const float*)d_in[30];
    const float* bd3      = (const float*)d_in[31];
    float* out = (float*)d_out;

    cudaFuncSetAttribute(k_gcnqkv, cudaFuncAttributeMaxDynamicSharedMemorySize, (int)sizeof(SG));
    cudaFuncSetAttribute(k_attnff, cudaFuncAttributeMaxDynamicSharedMemorySize, (int)sizeof(SAF));
    cudaFuncSetAttribute(k_dec,    cudaFuncAttributeMaxDynamicSharedMemorySize, (int)sizeof(SDec3));

    k_init<<<(NN + 255) / 256, 256>>>();
    k_count<<<(MM + 255) / 256, 256>>>(ei);
    k_scanall<<<NBLK, 1024>>>();
    k_fill<<<(MM + 255) / 256, 256>>>(ei);
    k_projck<<<NN / 4, 256>>>(x, W_proj, b_proj, u, useq);
    k_gcnqkv<<<1184, 384, sizeof(SG)>>>(W_gcn, b_gcn, Wk, bk, Wv, bv, Wq, bq);
    k_attnff<<<592, 384, sizeof(SAF)>>>(Wo, bo, ln1g, ln1b, W_ff1, b_ff1,
                                        W_ff2, b_ff2, ln2g, ln2b, Wd1, bd1);
    k_dec<<<2048, 256, sizeof(SDec3)>>>(ei, eattr, eseq, Wd1, Wd2, bd2, Wd3, bd3, out);
}

// round 12
// speedup vs baseline: 1.6694x; 1.0480x over previous
#include <cuda_runtime.h>
#include <cuda_fp16.h>
#include <math.h>

#define NN 100000
#define MM 800000
#define KK 6
#define HH 64
#define NHD 4
#define DHD 16
#define NBLK 98   // ceil(NN/1024)
#define WSTR 66   // padded transposed-weight row stride (floats)

typedef unsigned long long ull;

// ---------------- packed f32x2 helpers (sm_103a FFMA2 path) ----------------
__device__ __forceinline__ ull pack2(float lo, float hi) {
    ull r;
    asm("mov.b64 %0, {%1, %2};" : "=l"(r) : "f"(lo), "f"(hi));
    return r;
}
__device__ __forceinline__ void ffma2(ull& d, ull a, ull b) {
    asm("fma.rn.f32x2 %0, %1, %2, %0;" : "+l"(d) : "l"(a), "l"(b));
}
__device__ __forceinline__ float2 unpack2(ull v) {
    float lo, hi;
    asm("mov.b64 {%0, %1}, %2;" : "=f"(lo), "=f"(hi) : "l"(v));
    return make_float2(lo, hi);
}
__device__ __forceinline__ float hsum2(ull v) {
    float2 p = unpack2(v);
    return p.x + p.y;
}
// streaming 16-bit store (evict-first: kv is write-once/read-once)
__device__ __forceinline__ void sth_cs(__half* p, float v) {
    unsigned short u = __half_as_ushort(__float2half(v));
    asm volatile("st.global.cs.u16 [%0], %1;" :: "l"(p), "h"(u) : "memory");
}

// ---------------- scratch (device globals; allocation-free) ----------------
__device__ __half g_hh[NN * KK * HH];     // hs = tanh(proj)*dinv, fp16 (76.8 MB)
__device__ __half g_kvh[NN * KK * 128];   // per (n,k): [k(64)|v(64)] fp16 (153.6 MB)
__device__ float g_h2r5[NN * HH];         // post-GCN relu, row k=5 (residual + q input)
__device__ float g_pa[NN * HH];
__device__ float g_pb[NN * HH];
__device__ float g_dinv[NN];
__device__ int   g_counts[NN];
__device__ int   g_scan[NN];
__device__ int   g_blocksum[128];
__device__ int   g_blockoff[128];
__device__ int   g_rowstart[NN + 1];
__device__ int   g_cursor[NN];
__device__ int   g_srclist[MM];

// ---------------- small utility kernels ----------------
__global__ void k_zero_counts() {
    int i = blockIdx.x * blockDim.x + threadIdx.x;
    if (i < NN) g_counts[i] = 0;
}

__global__ void k_count(const int* __restrict__ ei) {
    int e = blockIdx.x * blockDim.x + threadIdx.x;
    if (e < MM) atomicAdd(&g_counts[ei[MM + e]], 1);
}

// ---------------- coalesced 3-phase scan (measured 5us total) ----------------
__global__ __launch_bounds__(1024) void k_blockscan() {
    __shared__ int warpsums[32];
    int t = threadIdx.x, lane = t & 31, w = t >> 5;
    int i = blockIdx.x * 1024 + t;
    int v0 = (i < NN) ? g_counts[i] : 0;
    if (i < NN) g_dinv[i] = rsqrtf((float)v0 + 1.0f);
    int v = v0;
#pragma unroll
    for (int off = 1; off < 32; off <<= 1) {
        int x = __shfl_up_sync(0xffffffffu, v, off);
        if (lane >= off) v += x;
    }
    if (lane == 31) warpsums[w] = v;
    __syncthreads();
    if (w == 0) {
        int s = warpsums[lane];
#pragma unroll
        for (int off = 1; off < 32; off <<= 1) {
            int x = __shfl_up_sync(0xffffffffu, s, off);
            if (lane >= off) s += x;
        }
        warpsums[lane] = s;
    }
    __syncthreads();
    int incl = v + (w > 0 ? warpsums[w - 1] : 0);
    if (i < NN) g_scan[i] = incl;
    if (t == 1023) g_blocksum[blockIdx.x] = incl;
}

__global__ void k_scan2() {
    __shared__ int warpsums[4];
    int t = threadIdx.x, lane = t & 31, w = t >> 5;
    int v0 = (t < NBLK) ? g_blocksum[t] : 0;
    int v = v0;
#pragma unroll
    for (int off = 1; off < 32; off <<= 1) {
        int x = __shfl_up_sync(0xffffffffu, v, off);
        if (lane >= off) v += x;
    }
    if (lane == 31) warpsums[w] = v;
    __syncthreads();
    int base = 0;
    for (int j = 0; j < w; j++) base += warpsums[j];
    int incl = v + base;
    if (t < NBLK) g_blockoff[t] = incl - v0;
    if (t == NBLK - 1) g_rowstart[NN] = incl;
}

__global__ void k_apply() {
    int i = blockIdx.x * blockDim.x + threadIdx.x;
    if (i < NN) {
        int excl = g_scan[i] - g_counts[i] + g_blockoff[i >> 10];
        g_rowstart[i] = excl;
        g_cursor[i]   = excl;
    }
}

__global__ void k_fill(const int* __restrict__ ei) {
    int e = blockIdx.x * blockDim.x + threadIdx.x;
    if (e < MM) {
        int d = ei[MM + e];
        int p = atomicAdd(&g_cursor[d], 1);
        g_srclist[p] = ei[e];
    }
}

// ---------------- projection (+ inline ck): hs = tanh(dot12 + ck)*dinv, fp16 --------
__global__ __launch_bounds__(256) void k_projck(
    const float* __restrict__ x, const float* __restrict__ W_proj,
    const float* __restrict__ b_proj, const float* __restrict__ u,
    const float* __restrict__ u_seq) {
    __shared__ float Wp12[12 * HH];
    __shared__ float cks[KK * HH];
    int t = threadIdx.x;
    for (int i = t; i < 12 * HH; i += 256) Wp12[i] = W_proj[i];
    if (t < HH) {
        int c = t;
        float base = b_proj[c];
#pragma unroll
        for (int j = 0; j < 11; j++) base += u[j] * W_proj[(12 + j) * HH + c];
#pragma unroll
        for (int k = 0; k < KK; k++) {
            float val = base;
#pragma unroll
            for (int j = 0; j < 5; j++) val += u_seq[k * 5 + j] * W_proj[(23 + j) * HH + c];
            cks[k * HH + c] = val;
        }
    }
    __syncthreads();
    int g = t >> 6, c = t & 63;
    int n = blockIdx.x * 4 + g;
    float dn = g_dinv[n];
    float s = 0.f;
#pragma unroll
    for (int j = 0; j < 12; j++) s += __ldg(&x[n * 12 + j]) * Wp12[j * HH + c];
    int base = n * (KK * HH) + c;
#pragma unroll
    for (int k = 0; k < KK; k++)
        g_hh[base + k * HH] = __float2half(tanhf(s + cks[k * HH + c]) * dn);
}

// ---------------- fused AGGREGATE + GCN + KV (warp per node) ----------------
struct __align__(16) SG {
    float Wgt[HH * WSTR];       // Wgt[c*66+j] = W_gcn[j][c]
    float Wkvt[128 * WSTR];     // Wkvt[c*66+j] = [Wk|Wv][j][c]
    float arow[12][KK][HH];
    float h2s[12][KK][HH];
    float bg[HH], bkv[128];
};

__global__ __launch_bounds__(384) void k_gcnqkv(
    const float* __restrict__ W_gcn, const float* __restrict__ b_gcn,
    const float* __restrict__ Wk, const float* __restrict__ bk,
    const float* __restrict__ Wv, const float* __restrict__ bv) {
    extern __shared__ char smem_raw[];
    SG& s = *reinterpret_cast<SG*>(smem_raw);
    int t = threadIdx.x, w = t >> 5, l = t & 31;
    for (int i = t; i < HH * HH; i += 384) {
        int j = i >> 6, c = i & 63;
        s.Wgt[c * WSTR + j] = W_gcn[i];
        s.Wkvt[c * WSTR + j] = Wk[i];
        s.Wkvt[(c + 64) * WSTR + j] = Wv[i];
    }
    if (t < HH) { s.bg[t] = b_gcn[t]; s.bkv[t] = bk[t]; s.bkv[64 + t] = bv[t]; }
    __syncthreads();
    const int c0 = l, c1 = l + 32;
    const __half2* hh2 = (const __half2*)g_hh;
    for (int n = blockIdx.x * 12 + w; n < NN; n += gridDim.x * 12) {
        // stage 0: aggregate (4-way unrolled gather)
        {
            float dn = g_dinv[n];
            int s0 = g_rowstart[n], s1 = g_rowstart[n + 1];
            float2 acc[KK];
#pragma unroll
            for (int r = 0; r < KK; r++)
                acc[r] = __half22float2(hh2[(n * KK + r) * 32 + l]);
            int i = s0;
            for (; i + 3 < s1; i += 4) {
                const __half2* pa = hh2 + g_srclist[i]     * (KK * 32) + l;
                const __half2* pb = hh2 + g_srclist[i + 1] * (KK * 32) + l;
                const __half2* pc = hh2 + g_srclist[i + 2] * (KK * 32) + l;
                const __half2* pd = hh2 + g_srclist[i + 3] * (KK * 32) + l;
#pragma unroll
                for (int r = 0; r < KK; r++) {
                    float2 va = __half22float2(pa[r * 32]);
                    float2 vb = __half22float2(pb[r * 32]);
                    float2 vc = __half22float2(pc[r * 32]);
                    float2 vd = __half22float2(pd[r * 32]);
                    acc[r].x += (va.x + vb.x) + (vc.x + vd.x);
                    acc[r].y += (va.y + vb.y) + (vc.y + vd.y);
                }
            }
            for (; i < s1; i++) {
                const __half2* pa = hh2 + g_srclist[i] * (KK * 32) + l;
#pragma unroll
                for (int r = 0; r < KK; r++) {
                    float2 va = __half22float2(pa[r * 32]);
                    acc[r].x += va.x;
                    acc[r].y += va.y;
                }
            }
#pragma unroll
            for (int r = 0; r < KK; r++) {
                s.arow[w][r][2 * l]     = acc[r].x * dn;
                s.arow[w][r][2 * l + 1] = acc[r].y * dn;
            }
        }
        __syncwarp();
        // stage 1: h2 = relu(agg @ Wg + bg)
        {
            ull acc[KK][2];
#pragma unroll
            for (int r = 0; r < KK; r++) { acc[r][0] = 0ull; acc[r][1] = 0ull; }
#pragma unroll
            for (int j2 = 0; j2 < 32; j2++) {
                ull w0 = *(const ull*)&s.Wgt[c0 * WSTR + 2 * j2];
                ull w1 = *(const ull*)&s.Wgt[c1 * WSTR + 2 * j2];
#pragma unroll
                for (int r = 0; r < KK; r++) {
                    ull av = *(const ull*)&s.arow[w][r][2 * j2];
                    ffma2(acc[r][0], av, w0);
                    ffma2(acc[r][1], av, w1);
                }
            }
#pragma unroll
            for (int r = 0; r < KK; r++) {
                float h0 = fmaxf(hsum2(acc[r][0]) + s.bg[c0], 0.f);
                float h1 = fmaxf(hsum2(acc[r][1]) + s.bg[c1], 0.f);
                s.h2s[w][r][c0] = h0;
                s.h2s[w][r][c1] = h1;
                if (r == KK - 1) {
                    g_h2r5[n * HH + c0] = h0;
                    g_h2r5[n * HH + c1] = h1;
                }
            }
        }
        __syncwarp();
        // stage 2: kv = h2 @ [Wk|Wv] + b -> fp16 global, direct coalesced half stores
        {
            ull acc[KK][4];
#pragma unroll
            for (int r = 0; r < KK; r++)
#pragma unroll
                for (int q = 0; q < 4; q++) acc[r][q] = 0ull;
#pragma unroll
            for (int j2 = 0; j2 < 32; j2++) {
                ull w0 = *(const ull*)&s.Wkvt[(l)      * WSTR + 2 * j2];
                ull w1 = *(const ull*)&s.Wkvt[(l + 32) * WSTR + 2 * j2];
                ull w2 = *(const ull*)&s.Wkvt[(l + 64) * WSTR + 2 * j2];
                ull w3 = *(const ull*)&s.Wkvt[(l + 96) * WSTR + 2 * j2];
#pragma unroll
                for (int r = 0; r < KK; r++) {
                    ull hv = *(const ull*)&s.h2s[w][r][2 * j2];
                    ffma2(acc[r][0], hv, w0);
                    ffma2(acc[r][1], hv, w1);
                    ffma2(acc[r][2], hv, w2);
                    ffma2(acc[r][3], hv, w3);
                }
            }
#pragma unroll
            for (int r = 0; r < KK; r++) {
                __half* kvp = &g_kvh[(n * KK + r) * 128];
                sth_cs(kvp + l,      hsum2(acc[r][0]) + s.bkv[l]);
                sth_cs(kvp + l + 32, hsum2(acc[r][1]) + s.bkv[l + 32]);
                sth_cs(kvp + l + 64, hsum2(acc[r][2]) + s.bkv[l + 64]);
                sth_cs(kvp + l + 96, hsum2(acc[r][3]) + s.bkv[l + 96]);
            }
        }
    }
}

// ---- fused Q + attention + LN1 + FF + LN2 + decoder-precompute (warp per node) ----
struct __align__(16) SAF {
    float Wqt[HH * WSTR];
    float Wot[HH * WSTR];
    float W1t[128 * WSTR];
    float W2t[HH * 130];
    float Wat[HH * WSTR];
    float Wbt[HH * WSTR];
    float kv[12][KK * 128];
    float qv[12][HH];
    float ao[12][HH];
    float hm[12][HH];
    float z1[12][2 * HH];
    float aw[12][NHD * KK];
    float bq[HH], bo[HH], g1[HH], b1[HH], bb2[HH], g2[HH], be2[HH], b1d[HH];
    float bb1[2 * HH];
};

__global__ __launch_bounds__(384) void k_attnff(
    const float* __restrict__ Wq, const float* __restrict__ bq,
    const float* __restrict__ Wo, const float* __restrict__ bo,
    const float* __restrict__ ln1g, const float* __restrict__ ln1b,
    const float* __restrict__ W_ff1, const float* __restrict__ b_ff1,
    const float* __restrict__ W_ff2, const float* __restrict__ b_ff2,
    const float* __restrict__ ln2g, const float* __restrict__ ln2b,
    const float* __restrict__ Wd1, const float* __restrict__ bd1) {
    extern __shared__ char smem_raw[];
    SAF& s = *reinterpret_cast<SAF*>(smem_raw);
    int t = threadIdx.x, w = t >> 5, l = t & 31;
    for (int i = t; i < HH * HH; i += 384) {
        int j = i >> 6, c = i & 63;
        s.Wqt[c * WSTR + j] = Wq[i];
        s.Wot[c * WSTR + j] = Wo[i];
        s.Wat[c * WSTR + j] = Wd1[i];
        s.Wbt[c * WSTR + j] = Wd1[HH * HH + i];
    }
    for (int i = t; i < HH * 128; i += 384) {
        int j = i >> 7, c = i & 127;
        s.W1t[c * WSTR + j] = W_ff1[i];
    }
    for (int i = t; i < 128 * HH; i += 384) {
        int j = i >> 6, c = i & 63;
        s.W2t[c * 130 + j] = W_ff2[i];
    }
    if (t < HH) {
        s.bq[t] = bq[t]; s.bo[t] = bo[t]; s.g1[t] = ln1g[t]; s.b1[t] = ln1b[t];
        s.bb2[t] = b_ff2[t]; s.g2[t] = ln2g[t]; s.be2[t] = ln2b[t];
        s.b1d[t] = bd1[t];
    }
    if (t < 2 * HH) s.bb1[t] = b_ff1[t];
    __syncthreads();
    const int c0 = l, c1 = l + 32;
    int c2 = 2 * l, c4 = 4 * l;
    for (int n = blockIdx.x * 12 + w; n < NN; n += gridDim.x * 12) {
        // load h2row5 (residual + q input) and kv (fp16 streaming -> fp32 smem)
        float r50 = g_h2r5[n * HH + c0];
        float r51 = g_h2r5[n * HH + c1];
        s.hm[w][c0] = r50; s.hm[w][c1] = r51;
#pragma unroll
        for (int r = 0; r < KK; r++) {
            ull raw = __ldcs((const ull*)&g_kvh[(n * KK + r) * 128 + c4]);
            __half2 h0 = *(__half2*)&raw;
            __half2 h1 = *((__half2*)&raw + 1);
            float2 f0 = __half22float2(h0), f1 = __half22float2(h1);
            *(float4*)&s.kv[w][r * 128 + c4] = make_float4(f0.x, f0.y, f1.x, f1.y);
        }
        __syncwarp();
        // q = h2row5 @ Wq + bq
        {
            ull q0 = 0ull, q1 = 0ull;
#pragma unroll
            for (int j2 = 0; j2 < 32; j2++) {
                ull hv = *(const ull*)&s.hm[w][2 * j2];
                ull w0 = *(const ull*)&s.Wqt[c0 * WSTR + 2 * j2];
                ull w1 = *(const ull*)&s.Wqt[c1 * WSTR + 2 * j2];
                ffma2(q0, hv, w0);
                ffma2(q1, hv, w1);
            }
            s.qv[w][c0] = hsum2(q0) + s.bq[c0];
            s.qv[w][c1] = hsum2(q1) + s.bq[c1];
        }
        __syncwarp();
        // scores
        float sc = 0.f;
        int hh = l / KK, kk = l - hh * KK;
        if (l < NHD * KK) {
#pragma unroll
            for (int d = 0; d < DHD; d++)
                sc += s.qv[w][hh * DHD + d] * s.kv[w][kk * 128 + hh * DHD + d];
            sc *= 0.25f;
        }
        float mysc[KK];
#pragma unroll
        for (int j = 0; j < KK; j++)
            mysc[j] = __shfl_sync(0xffffffffu, sc, (l & 3) * KK + j);
        if (l < NHD) {
            float mx = mysc[0];
#pragma unroll
            for (int j = 1; j < KK; j++) mx = fmaxf(mx, mysc[j]);
            float sum = 0.f;
#pragma unroll
            for (int j = 0; j < KK; j++) { mysc[j] = expf(mysc[j] - mx); sum += mysc[j]; }
            float inv = 1.0f / sum;
#pragma unroll
            for (int j = 0; j < KK; j++) s.aw[w][l * KK + j] = mysc[j] * inv;
        }
        __syncwarp();
        // AV
        int hd = l >> 3;
        float a0 = 0.f, a1 = 0.f;
#pragma unroll
        for (int j = 0; j < KK; j++) {
            float wgt = s.aw[w][hd * KK + j];
            float2 vv = *(const float2*)&s.kv[w][j * 128 + 64 + c2];
            a0 += wgt * vv.x; a1 += wgt * vv.y;
        }
        s.ao[w][c2] = a0; s.ao[w][c2 + 1] = a1;
        __syncwarp();
        // Wo GEMV + residual + LN1
        ull o0 = 0ull, o1 = 0ull;
#pragma unroll
        for (int j2 = 0; j2 < 32; j2++) {
            ull av = *(const ull*)&s.ao[w][2 * j2];
            ull w0 = *(const ull*)&s.Wot[c0 * WSTR + 2 * j2];
            ull w1 = *(const ull*)&s.Wot[c1 * WSTR + 2 * j2];
            ffma2(o0, av, w0);
            ffma2(o1, av, w1);
        }
        float y0 = r50 + hsum2(o0) + s.bo[c0];
        float y1 = r51 + hsum2(o1) + s.bo[c1];
        float s1 = y0 + y1, s2 = y0 * y0 + y1 * y1;
#pragma unroll
        for (int off = 16; off > 0; off >>= 1) {
            s1 += __shfl_xor_sync(0xffffffffu, s1, off);
            s2 += __shfl_xor_sync(0xffffffffu, s2, off);
        }
        float m = s1 * (1.0f / HH);
        float var = s2 * (1.0f / HH) - m * m;
        float rstd = rsqrtf(var + 1e-5f);
        float hm0 = (y0 - m) * rstd * s.g1[c0] + s.b1[c0];
        float hm1 = (y1 - m) * rstd * s.g1[c1] + s.b1[c1];
        __syncwarp();
        s.hm[w][c0] = hm0; s.hm[w][c1] = hm1;
        __syncwarp();
        // FF1
        {
            ull f0 = 0ull, f1 = 0ull, f2 = 0ull, f3 = 0ull;
#pragma unroll
            for (int j2 = 0; j2 < 32; j2++) {
                ull hv = *(const ull*)&s.hm[w][2 * j2];
                ull w0 = *(const ull*)&s.W1t[(l)      * WSTR + 2 * j2];
                ull w1 = *(const ull*)&s.W1t[(l + 32) * WSTR + 2 * j2];
                ull w2 = *(const ull*)&s.W1t[(l + 64) * WSTR + 2 * j2];
                ull w3 = *(const ull*)&s.W1t[(l + 96) * WSTR + 2 * j2];
                ffma2(f0, hv, w0);
                ffma2(f1, hv, w1);
                ffma2(f2, hv, w2);
                ffma2(f3, hv, w3);
            }
            s.z1[w][l]      = fmaxf(hsum2(f0) + s.bb1[l], 0.f);
            s.z1[w][l + 32] = fmaxf(hsum2(f1) + s.bb1[l + 32], 0.f);
            s.z1[w][l + 64] = fmaxf(hsum2(f2) + s.bb1[l + 64], 0.f);
            s.z1[w][l + 96] = fmaxf(hsum2(f3) + s.bb1[l + 96], 0.f);
        }
        __syncwarp();
        // FF2 + residual + LN2
        ull g0 = 0ull, g1a = 0ull;
#pragma unroll
        for (int j2 = 0; j2 < 64; j2++) {
            ull zv = *(const ull*)&s.z1[w][2 * j2];
            ull w0 = *(const ull*)&s.W2t[c0 * 130 + 2 * j2];
            ull w1 = *(const ull*)&s.W2t[c1 * 130 + 2 * j2];
            ffma2(g0, zv, w0);
            ffma2(g1a, zv, w1);
        }
        float u0 = hm0 + hsum2(g0) + s.bb2[c0];
        float u1 = hm1 + hsum2(g1a) + s.bb2[c1];
        float t1 = u0 + u1, t2 = u0 * u0 + u1 * u1;
#pragma unroll
        for (int off = 16; off > 0; off >>= 1) {
            t1 += __shfl_xor_sync(0xffffffffu, t1, off);
            t2 += __shfl_xor_sync(0xffffffffu, t2, off);
        }
        float m2 = t1 * (1.0f / HH);
        float var2 = t2 * (1.0f / HH) - m2 * m2;
        float rstd2 = rsqrtf(var2 + 1e-5f);
        float hf0 = (u0 - m2) * rstd2 * s.g2[c0] + s.be2[c0];
        float hf1 = (u1 - m2) * rstd2 * s.g2[c1] + s.be2[c1];
        __syncwarp();
        // decoder precompute (share hf via z1 buffer)
        s.z1[w][c0] = hf0; s.z1[w][c1] = hf1;
        __syncwarp();
        ull pa0 = 0ull, pa1 = 0ull, pb0 = 0ull, pb1 = 0ull;
#pragma unroll
        for (int j2 = 0; j2 < 32; j2++) {
            ull v = *(const ull*)&s.z1[w][2 * j2];
            ull wa0 = *(const ull*)&s.Wat[c0 * WSTR + 2 * j2];
            ull wa1 = *(const ull*)&s.Wat[c1 * WSTR + 2 * j2];
            ull wb0 = *(const ull*)&s.Wbt[c0 * WSTR + 2 * j2];
            ull wb1 = *(const ull*)&s.Wbt[c1 * WSTR + 2 * j2];
            ffma2(pa0, v, wa0);
            ffma2(pa1, v, wa1);
            ffma2(pb0, v, wb0);
            ffma2(pb1, v, wb1);
        }
        g_pa[n * HH + c0] = hsum2(pa0);
        g_pa[n * HH + c1] = hsum2(pa1);
        g_pb[n * HH + c0] = hsum2(pb0) + s.b1d[c0];
        g_pb[n * HH + c1] = hsum2(pb1) + s.b1d[c1];
        __syncwarp();
    }
}

// ---------------- edge decoder (factorized, FFMA2 W2) ----------------
struct __align__(16) SDec3 {
    float z1[8][HH];      // offset 0 (8B-aligned) — required for LDS.64
    float2 W2p[32][32];
    float W1c[5 * HH];
    float W1d[4 * HH];
    float W3[32];
    float b2[32];
    float b3;
};

__global__ __launch_bounds__(256) void k_dec(
    const int* __restrict__ ei,
    const float* __restrict__ edge_attr, const float* __restrict__ edge_seq,
    const float* __restrict__ Wd1,
    const float* __restrict__ Wd2, const float* __restrict__ bd2,
    const float* __restrict__ Wd3, const float* __restrict__ bd3,
    float* __restrict__ out) {
    extern __shared__ char smem_raw[];
    SDec3& s = *reinterpret_cast<SDec3*>(smem_raw);
    int t = threadIdx.x, w = t >> 5, l = t & 31;
    for (int i = t; i < 5 * HH; i += 256) s.W1c[i] = Wd1[(2 * HH) * HH + i];
    for (int i = t; i < 4 * HH; i += 256) s.W1d[i] = Wd1[(2 * HH + 5) * HH + i];
    for (int i = t; i < 1024; i += 256) {
        int j = i >> 5, ll = i & 31;
        s.W2p[j][ll] = make_float2(Wd2[(2 * j) * 32 + ll], Wd2[(2 * j + 1) * 32 + ll]);
    }
    if (t < 32) { s.W3[t] = Wd3[t]; s.b2[t] = bd2[t]; }
    if (t == 0) s.b3 = bd3[0];
    __syncthreads();
    float* z1 = s.z1[w];
    int c = 2 * l;
    for (int e = blockIdx.x * 8 + w; e < MM; e += gridDim.x * 8) {
        int src = ei[e], dst = ei[MM + e];
        float2 pav = *(const float2*)&g_pa[src * HH + c];
        float2 pbv = *(const float2*)&g_pb[dst * HH + c];
        float zx = pav.x + pbv.x, zy = pav.y + pbv.y;
#pragma unroll
        for (int j = 0; j < 5; j++) {
            float ev = __ldg(&edge_attr[e * 5 + j]);
            float2 wv = *(const float2*)&s.W1c[j * HH + c];
            zx += ev * wv.x; zy += ev * wv.y;
        }
#pragma unroll
        for (int j = 0; j < 4; j++) {
            float ev = __ldg(&edge_seq[e * (KK * 4) + (KK - 1) * 4 + j]);
            float2 wv = *(const float2*)&s.W1d[j * HH + c];
            zx += ev * wv.x; zy += ev * wv.y;
        }
        z1[c] = fmaxf(zx, 0.f);
        z1[c + 1] = fmaxf(zy, 0.f);
        __syncwarp();
        ull acc = pack2(s.b2[l], 0.f);
#pragma unroll
        for (int j = 0; j < 32; j++) {
            ull z2 = *(const ull*)&z1[2 * j];
            ull w2 = *(const ull*)&s.W2p[j][l];
            ffma2(acc, z2, w2);
        }
        float2 av = unpack2(acc);
        float a2 = fmaxf(av.x + av.y, 0.f);
        float p = a2 * s.W3[l];
#pragma unroll
        for (int off = 16; off > 0; off >>= 1) p += __shfl_down_sync(0xffffffffu, p, off);
        if (l == 0) out[e] = p + s.b3;
        __syncwarp();
    }
}

// ---------------- launch ----------------
extern "C" void kernel_launch(void* const* d_in, const int* in_sizes, int n_in,
                              void* d_out, int out_size) {
    const float* x        = (const float*)d_in[0];
    const int*   ei       = (const int*)  d_in[1];
    const float* eattr    = (const float*)d_in[2];
    const float* u        = (const float*)d_in[3];
    const float* eseq     = (const float*)d_in[4];
    const float* useq     = (const float*)d_in[5];
    const float* W_proj   = (const float*)d_in[6];
    const float* b_proj   = (const float*)d_in[7];
    const float* W_gcn    = (const float*)d_in[8];
    const float* b_gcn    = (const float*)d_in[9];
    const float* Wq       = (const float*)d_in[10];
    const float* bq       = (const float*)d_in[11];
    const float* Wk       = (const float*)d_in[12];
    const float* bk       = (const float*)d_in[13];
    const float* Wv       = (const float*)d_in[14];
    const float* bv       = (const float*)d_in[15];
    const float* Wo       = (const float*)d_in[16];
    const float* bo       = (const float*)d_in[17];
    const float* ln1g     = (const float*)d_in[18];
    const float* ln1b     = (const float*)d_in[19];
    const float* W_ff1    = (const float*)d_in[20];
    const float* b_ff1    = (const float*)d_in[21];
    const float* W_ff2    = (const float*)d_in[22];
    const float* b_ff2    = (const float*)d_in[23];
    const float* ln2g     = (const float*)d_in[24];
    const float* ln2b     = (const float*)d_in[25];
    const float* Wd1      = (const float*)d_in[26];
    const float* bd1      = (const float*)d_in[27];
    const float* Wd2      = (const float*)d_in[28];
    const float* bd2      = (const float*)d_in[29];
    const float* Wd3      = (const float*)d_in[30];
    const float* bd3      = (const float*)d_in[31];
    float* out = (float*)d_out;

    cudaFuncSetAttribute(k_gcnqkv, cudaFuncAttributeMaxDynamicSharedMemorySize, (int)sizeof(SG));
    cudaFuncSetAttribute(k_attnff, cudaFuncAttributeMaxDynamicSharedMemorySize, (int)sizeof(SAF));
    cudaFuncSetAttribute(k_dec,    cudaFuncAttributeMaxDynamicSharedMemorySize, (int)sizeof(SDec3));

    k_zero_counts<<<(NN + 255) / 256, 256>>>();
    k_count<<<(MM + 255) / 256, 256>>>(ei);
    k_blockscan<<<NBLK, 1024>>>();
    k_scan2<<<1, 128>>>();
    k_apply<<<(NN + 255) / 256, 256>>>();
    k_fill<<<(MM + 255) / 256, 256>>>(ei);
    k_projck<<<NN / 4, 256>>>(x, W_proj, b_proj, u, useq);
    k_gcnqkv<<<1184, 384, sizeof(SG)>>>(W_gcn, b_gcn, Wk, bk, Wv, bv);
    k_attnff<<<592, 384, sizeof(SAF)>>>(Wq, bq, Wo, bo, ln1g, ln1b, W_ff1, b_ff1,
                                        W_ff2, b_ff2, ln2g, ln2b, Wd1, bd1);
    k_dec<<<2048, 256, sizeof(SDec3)>>>(ei, eattr, eseq, Wd1, Wd2, bd2, Wd3, bd3, out);
}

// round 13
// speedup vs baseline: 1.6786x; 1.0055x over previous
#include <cuda_runtime.h>
#include <cuda_fp16.h>
#include <math.h>

#define NN 100000
#define MM 800000
#define KK 6
#define HH 64
#define NHD 4
#define DHD 16
#define NBLK 98   // ceil(NN/1024)
#define WSTR 66   // padded transposed-weight row stride (floats)

typedef unsigned long long ull;

// ---------------- packed f32x2 helpers (sm_103a FFMA2 path) ----------------
__device__ __forceinline__ ull pack2(float lo, float hi) {
    ull r;
    asm("mov.b64 %0, {%1, %2};" : "=l"(r) : "f"(lo), "f"(hi));
    return r;
}
__device__ __forceinline__ void ffma2(ull& d, ull a, ull b) {
    asm("fma.rn.f32x2 %0, %1, %2, %0;" : "+l"(d) : "l"(a), "l"(b));
}
__device__ __forceinline__ float2 unpack2(ull v) {
    float lo, hi;
    asm("mov.b64 {%0, %1}, %2;" : "=f"(lo), "=f"(hi) : "l"(v));
    return make_float2(lo, hi);
}
__device__ __forceinline__ float hsum2(ull v) {
    float2 p = unpack2(v);
    return p.x + p.y;
}
// streaming 16-bit store (evict-first: kv is write-once/read-once)
__device__ __forceinline__ void sth_cs(__half* p, float v) {
    unsigned short u = __half_as_ushort(__float2half(v));
    asm volatile("st.global.cs.u16 [%0], %1;" :: "l"(p), "h"(u) : "memory");
}

// ---------------- scratch (device globals; allocation-free) ----------------
__device__ __half g_hh[NN * KK * HH];     // hs = tanh(proj)*dinv, fp16 (76.8 MB)
__device__ __half g_kvh[NN * KK * 128];   // per (n,k): [k(64)|v(64)] fp16 (153.6 MB)
__device__ float g_h2r5[NN * HH];         // post-GCN relu, row k=5 (residual + q input)
__device__ __half g_pah[NN * HH];         // h_final @ Wd1[0:64], fp16 (12.8 MB)
__device__ __half g_pbh[NN * HH];         // h_final @ Wd1[64:128] + b1, fp16
__device__ float g_dinv[NN];
__device__ int   g_counts[NN];
__device__ int   g_scan[NN];
__device__ int   g_blocksum[128];
__device__ int   g_blockoff[128];
__device__ int   g_rowstart[NN + 1];
__device__ int   g_cursor[NN];
__device__ int   g_srclist[MM];

// ---------------- small utility kernels ----------------
__global__ void k_zero_counts() {
    int i = blockIdx.x * blockDim.x + threadIdx.x;
    if (i < NN) g_counts[i] = 0;
}

__global__ void k_count(const int* __restrict__ ei) {
    int e = blockIdx.x * blockDim.x + threadIdx.x;
    if (e < MM) atomicAdd(&g_counts[ei[MM + e]], 1);
}

// ---------------- coalesced 3-phase scan (measured 5us total) ----------------
__global__ __launch_bounds__(1024) void k_blockscan() {
    __shared__ int warpsums[32];
    int t = threadIdx.x, lane = t & 31, w = t >> 5;
    int i = blockIdx.x * 1024 + t;
    int v0 = (i < NN) ? g_counts[i] : 0;
    if (i < NN) g_dinv[i] = rsqrtf((float)v0 + 1.0f);
    int v = v0;
#pragma unroll
    for (int off = 1; off < 32; off <<= 1) {
        int x = __shfl_up_sync(0xffffffffu, v, off);
        if (lane >= off) v += x;
    }
    if (lane == 31) warpsums[w] = v;
    __syncthreads();
    if (w == 0) {
        int s = warpsums[lane];
#pragma unroll
        for (int off = 1; off < 32; off <<= 1) {
            int x = __shfl_up_sync(0xffffffffu, s, off);
            if (lane >= off) s += x;
        }
        warpsums[lane] = s;
    }
    __syncthreads();
    int incl = v + (w > 0 ? warpsums[w - 1] : 0);
    if (i < NN) g_scan[i] = incl;
    if (t == 1023) g_blocksum[blockIdx.x] = incl;
}

__global__ void k_scan2() {
    __shared__ int warpsums[4];
    int t = threadIdx.x, lane = t & 31, w = t >> 5;
    int v0 = (t < NBLK) ? g_blocksum[t] : 0;
    int v = v0;
#pragma unroll
    for (int off = 1; off < 32; off <<= 1) {
        int x = __shfl_up_sync(0xffffffffu, v, off);
        if (lane >= off) v += x;
    }
    if (lane == 31) warpsums[w] = v;
    __syncthreads();
    int base = 0;
    for (int j = 0; j < w; j++) base += warpsums[j];
    int incl = v + base;
    if (t < NBLK) g_blockoff[t] = incl - v0;
    if (t == NBLK - 1) g_rowstart[NN] = incl;
}

__global__ void k_apply() {
    int i = blockIdx.x * blockDim.x + threadIdx.x;
    if (i < NN) {
        int excl = g_scan[i] - g_counts[i] + g_blockoff[i >> 10];
        g_rowstart[i] = excl;
        g_cursor[i]   = excl;
    }
}

__global__ void k_fill(const int* __restrict__ ei) {
    int e = blockIdx.x * blockDim.x + threadIdx.x;
    if (e < MM) {
        int d = ei[MM + e];
        int p = atomicAdd(&g_cursor[d], 1);
        g_srclist[p] = ei[e];
    }
}

// ---------------- projection (+ inline ck): hs = tanh(dot12 + ck)*dinv, fp16 --------
__global__ __launch_bounds__(256) void k_projck(
    const float* __restrict__ x, const float* __restrict__ W_proj,
    const float* __restrict__ b_proj, const float* __restrict__ u,
    const float* __restrict__ u_seq) {
    __shared__ float Wp12[12 * HH];
    __shared__ float cks[KK * HH];
    int t = threadIdx.x;
    for (int i = t; i < 12 * HH; i += 256) Wp12[i] = W_proj[i];
    if (t < HH) {
        int c = t;
        float base = b_proj[c];
#pragma unroll
        for (int j = 0; j < 11; j++) base += u[j] * W_proj[(12 + j) * HH + c];
#pragma unroll
        for (int k = 0; k < KK; k++) {
            float val = base;
#pragma unroll
            for (int j = 0; j < 5; j++) val += u_seq[k * 5 + j] * W_proj[(23 + j) * HH + c];
            cks[k * HH + c] = val;
        }
    }
    __syncthreads();
    int g = t >> 6, c = t & 63;
    int n = blockIdx.x * 4 + g;
    float dn = g_dinv[n];
    float s = 0.f;
#pragma unroll
    for (int j = 0; j < 12; j++) s += __ldg(&x[n * 12 + j]) * Wp12[j * HH + c];
    int base = n * (KK * HH) + c;
#pragma unroll
    for (int k = 0; k < KK; k++)
        g_hh[base + k * HH] = __float2half(tanhf(s + cks[k * HH + c]) * dn);
}

// ---------------- fused AGGREGATE + GCN + KV (warp per node) ----------------
struct __align__(16) SG {
    float Wgt[HH * WSTR];       // Wgt[c*66+j] = W_gcn[j][c]
    float Wkvt[128 * WSTR];     // Wkvt[c*66+j] = [Wk|Wv][j][c]
    float arow[12][KK][HH];
    float h2s[12][KK][HH];
    float bg[HH], bkv[128];
};

__global__ __launch_bounds__(384) void k_gcnqkv(
    const float* __restrict__ W_gcn, const float* __restrict__ b_gcn,
    const float* __restrict__ Wk, const float* __restrict__ bk,
    const float* __restrict__ Wv, const float* __restrict__ bv) {
    extern __shared__ char smem_raw[];
    SG& s = *reinterpret_cast<SG*>(smem_raw);
    int t = threadIdx.x, w = t >> 5, l = t & 31;
    for (int i = t; i < HH * HH; i += 384) {
        int j = i >> 6, c = i & 63;
        s.Wgt[c * WSTR + j] = W_gcn[i];
        s.Wkvt[c * WSTR + j] = Wk[i];
        s.Wkvt[(c + 64) * WSTR + j] = Wv[i];
    }
    if (t < HH) { s.bg[t] = b_gcn[t]; s.bkv[t] = bk[t]; s.bkv[64 + t] = bv[t]; }
    __syncthreads();
    const int c0 = l, c1 = l + 32;
    const __half2* hh2 = (const __half2*)g_hh;
    for (int n = blockIdx.x * 12 + w; n < NN; n += gridDim.x * 12) {
        // stage 0: aggregate (4-way unrolled gather)
        {
            float dn = g_dinv[n];
            int s0 = g_rowstart[n], s1 = g_rowstart[n + 1];
            float2 acc[KK];
#pragma unroll
            for (int r = 0; r < KK; r++)
                acc[r] = __half22float2(hh2[(n * KK + r) * 32 + l]);
            int i = s0;
            for (; i + 3 < s1; i += 4) {
                const __half2* pa = hh2 + g_srclist[i]     * (KK * 32) + l;
                const __half2* pb = hh2 + g_srclist[i + 1] * (KK * 32) + l;
                const __half2* pc = hh2 + g_srclist[i + 2] * (KK * 32) + l;
                const __half2* pd = hh2 + g_srclist[i + 3] * (KK * 32) + l;
#pragma unroll
                for (int r = 0; r < KK; r++) {
                    float2 va = __half22float2(pa[r * 32]);
                    float2 vb = __half22float2(pb[r * 32]);
                    float2 vc = __half22float2(pc[r * 32]);
                    float2 vd = __half22float2(pd[r * 32]);
                    acc[r].x += (va.x + vb.x) + (vc.x + vd.x);
                    acc[r].y += (va.y + vb.y) + (vc.y + vd.y);
                }
            }
            for (; i < s1; i++) {
                const __half2* pa = hh2 + g_srclist[i] * (KK * 32) + l;
#pragma unroll
                for (int r = 0; r < KK; r++) {
                    float2 va = __half22float2(pa[r * 32]);
                    acc[r].x += va.x;
                    acc[r].y += va.y;
                }
            }
#pragma unroll
            for (int r = 0; r < KK; r++) {
                s.arow[w][r][2 * l]     = acc[r].x * dn;
                s.arow[w][r][2 * l + 1] = acc[r].y * dn;
            }
        }
        __syncwarp();
        // stage 1: h2 = relu(agg @ Wg + bg)
        {
            ull acc[KK][2];
#pragma unroll
            for (int r = 0; r < KK; r++) { acc[r][0] = 0ull; acc[r][1] = 0ull; }
#pragma unroll
            for (int j2 = 0; j2 < 32; j2++) {
                ull w0 = *(const ull*)&s.Wgt[c0 * WSTR + 2 * j2];
                ull w1 = *(const ull*)&s.Wgt[c1 * WSTR + 2 * j2];
#pragma unroll
                for (int r = 0; r < KK; r++) {
                    ull av = *(const ull*)&s.arow[w][r][2 * j2];
                    ffma2(acc[r][0], av, w0);
                    ffma2(acc[r][1], av, w1);
                }
            }
#pragma unroll
            for (int r = 0; r < KK; r++) {
                float h0 = fmaxf(hsum2(acc[r][0]) + s.bg[c0], 0.f);
                float h1 = fmaxf(hsum2(acc[r][1]) + s.bg[c1], 0.f);
                s.h2s[w][r][c0] = h0;
                s.h2s[w][r][c1] = h1;
                if (r == KK - 1) {
                    g_h2r5[n * HH + c0] = h0;
                    g_h2r5[n * HH + c1] = h1;
                }
            }
        }
        __syncwarp();
        // stage 2: kv = h2 @ [Wk|Wv] + b -> fp16 global, direct coalesced half stores
        {
            ull acc[KK][4];
#pragma unroll
            for (int r = 0; r < KK; r++)
#pragma unroll
                for (int q = 0; q < 4; q++) acc[r][q] = 0ull;
#pragma unroll
            for (int j2 = 0; j2 < 32; j2++) {
                ull w0 = *(const ull*)&s.Wkvt[(l)      * WSTR + 2 * j2];
                ull w1 = *(const ull*)&s.Wkvt[(l + 32) * WSTR + 2 * j2];
                ull w2 = *(const ull*)&s.Wkvt[(l + 64) * WSTR + 2 * j2];
                ull w3 = *(const ull*)&s.Wkvt[(l + 96) * WSTR + 2 * j2];
#pragma unroll
                for (int r = 0; r < KK; r++) {
                    ull hv = *(const ull*)&s.h2s[w][r][2 * j2];
                    ffma2(acc[r][0], hv, w0);
                    ffma2(acc[r][1], hv, w1);
                    ffma2(acc[r][2], hv, w2);
                    ffma2(acc[r][3], hv, w3);
                }
            }
#pragma unroll
            for (int r = 0; r < KK; r++) {
                __half* kvp = &g_kvh[(n * KK + r) * 128];
                sth_cs(kvp + l,      hsum2(acc[r][0]) + s.bkv[l]);
                sth_cs(kvp + l + 32, hsum2(acc[r][1]) + s.bkv[l + 32]);
                sth_cs(kvp + l + 64, hsum2(acc[r][2]) + s.bkv[l + 64]);
                sth_cs(kvp + l + 96, hsum2(acc[r][3]) + s.bkv[l + 96]);
            }
        }
    }
}

// ---- fused Q + attention + LN1 + FF + LN2 + decoder-precompute (warp per node) ----
struct __align__(16) SAF {
    float Wqt[HH * WSTR];
    float Wot[HH * WSTR];
    float W1t[128 * WSTR];
    float W2t[HH * 130];
    float Wat[HH * WSTR];
    float Wbt[HH * WSTR];
    float kv[12][KK * 128];
    float qv[12][HH];
    float ao[12][HH];
    float hm[12][HH];
    float z1[12][2 * HH];
    float aw[12][NHD * KK];
    float bq[HH], bo[HH], g1[HH], b1[HH], bb2[HH], g2[HH], be2[HH], b1d[HH];
    float bb1[2 * HH];
};

__global__ __launch_bounds__(384) void k_attnff(
    const float* __restrict__ Wq, const float* __restrict__ bq,
    const float* __restrict__ Wo, const float* __restrict__ bo,
    const float* __restrict__ ln1g, const float* __restrict__ ln1b,
    const float* __restrict__ W_ff1, const float* __restrict__ b_ff1,
    const float* __restrict__ W_ff2, const float* __restrict__ b_ff2,
    const float* __restrict__ ln2g, const float* __restrict__ ln2b,
    const float* __restrict__ Wd1, const float* __restrict__ bd1) {
    extern __shared__ char smem_raw[];
    SAF& s = *reinterpret_cast<SAF*>(smem_raw);
    int t = threadIdx.x, w = t >> 5, l = t & 31;
    for (int i = t; i < HH * HH; i += 384) {
        int j = i >> 6, c = i & 63;
        s.Wqt[c * WSTR + j] = Wq[i];
        s.Wot[c * WSTR + j] = Wo[i];
        s.Wat[c * WSTR + j] = Wd1[i];
        s.Wbt[c * WSTR + j] = Wd1[HH * HH + i];
    }
    for (int i = t; i < HH * 128; i += 384) {
        int j = i >> 7, c = i & 127;
        s.W1t[c * WSTR + j] = W_ff1[i];
    }
    for (int i = t; i < 128 * HH; i += 384) {
        int j = i >> 6, c = i & 63;
        s.W2t[c * 130 + j] = W_ff2[i];
    }
    if (t < HH) {
        s.bq[t] = bq[t]; s.bo[t] = bo[t]; s.g1[t] = ln1g[t]; s.b1[t] = ln1b[t];
        s.bb2[t] = b_ff2[t]; s.g2[t] = ln2g[t]; s.be2[t] = ln2b[t];
        s.b1d[t] = bd1[t];
    }
    if (t < 2 * HH) s.bb1[t] = b_ff1[t];
    __syncthreads();
    const int c0 = l, c1 = l + 32;
    int c2 = 2 * l, c4 = 4 * l;
    for (int n = blockIdx.x * 12 + w; n < NN; n += gridDim.x * 12) {
        // load h2row5 (residual + q input) and kv (fp16 streaming -> fp32 smem)
        float r50 = g_h2r5[n * HH + c0];
        float r51 = g_h2r5[n * HH + c1];
        s.hm[w][c0] = r50; s.hm[w][c1] = r51;
#pragma unroll
        for (int r = 0; r < KK; r++) {
            ull raw = __ldcs((const ull*)&g_kvh[(n * KK + r) * 128 + c4]);
            __half2 h0 = *(__half2*)&raw;
            __half2 h1 = *((__half2*)&raw + 1);
            float2 f0 = __half22float2(h0), f1 = __half22float2(h1);
            *(float4*)&s.kv[w][r * 128 + c4] = make_float4(f0.x, f0.y, f1.x, f1.y);
        }
        __syncwarp();
        // q = h2row5 @ Wq + bq
        {
            ull q0 = 0ull, q1 = 0ull;
#pragma unroll
            for (int j2 = 0; j2 < 32; j2++) {
                ull hv = *(const ull*)&s.hm[w][2 * j2];
                ull w0 = *(const ull*)&s.Wqt[c0 * WSTR + 2 * j2];
                ull w1 = *(const ull*)&s.Wqt[c1 * WSTR + 2 * j2];
                ffma2(q0, hv, w0);
                ffma2(q1, hv, w1);
            }
            s.qv[w][c0] = hsum2(q0) + s.bq[c0];
            s.qv[w][c1] = hsum2(q1) + s.bq[c1];
        }
        __syncwarp();
        // scores
        float sc = 0.f;
        int hh = l / KK, kk = l - hh * KK;
        if (l < NHD * KK) {
#pragma unroll
            for (int d = 0; d < DHD; d++)
                sc += s.qv[w][hh * DHD + d] * s.kv[w][kk * 128 + hh * DHD + d];
            sc *= 0.25f;
        }
        float mysc[KK];
#pragma unroll
        for (int j = 0; j < KK; j++)
            mysc[j] = __shfl_sync(0xffffffffu, sc, (l & 3) * KK + j);
        if (l < NHD) {
            float mx = mysc[0];
#pragma unroll
            for (int j = 1; j < KK; j++) mx = fmaxf(mx, mysc[j]);
            float sum = 0.f;
#pragma unroll
            for (int j = 0; j < KK; j++) { mysc[j] = expf(mysc[j] - mx); sum += mysc[j]; }
            float inv = 1.0f / sum;
#pragma unroll
            for (int j = 0; j < KK; j++) s.aw[w][l * KK + j] = mysc[j] * inv;
        }
        __syncwarp();
        // AV
        int hd = l >> 3;
        float a0 = 0.f, a1 = 0.f;
#pragma unroll
        for (int j = 0; j < KK; j++) {
            float wgt = s.aw[w][hd * KK + j];
            float2 vv = *(const float2*)&s.kv[w][j * 128 + 64 + c2];
            a0 += wgt * vv.x; a1 += wgt * vv.y;
        }
        s.ao[w][c2] = a0; s.ao[w][c2 + 1] = a1;
        __syncwarp();
        // Wo GEMV + residual + LN1
        ull o0 = 0ull, o1 = 0ull;
#pragma unroll
        for (int j2 = 0; j2 < 32; j2++) {
            ull av = *(const ull*)&s.ao[w][2 * j2];
            ull w0 = *(const ull*)&s.Wot[c0 * WSTR + 2 * j2];
            ull w1 = *(const ull*)&s.Wot[c1 * WSTR + 2 * j2];
            ffma2(o0, av, w0);
            ffma2(o1, av, w1);
        }
        float y0 = r50 + hsum2(o0) + s.bo[c0];
        float y1 = r51 + hsum2(o1) + s.bo[c1];
        float s1 = y0 + y1, s2 = y0 * y0 + y1 * y1;
#pragma unroll
        for (int off = 16; off > 0; off >>= 1) {
            s1 += __shfl_xor_sync(0xffffffffu, s1, off);
            s2 += __shfl_xor_sync(0xffffffffu, s2, off);
        }
        float m = s1 * (1.0f / HH);
        float var = s2 * (1.0f / HH) - m * m;
        float rstd = rsqrtf(var + 1e-5f);
        float hm0 = (y0 - m) * rstd * s.g1[c0] + s.b1[c0];
        float hm1 = (y1 - m) * rstd * s.g1[c1] + s.b1[c1];
        __syncwarp();
        s.hm[w][c0] = hm0; s.hm[w][c1] = hm1;
        __syncwarp();
        // FF1
        {
            ull f0 = 0ull, f1 = 0ull, f2 = 0ull, f3 = 0ull;
#pragma unroll
            for (int j2 = 0; j2 < 32; j2++) {
                ull hv = *(const ull*)&s.hm[w][2 * j2];
                ull w0 = *(const ull*)&s.W1t[(l)      * WSTR + 2 * j2];
                ull w1 = *(const ull*)&s.W1t[(l + 32) * WSTR + 2 * j2];
                ull w2 = *(const ull*)&s.W1t[(l + 64) * WSTR + 2 * j2];
                ull w3 = *(const ull*)&s.W1t[(l + 96) * WSTR + 2 * j2];
                ffma2(f0, hv, w0);
                ffma2(f1, hv, w1);
                ffma2(f2, hv, w2);
                ffma2(f3, hv, w3);
            }
            s.z1[w][l]      = fmaxf(hsum2(f0) + s.bb1[l], 0.f);
            s.z1[w][l + 32] = fmaxf(hsum2(f1) + s.bb1[l + 32], 0.f);
            s.z1[w][l + 64] = fmaxf(hsum2(f2) + s.bb1[l + 64], 0.f);
            s.z1[w][l + 96] = fmaxf(hsum2(f3) + s.bb1[l + 96], 0.f);
        }
        __syncwarp();
        // FF2 + residual + LN2
        ull g0 = 0ull, g1a = 0ull;
#pragma unroll
        for (int j2 = 0; j2 < 64; j2++) {
            ull zv = *(const ull*)&s.z1[w][2 * j2];
            ull w0 = *(const ull*)&s.W2t[c0 * 130 + 2 * j2];
            ull w1 = *(const ull*)&s.W2t[c1 * 130 + 2 * j2];
            ffma2(g0, zv, w0);
            ffma2(g1a, zv, w1);
        }
        float u0 = hm0 + hsum2(g0) + s.bb2[c0];
        float u1 = hm1 + hsum2(g1a) + s.bb2[c1];
        float t1 = u0 + u1, t2 = u0 * u0 + u1 * u1;
#pragma unroll
        for (int off = 16; off > 0; off >>= 1) {
            t1 += __shfl_xor_sync(0xffffffffu, t1, off);
            t2 += __shfl_xor_sync(0xffffffffu, t2, off);
        }
        float m2 = t1 * (1.0f / HH);
        float var2 = t2 * (1.0f / HH) - m2 * m2;
        float rstd2 = rsqrtf(var2 + 1e-5f);
        float hf0 = (u0 - m2) * rstd2 * s.g2[c0] + s.be2[c0];
        float hf1 = (u1 - m2) * rstd2 * s.g2[c1] + s.be2[c1];
        __syncwarp();
        // decoder precompute (share hf via z1 buffer)
        s.z1[w][c0] = hf0; s.z1[w][c1] = hf1;
        __syncwarp();
        ull pa0 = 0ull, pa1 = 0ull, pb0 = 0ull, pb1 = 0ull;
#pragma unroll
        for (int j2 = 0; j2 < 32; j2++) {
            ull v = *(const ull*)&s.z1[w][2 * j2];
            ull wa0 = *(const ull*)&s.Wat[c0 * WSTR + 2 * j2];
            ull wa1 = *(const ull*)&s.Wat[c1 * WSTR + 2 * j2];
            ull wb0 = *(const ull*)&s.Wbt[c0 * WSTR + 2 * j2];
            ull wb1 = *(const ull*)&s.Wbt[c1 * WSTR + 2 * j2];
            ffma2(pa0, v, wa0);
            ffma2(pa1, v, wa1);
            ffma2(pb0, v, wb0);
            ffma2(pb1, v, wb1);
        }
        g_pah[n * HH + c0] = __float2half(hsum2(pa0));
        g_pah[n * HH + c1] = __float2half(hsum2(pa1));
        g_pbh[n * HH + c0] = __float2half(hsum2(pb0) + s.b1d[c0]);
        g_pbh[n * HH + c1] = __float2half(hsum2(pb1) + s.b1d[c1]);
        __syncwarp();
    }
}

// ---------------- edge decoder (factorized, FFMA2 W2, fp16 pa/pb gathers) -----------
struct __align__(16) SDec3 {
    float z1[8][HH];      // offset 0 (8B-aligned) — required for LDS.64
    float2 W2p[32][32];
    float W1c[5 * HH];
    float W1d[4 * HH];
    float W3[32];
    float b2[32];
    float b3;
};

__global__ __launch_bounds__(256) void k_dec(
    const int* __restrict__ ei,
    const float* __restrict__ edge_attr, const float* __restrict__ edge_seq,
    const float* __restrict__ Wd1,
    const float* __restrict__ Wd2, const float* __restrict__ bd2,
    const float* __restrict__ Wd3, const float* __restrict__ bd3,
    float* __restrict__ out) {
    extern __shared__ char smem_raw[];
    SDec3& s = *reinterpret_cast<SDec3*>(smem_raw);
    int t = threadIdx.x, w = t >> 5, l = t & 31;
    for (int i = t; i < 5 * HH; i += 256) s.W1c[i] = Wd1[(2 * HH) * HH + i];
    for (int i = t; i < 4 * HH; i += 256) s.W1d[i] = Wd1[(2 * HH + 5) * HH + i];
    for (int i = t; i < 1024; i += 256) {
        int j = i >> 5, ll = i & 31;
        s.W2p[j][ll] = make_float2(Wd2[(2 * j) * 32 + ll], Wd2[(2 * j + 1) * 32 + ll]);
    }
    if (t < 32) { s.W3[t] = Wd3[t]; s.b2[t] = bd2[t]; }
    if (t == 0) s.b3 = bd3[0];
    __syncthreads();
    float* z1 = s.z1[w];
    int c = 2 * l;
    const __half2* pa2 = (const __half2*)g_pah;
    const __half2* pb2 = (const __half2*)g_pbh;
    for (int e = blockIdx.x * 8 + w; e < MM; e += gridDim.x * 8) {
        int src = ei[e], dst = ei[MM + e];
        float2 pav = __half22float2(pa2[src * 32 + l]);
        float2 pbv = __half22float2(pb2[dst * 32 + l]);
        float zx = pav.x + pbv.x, zy = pav.y + pbv.y;
#pragma unroll
        for (int j = 0; j < 5; j++) {
            float ev = __ldg(&edge_attr[e * 5 + j]);
            float2 wv = *(const float2*)&s.W1c[j * HH + c];
            zx += ev * wv.x; zy += ev * wv.y;
        }
#pragma unroll
        for (int j = 0; j < 4; j++) {
            float ev = __ldg(&edge_seq[e * (KK * 4) + (KK - 1) * 4 + j]);
            float2 wv = *(const float2*)&s.W1d[j * HH + c];
            zx += ev * wv.x; zy += ev * wv.y;
        }
        z1[c] = fmaxf(zx, 0.f);
        z1[c + 1] = fmaxf(zy, 0.f);
        __syncwarp();
        ull acc = pack2(s.b2[l], 0.f);
#pragma unroll
        for (int j = 0; j < 32; j++) {
            ull z2 = *(const ull*)&z1[2 * j];
            ull w2 = *(const ull*)&s.W2p[j][l];
            ffma2(acc, z2, w2);
        }
        float2 av = unpack2(acc);
        float a2 = fmaxf(av.x + av.y, 0.f);
        float p = a2 * s.W3[l];
#pragma unroll
        for (int off = 16; off > 0; off >>= 1) p += __shfl_down_sync(0xffffffffu, p, off);
        if (l == 0) out[e] = p + s.b3;
        __syncwarp();
    }
}

// ---------------- launch ----------------
extern "C" void kernel_launch(void* const* d_in, const int* in_sizes, int n_in,
                              void* d_out, int out_size) {
    const float* x        = (const float*)d_in[0];
    const int*   ei       = (const int*)  d_in[1];
    const float* eattr    = (const float*)d_in[2];
    const float* u        = (const float*)d_in[3];
    const float* eseq     = (const float*)d_in[4];
    const float* useq     = (const float*)d_in[5];
    const float* W_proj   = (const float*)d_in[6];
    const float* b_proj   = (const float*)d_in[7];
    const float* W_gcn    = (const float*)d_in[8];
    const float* b_gcn    = (const float*)d_in[9];
    const float* Wq       = (const float*)d_in[10];
    const float* bq       = (const float*)d_in[11];
    const float* Wk       = (const float*)d_in[12];
    const float* bk       = (const float*)d_in[13];
    const float* Wv       = (const float*)d_in[14];
    const float* bv       = (const float*)d_in[15];
    const float* Wo       = (const float*)d_in[16];
    const float* bo       = (const float*)d_in[17];
    const float* ln1g     = (const float*)d_in[18];
    const float* ln1b     = (const float*)d_in[19];
    const float* W_ff1    = (const float*)d_in[20];
    const float* b_ff1    = (const float*)d_in[21];
    const float* W_ff2    = (const float*)d_in[22];
    const float* b_ff2    = (const float*)d_in[23];
    const float* ln2g     = (const float*)d_in[24];
    const float* ln2b     = (const float*)d_in[25];
    const float* Wd1      = (const float*)d_in[26];
    const float* bd1      = (const float*)d_in[27];
    const float* Wd2      = (const float*)d_in[28];
    const float* bd2      = (const float*)d_in[29];
    const float* Wd3      = (const float*)d_in[30];
    const float* bd3      = (const float*)d_in[31];
    float* out = (float*)d_out;

    cudaFuncSetAttribute(k_gcnqkv, cudaFuncAttributeMaxDynamicSharedMemorySize, (int)sizeof(SG));
    cudaFuncSetAttribute(k_attnff, cudaFuncAttributeMaxDynamicSharedMemorySize, (int)sizeof(SAF));
    cudaFuncSetAttribute(k_dec,    cudaFuncAttributeMaxDynamicSharedMemorySize, (int)sizeof(SDec3));

    k_zero_counts<<<(NN + 255) / 256, 256>>>();
    k_count<<<(MM + 255) / 256, 256>>>(ei);
    k_blockscan<<<NBLK, 1024>>>();
    k_scan2<<<1, 128>>>();
    k_apply<<<(NN + 255) / 256, 256>>>();
    k_fill<<<(MM + 255) / 256, 256>>>(ei);
    k_projck<<<NN / 4, 256>>>(x, W_proj, b_proj, u, useq);
    k_gcnqkv<<<1184, 384, sizeof(SG)>>>(W_gcn, b_gcn, Wk, bk, Wv, bv);
    k_attnff<<<592, 384, sizeof(SAF)>>>(Wq, bq, Wo, bo, ln1g, ln1b, W_ff1, b_ff1,
                                        W_ff2, b_ff2, ln2g, ln2b, Wd1, bd1);
    k_dec<<<2048, 256, sizeof(SDec3)>>>(ei, eattr, eseq, Wd1, Wd2, bd2, Wd3, bd3, out);
}

// round 14
// speedup vs baseline: 1.8243x; 1.0868x over previous
#include <cuda_runtime.h>
#include <cuda_fp16.h>
#include <math.h>

#define NN 100000
#define MM 800000
#define KK 6
#define HH 64
#define NHD 4
#define DHD 16
#define NBLK 98   // ceil(NN/1024)
#define WSTR 66   // padded transposed-weight row stride (floats)

typedef unsigned long long ull;

// ---------------- packed f32x2 helpers (sm_103a FFMA2 path) ----------------
__device__ __forceinline__ ull pack2(float lo, float hi) {
    ull r;
    asm("mov.b64 %0, {%1, %2};" : "=l"(r) : "f"(lo), "f"(hi));
    return r;
}
__device__ __forceinline__ void ffma2(ull& d, ull a, ull b) {
    asm("fma.rn.f32x2 %0, %1, %2, %0;" : "+l"(d) : "l"(a), "l"(b));
}
__device__ __forceinline__ float2 unpack2(ull v) {
    float lo, hi;
    asm("mov.b64 {%0, %1}, %2;" : "=f"(lo), "=f"(hi) : "l"(v));
    return make_float2(lo, hi);
}
__device__ __forceinline__ float hsum2(ull v) {
    float2 p = unpack2(v);
    return p.x + p.y;
}
// streaming 16-bit store (evict-first: kv is write-once/read-once)
__device__ __forceinline__ void sth_cs(__half* p, float v) {
    unsigned short u = __half_as_ushort(__float2half(v));
    asm volatile("st.global.cs.u16 [%0], %1;" :: "l"(p), "h"(u) : "memory");
}

// ---------------- scratch (device globals; allocation-free) ----------------
__device__ __half g_hh[NN * KK * HH];     // hs = tanh(proj)*dinv, fp16 (76.8 MB)
__device__ __half g_kvh[NN * KK * 128];   // per (n,k): [k(64)|v(64)] fp16 (153.6 MB)
__device__ float g_h2r5[NN * HH];         // post-GCN relu, row k=5 (residual + q input)
__device__ __half g_pah[NN * HH];         // h_final @ Wd1[0:64], fp16 (12.8 MB)
__device__ __half g_pbh[NN * HH];         // h_final @ Wd1[64:128] + b1, fp16
__device__ float g_dinv[NN];
__device__ int   g_counts[NN];
__device__ int   g_scan[NN];
__device__ int   g_blocksum[128];
__device__ int   g_blockoff[128];
__device__ int   g_rowstart[NN + 1];
__device__ int   g_cursor[NN];
__device__ int   g_srclist[MM];

// ---------------- small utility kernels ----------------
__global__ void k_zero_counts() {
    int i = blockIdx.x * blockDim.x + threadIdx.x;
    if (i < NN) g_counts[i] = 0;
}

__global__ void k_count(const int* __restrict__ ei) {
    int e = blockIdx.x * blockDim.x + threadIdx.x;
    if (e < MM) atomicAdd(&g_counts[ei[MM + e]], 1);
}

// ---------------- coalesced 3-phase scan (measured 5us total) ----------------
__global__ __launch_bounds__(1024) void k_blockscan() {
    __shared__ int warpsums[32];
    int t = threadIdx.x, lane = t & 31, w = t >> 5;
    int i = blockIdx.x * 1024 + t;
    int v0 = (i < NN) ? g_counts[i] : 0;
    if (i < NN) g_dinv[i] = rsqrtf((float)v0 + 1.0f);
    int v = v0;
#pragma unroll
    for (int off = 1; off < 32; off <<= 1) {
        int x = __shfl_up_sync(0xffffffffu, v, off);
        if (lane >= off) v += x;
    }
    if (lane == 31) warpsums[w] = v;
    __syncthreads();
    if (w == 0) {
        int s = warpsums[lane];
#pragma unroll
        for (int off = 1; off < 32; off <<= 1) {
            int x = __shfl_up_sync(0xffffffffu, s, off);
            if (lane >= off) s += x;
        }
        warpsums[lane] = s;
    }
    __syncthreads();
    int incl = v + (w > 0 ? warpsums[w - 1] : 0);
    if (i < NN) g_scan[i] = incl;
    if (t == 1023) g_blocksum[blockIdx.x] = incl;
}

__global__ void k_scan2() {
    __shared__ int warpsums[4];
    int t = threadIdx.x, lane = t & 31, w = t >> 5;
    int v0 = (t < NBLK) ? g_blocksum[t] : 0;
    int v = v0;
#pragma unroll
    for (int off = 1; off < 32; off <<= 1) {
        int x = __shfl_up_sync(0xffffffffu, v, off);
        if (lane >= off) v += x;
    }
    if (lane == 31) warpsums[w] = v;
    __syncthreads();
    int base = 0;
    for (int j = 0; j < w; j++) base += warpsums[j];
    int incl = v + base;
    if (t < NBLK) g_blockoff[t] = incl - v0;
    if (t == NBLK - 1) g_rowstart[NN] = incl;
}

__global__ void k_apply() {
    int i = blockIdx.x * blockDim.x + threadIdx.x;
    if (i < NN) {
        int excl = g_scan[i] - g_counts[i] + g_blockoff[i >> 10];
        g_rowstart[i] = excl;
        g_cursor[i]   = excl;
    }
}

__global__ void k_fill(const int* __restrict__ ei) {
    int e = blockIdx.x * blockDim.x + threadIdx.x;
    if (e < MM) {
        int d = ei[MM + e];
        int p = atomicAdd(&g_cursor[d], 1);
        g_srclist[p] = ei[e];
    }
}

// ---------------- projection (+ inline ck): hs = tanh(dot12 + ck)*dinv, fp16 --------
__global__ __launch_bounds__(256) void k_projck(
    const float* __restrict__ x, const float* __restrict__ W_proj,
    const float* __restrict__ b_proj, const float* __restrict__ u,
    const float* __restrict__ u_seq) {
    __shared__ float Wp12[12 * HH];
    __shared__ float cks[KK * HH];
    int t = threadIdx.x;
    for (int i = t; i < 12 * HH; i += 256) Wp12[i] = W_proj[i];
    if (t < HH) {
        int c = t;
        float base = b_proj[c];
#pragma unroll
        for (int j = 0; j < 11; j++) base += u[j] * W_proj[(12 + j) * HH + c];
#pragma unroll
        for (int k = 0; k < KK; k++) {
            float val = base;
#pragma unroll
            for (int j = 0; j < 5; j++) val += u_seq[k * 5 + j] * W_proj[(23 + j) * HH + c];
            cks[k * HH + c] = val;
        }
    }
    __syncthreads();
    int g = t >> 6, c = t & 63;
    int n = blockIdx.x * 4 + g;
    float dn = g_dinv[n];
    float s = 0.f;
#pragma unroll
    for (int j = 0; j < 12; j++) s += __ldg(&x[n * 12 + j]) * Wp12[j * HH + c];
    int base = n * (KK * HH) + c;
#pragma unroll
    for (int k = 0; k < KK; k++)
        g_hh[base + k * HH] = __float2half(tanhf(s + cks[k * HH + c]) * dn);
}

// ---------------- fused AGGREGATE + GCN + KV (warp per node) ----------------
struct __align__(16) SG {
    float Wgt[HH * WSTR];       // Wgt[c*66+j] = W_gcn[j][c]
    float Wkvt[128 * WSTR];     // Wkvt[c*66+j] = [Wk|Wv][j][c]
    float arow[12][KK][HH];
    float h2s[12][KK][HH];
    float bg[HH], bkv[128];
};

__global__ __launch_bounds__(384) void k_gcnqkv(
    const float* __restrict__ W_gcn, const float* __restrict__ b_gcn,
    const float* __restrict__ Wk, const float* __restrict__ bk,
    const float* __restrict__ Wv, const float* __restrict__ bv) {
    extern __shared__ char smem_raw[];
    SG& s = *reinterpret_cast<SG*>(smem_raw);
    int t = threadIdx.x, w = t >> 5, l = t & 31;
    for (int i = t; i < HH * HH; i += 384) {
        int j = i >> 6, c = i & 63;
        s.Wgt[c * WSTR + j] = W_gcn[i];
        s.Wkvt[c * WSTR + j] = Wk[i];
        s.Wkvt[(c + 64) * WSTR + j] = Wv[i];
    }
    if (t < HH) { s.bg[t] = b_gcn[t]; s.bkv[t] = bk[t]; s.bkv[64 + t] = bv[t]; }
    __syncthreads();
    const int c0 = l, c1 = l + 32;
    const __half2* hh2 = (const __half2*)g_hh;
    for (int n = blockIdx.x * 12 + w; n < NN; n += gridDim.x * 12) {
        // stage 0: aggregate (4-way unrolled gather)
        {
            float dn = g_dinv[n];
            int s0 = g_rowstart[n], s1 = g_rowstart[n + 1];
            float2 acc[KK];
#pragma unroll
            for (int r = 0; r < KK; r++)
                acc[r] = __half22float2(hh2[(n * KK + r) * 32 + l]);
            int i = s0;
            for (; i + 3 < s1; i += 4) {
                const __half2* pa = hh2 + g_srclist[i]     * (KK * 32) + l;
                const __half2* pb = hh2 + g_srclist[i + 1] * (KK * 32) + l;
                const __half2* pc = hh2 + g_srclist[i + 2] * (KK * 32) + l;
                const __half2* pd = hh2 + g_srclist[i + 3] * (KK * 32) + l;
#pragma unroll
                for (int r = 0; r < KK; r++) {
                    float2 va = __half22float2(pa[r * 32]);
                    float2 vb = __half22float2(pb[r * 32]);
                    float2 vc = __half22float2(pc[r * 32]);
                    float2 vd = __half22float2(pd[r * 32]);
                    acc[r].x += (va.x + vb.x) + (vc.x + vd.x);
                    acc[r].y += (va.y + vb.y) + (vc.y + vd.y);
                }
            }
            for (; i < s1; i++) {
                const __half2* pa = hh2 + g_srclist[i] * (KK * 32) + l;
#pragma unroll
                for (int r = 0; r < KK; r++) {
                    float2 va = __half22float2(pa[r * 32]);
                    acc[r].x += va.x;
                    acc[r].y += va.y;
                }
            }
#pragma unroll
            for (int r = 0; r < KK; r++) {
                s.arow[w][r][2 * l]     = acc[r].x * dn;
                s.arow[w][r][2 * l + 1] = acc[r].y * dn;
            }
        }
        __syncwarp();
        // stage 1: h2 = relu(agg @ Wg + bg)
        {
            ull acc[KK][2];
#pragma unroll
            for (int r = 0; r < KK; r++) { acc[r][0] = 0ull; acc[r][1] = 0ull; }
#pragma unroll
            for (int j2 = 0; j2 < 32; j2++) {
                ull w0 = *(const ull*)&s.Wgt[c0 * WSTR + 2 * j2];
                ull w1 = *(const ull*)&s.Wgt[c1 * WSTR + 2 * j2];
#pragma unroll
                for (int r = 0; r < KK; r++) {
                    ull av = *(const ull*)&s.arow[w][r][2 * j2];
                    ffma2(acc[r][0], av, w0);
                    ffma2(acc[r][1], av, w1);
                }
            }
#pragma unroll
            for (int r = 0; r < KK; r++) {
                float h0 = fmaxf(hsum2(acc[r][0]) + s.bg[c0], 0.f);
                float h1 = fmaxf(hsum2(acc[r][1]) + s.bg[c1], 0.f);
                s.h2s[w][r][c0] = h0;
                s.h2s[w][r][c1] = h1;
                if (r == KK - 1) {
                    g_h2r5[n * HH + c0] = h0;
                    g_h2r5[n * HH + c1] = h1;
                }
            }
        }
        __syncwarp();
        // stage 2: kv = h2 @ [Wk|Wv] + b -> fp16 global, direct coalesced half stores
        {
            ull acc[KK][4];
#pragma unroll
            for (int r = 0; r < KK; r++)
#pragma unroll
                for (int q = 0; q < 4; q++) acc[r][q] = 0ull;
#pragma unroll
            for (int j2 = 0; j2 < 32; j2++) {
                ull w0 = *(const ull*)&s.Wkvt[(l)      * WSTR + 2 * j2];
                ull w1 = *(const ull*)&s.Wkvt[(l + 32) * WSTR + 2 * j2];
                ull w2 = *(const ull*)&s.Wkvt[(l + 64) * WSTR + 2 * j2];
                ull w3 = *(const ull*)&s.Wkvt[(l + 96) * WSTR + 2 * j2];
#pragma unroll
                for (int r = 0; r < KK; r++) {
                    ull hv = *(const ull*)&s.h2s[w][r][2 * j2];
                    ffma2(acc[r][0], hv, w0);
                    ffma2(acc[r][1], hv, w1);
                    ffma2(acc[r][2], hv, w2);
                    ffma2(acc[r][3], hv, w3);
                }
            }
#pragma unroll
            for (int r = 0; r < KK; r++) {
                __half* kvp = &g_kvh[(n * KK + r) * 128];
                sth_cs(kvp + l,      hsum2(acc[r][0]) + s.bkv[l]);
                sth_cs(kvp + l + 32, hsum2(acc[r][1]) + s.bkv[l + 32]);
                sth_cs(kvp + l + 64, hsum2(acc[r][2]) + s.bkv[l + 64]);
                sth_cs(kvp + l + 96, hsum2(acc[r][3]) + s.bkv[l + 96]);
            }
        }
    }
}

// ---- fused Q + attention + LN1 + FF + LN2 + decoder-precompute (warp per node) ----
struct __align__(16) SAF {
    float Wqt[HH * WSTR];
    float Wot[HH * WSTR];
    float W1t[128 * WSTR];
    float W2t[HH * 130];
    float Wat[HH * WSTR];
    float Wbt[HH * WSTR];
    float kv[12][KK * 128];
    float qv[12][HH];
    float ao[12][HH];
    float hm[12][HH];
    float z1[12][2 * HH];
    float aw[12][NHD * KK];
    float bq[HH], bo[HH], g1[HH], b1[HH], bb2[HH], g2[HH], be2[HH], b1d[HH];
    float bb1[2 * HH];
};

__global__ __launch_bounds__(384) void k_attnff(
    const float* __restrict__ Wq, const float* __restrict__ bq,
    const float* __restrict__ Wo, const float* __restrict__ bo,
    const float* __restrict__ ln1g, const float* __restrict__ ln1b,
    const float* __restrict__ W_ff1, const float* __restrict__ b_ff1,
    const float* __restrict__ W_ff2, const float* __restrict__ b_ff2,
    const float* __restrict__ ln2g, const float* __restrict__ ln2b,
    const float* __restrict__ Wd1, const float* __restrict__ bd1) {
    extern __shared__ char smem_raw[];
    SAF& s = *reinterpret_cast<SAF*>(smem_raw);
    int t = threadIdx.x, w = t >> 5, l = t & 31;
    for (int i = t; i < HH * HH; i += 384) {
        int j = i >> 6, c = i & 63;
        s.Wqt[c * WSTR + j] = Wq[i];
        s.Wot[c * WSTR + j] = Wo[i];
        s.Wat[c * WSTR + j] = Wd1[i];
        s.Wbt[c * WSTR + j] = Wd1[HH * HH + i];
    }
    for (int i = t; i < HH * 128; i += 384) {
        int j = i >> 7, c = i & 127;
        s.W1t[c * WSTR + j] = W_ff1[i];
    }
    for (int i = t; i < 128 * HH; i += 384) {
        int j = i >> 6, c = i & 63;
        s.W2t[c * 130 + j] = W_ff2[i];
    }
    if (t < HH) {
        s.bq[t] = bq[t]; s.bo[t] = bo[t]; s.g1[t] = ln1g[t]; s.b1[t] = ln1b[t];
        s.bb2[t] = b_ff2[t]; s.g2[t] = ln2g[t]; s.be2[t] = ln2b[t];
        s.b1d[t] = bd1[t];
    }
    if (t < 2 * HH) s.bb1[t] = b_ff1[t];
    __syncthreads();
    const int c0 = l, c1 = l + 32;
    int c2 = 2 * l, c4 = 4 * l;
    for (int n = blockIdx.x * 12 + w; n < NN; n += gridDim.x * 12) {
        // load h2row5 (residual + q input) and kv (fp16 streaming -> fp32 smem)
        float r50 = g_h2r5[n * HH + c0];
        float r51 = g_h2r5[n * HH + c1];
        s.hm[w][c0] = r50; s.hm[w][c1] = r51;
#pragma unroll
        for (int r = 0; r < KK; r++) {
            ull raw = __ldcs((const ull*)&g_kvh[(n * KK + r) * 128 + c4]);
            __half2 h0 = *(__half2*)&raw;
            __half2 h1 = *((__half2*)&raw + 1);
            float2 f0 = __half22float2(h0), f1 = __half22float2(h1);
            *(float4*)&s.kv[w][r * 128 + c4] = make_float4(f0.x, f0.y, f1.x, f1.y);
        }
        __syncwarp();
        // q = h2row5 @ Wq + bq
        {
            ull q0 = 0ull, q1 = 0ull;
#pragma unroll
            for (int j2 = 0; j2 < 32; j2++) {
                ull hv = *(const ull*)&s.hm[w][2 * j2];
                ull w0 = *(const ull*)&s.Wqt[c0 * WSTR + 2 * j2];
                ull w1 = *(const ull*)&s.Wqt[c1 * WSTR + 2 * j2];
                ffma2(q0, hv, w0);
                ffma2(q1, hv, w1);
            }
            s.qv[w][c0] = hsum2(q0) + s.bq[c0];
            s.qv[w][c1] = hsum2(q1) + s.bq[c1];
        }
        __syncwarp();
        // scores
        float sc = 0.f;
        int hh = l / KK, kk = l - hh * KK;
        if (l < NHD * KK) {
#pragma unroll
            for (int d = 0; d < DHD; d++)
                sc += s.qv[w][hh * DHD + d] * s.kv[w][kk * 128 + hh * DHD + d];
            sc *= 0.25f;
        }
        float mysc[KK];
#pragma unroll
        for (int j = 0; j < KK; j++)
            mysc[j] = __shfl_sync(0xffffffffu, sc, (l & 3) * KK + j);
        if (l < NHD) {
            float mx = mysc[0];
#pragma unroll
            for (int j = 1; j < KK; j++) mx = fmaxf(mx, mysc[j]);
            float sum = 0.f;
#pragma unroll
            for (int j = 0; j < KK; j++) { mysc[j] = expf(mysc[j] - mx); sum += mysc[j]; }
            float inv = 1.0f / sum;
#pragma unroll
            for (int j = 0; j < KK; j++) s.aw[w][l * KK + j] = mysc[j] * inv;
        }
        __syncwarp();
        // AV
        int hd = l >> 3;
        float a0 = 0.f, a1 = 0.f;
#pragma unroll
        for (int j = 0; j < KK; j++) {
            float wgt = s.aw[w][hd * KK + j];
            float2 vv = *(const float2*)&s.kv[w][j * 128 + 64 + c2];
            a0 += wgt * vv.x; a1 += wgt * vv.y;
        }
        s.ao[w][c2] = a0; s.ao[w][c2 + 1] = a1;
        __syncwarp();
        // Wo GEMV + residual + LN1
        ull o0 = 0ull, o1 = 0ull;
#pragma unroll
        for (int j2 = 0; j2 < 32; j2++) {
            ull av = *(const ull*)&s.ao[w][2 * j2];
            ull w0 = *(const ull*)&s.Wot[c0 * WSTR + 2 * j2];
            ull w1 = *(const ull*)&s.Wot[c1 * WSTR + 2 * j2];
            ffma2(o0, av, w0);
            ffma2(o1, av, w1);
        }
        float y0 = r50 + hsum2(o0) + s.bo[c0];
        float y1 = r51 + hsum2(o1) + s.bo[c1];
        float s1 = y0 + y1, s2 = y0 * y0 + y1 * y1;
#pragma unroll
        for (int off = 16; off > 0; off >>= 1) {
            s1 += __shfl_xor_sync(0xffffffffu, s1, off);
            s2 += __shfl_xor_sync(0xffffffffu, s2, off);
        }
        float m = s1 * (1.0f / HH);
        float var = s2 * (1.0f / HH) - m * m;
        float rstd = rsqrtf(var + 1e-5f);
        float hm0 = (y0 - m) * rstd * s.g1[c0] + s.b1[c0];
        float hm1 = (y1 - m) * rstd * s.g1[c1] + s.b1[c1];
        __syncwarp();
        s.hm[w][c0] = hm0; s.hm[w][c1] = hm1;
        __syncwarp();
        // FF1
        {
            ull f0 = 0ull, f1 = 0ull, f2 = 0ull, f3 = 0ull;
#pragma unroll
            for (int j2 = 0; j2 < 32; j2++) {
                ull hv = *(const ull*)&s.hm[w][2 * j2];
                ull w0 = *(const ull*)&s.W1t[(l)      * WSTR + 2 * j2];
                ull w1 = *(const ull*)&s.W1t[(l + 32) * WSTR + 2 * j2];
                ull w2 = *(const ull*)&s.W1t[(l + 64) * WSTR + 2 * j2];
                ull w3 = *(const ull*)&s.W1t[(l + 96) * WSTR + 2 * j2];
                ffma2(f0, hv, w0);
                ffma2(f1, hv, w1);
                ffma2(f2, hv, w2);
                ffma2(f3, hv, w3);
            }
            s.z1[w][l]      = fmaxf(hsum2(f0) + s.bb1[l], 0.f);
            s.z1[w][l + 32] = fmaxf(hsum2(f1) + s.bb1[l + 32], 0.f);
            s.z1[w][l + 64] = fmaxf(hsum2(f2) + s.bb1[l + 64], 0.f);
            s.z1[w][l + 96] = fmaxf(hsum2(f3) + s.bb1[l + 96], 0.f);
        }
        __syncwarp();
        // FF2 + residual + LN2
        ull g0 = 0ull, g1a = 0ull;
#pragma unroll
        for (int j2 = 0; j2 < 64; j2++) {
            ull zv = *(const ull*)&s.z1[w][2 * j2];
            ull w0 = *(const ull*)&s.W2t[c0 * 130 + 2 * j2];
            ull w1 = *(const ull*)&s.W2t[c1 * 130 + 2 * j2];
            ffma2(g0, zv, w0);
            ffma2(g1a, zv, w1);
        }
        float u0 = hm0 + hsum2(g0) + s.bb2[c0];
        float u1 = hm1 + hsum2(g1a) + s.bb2[c1];
        float t1 = u0 + u1, t2 = u0 * u0 + u1 * u1;
#pragma unroll
        for (int off = 16; off > 0; off >>= 1) {
            t1 += __shfl_xor_sync(0xffffffffu, t1, off);
            t2 += __shfl_xor_sync(0xffffffffu, t2, off);
        }
        float m2 = t1 * (1.0f / HH);
        float var2 = t2 * (1.0f / HH) - m2 * m2;
        float rstd2 = rsqrtf(var2 + 1e-5f);
        float hf0 = (u0 - m2) * rstd2 * s.g2[c0] + s.be2[c0];
        float hf1 = (u1 - m2) * rstd2 * s.g2[c1] + s.be2[c1];
        __syncwarp();
        // decoder precompute (share hf via z1 buffer)
        s.z1[w][c0] = hf0; s.z1[w][c1] = hf1;
        __syncwarp();
        ull pa0 = 0ull, pa1 = 0ull, pb0 = 0ull, pb1 = 0ull;
#pragma unroll
        for (int j2 = 0; j2 < 32; j2++) {
            ull v = *(const ull*)&s.z1[w][2 * j2];
            ull wa0 = *(const ull*)&s.Wat[c0 * WSTR + 2 * j2];
            ull wa1 = *(const ull*)&s.Wat[c1 * WSTR + 2 * j2];
            ull wb0 = *(const ull*)&s.Wbt[c0 * WSTR + 2 * j2];
            ull wb1 = *(const ull*)&s.Wbt[c1 * WSTR + 2 * j2];
            ffma2(pa0, v, wa0);
            ffma2(pa1, v, wa1);
            ffma2(pb0, v, wb0);
            ffma2(pb1, v, wb1);
        }
        g_pah[n * HH + c0] = __float2half(hsum2(pa0));
        g_pah[n * HH + c1] = __float2half(hsum2(pa1));
        g_pbh[n * HH + c0] = __float2half(hsum2(pb0) + s.b1d[c0]);
        g_pbh[n * HH + c1] = __float2half(hsum2(pb1) + s.b1d[c1]);
        __syncwarp();
    }
}

// ------- edge decoder (factorized, FFMA2 W2, fp16 gathers, 2 edges per iteration) ----
struct __align__(16) SDec4 {
    float z1[8][2][HH];   // offset 0 (8B-aligned) — required for LDS.64
    float2 W2p[32][32];
    float W1c[5 * HH];
    float W1d[4 * HH];
    float W3[32];
    float b2[32];
    float b3;
};

__global__ __launch_bounds__(256) void k_dec(
    const int* __restrict__ ei,
    const float* __restrict__ edge_attr, const float* __restrict__ edge_seq,
    const float* __restrict__ Wd1,
    const float* __restrict__ Wd2, const float* __restrict__ bd2,
    const float* __restrict__ Wd3, const float* __restrict__ bd3,
    float* __restrict__ out) {
    extern __shared__ char smem_raw[];
    SDec4& s = *reinterpret_cast<SDec4*>(smem_raw);
    int t = threadIdx.x, w = t >> 5, l = t & 31;
    for (int i = t; i < 5 * HH; i += 256) s.W1c[i] = Wd1[(2 * HH) * HH + i];
    for (int i = t; i < 4 * HH; i += 256) s.W1d[i] = Wd1[(2 * HH + 5) * HH + i];
    for (int i = t; i < 1024; i += 256) {
        int j = i >> 5, ll = i & 31;
        s.W2p[j][ll] = make_float2(Wd2[(2 * j) * 32 + ll], Wd2[(2 * j + 1) * 32 + ll]);
    }
    if (t < 32) { s.W3[t] = Wd3[t]; s.b2[t] = bd2[t]; }
    if (t == 0) s.b3 = bd3[0];
    __syncthreads();
    float* z0 = s.z1[w][0];
    float* z1 = s.z1[w][1];
    int c = 2 * l;
    const __half2* pa2 = (const __half2*)g_pah;
    const __half2* pb2 = (const __half2*)g_pbh;
    const int NP = MM / 2;   // 400000 edge pairs
    for (int p = blockIdx.x * 8 + w; p < NP; p += gridDim.x * 8) {
        int e0 = 2 * p, e1 = 2 * p + 1;
        int src0 = ei[e0], dst0 = ei[MM + e0];
        int src1 = ei[e1], dst1 = ei[MM + e1];
        // 4 independent random gathers in flight
        float2 pav0 = __half22float2(pa2[src0 * 32 + l]);
        float2 pbv0 = __half22float2(pb2[dst0 * 32 + l]);
        float2 pav1 = __half22float2(pa2[src1 * 32 + l]);
        float2 pbv1 = __half22float2(pb2[dst1 * 32 + l]);
        float zx0 = pav0.x + pbv0.x, zy0 = pav0.y + pbv0.y;
        float zx1 = pav1.x + pbv1.x, zy1 = pav1.y + pbv1.y;
#pragma unroll
        for (int j = 0; j < 5; j++) {
            float ev0 = __ldg(&edge_attr[e0 * 5 + j]);
            float ev1 = __ldg(&edge_attr[e1 * 5 + j]);
            float2 wv = *(const float2*)&s.W1c[j * HH + c];
            zx0 += ev0 * wv.x; zy0 += ev0 * wv.y;
            zx1 += ev1 * wv.x; zy1 += ev1 * wv.y;
        }
#pragma unroll
        for (int j = 0; j < 4; j++) {
            float ev0 = __ldg(&edge_seq[e0 * (KK * 4) + (KK - 1) * 4 + j]);
            float ev1 = __ldg(&edge_seq[e1 * (KK * 4) + (KK - 1) * 4 + j]);
            float2 wv = *(const float2*)&s.W1d[j * HH + c];
            zx0 += ev0 * wv.x; zy0 += ev0 * wv.y;
            zx1 += ev1 * wv.x; zy1 += ev1 * wv.y;
        }
        z0[c] = fmaxf(zx0, 0.f); z0[c + 1] = fmaxf(zy0, 0.f);
        z1[c] = fmaxf(zx1, 0.f); z1[c + 1] = fmaxf(zy1, 0.f);
        __syncwarp();
        // W2 GEMV: one weight load serves both edges; 2 independent chains
        ull acc0 = pack2(s.b2[l], 0.f);
        ull acc1 = pack2(s.b2[l], 0.f);
#pragma unroll
        for (int j = 0; j < 32; j++) {
            ull w2 = *(const ull*)&s.W2p[j][l];
            ull za = *(const ull*)&z0[2 * j];
            ull zb = *(const ull*)&z1[2 * j];
            ffma2(acc0, za, w2);
            ffma2(acc1, zb, w2);
        }
        float2 av0 = unpack2(acc0);
        float2 av1 = unpack2(acc1);
        float a20 = fmaxf(av0.x + av0.y, 0.f);
        float a21 = fmaxf(av1.x + av1.y, 0.f);
        float p0 = a20 * s.W3[l];
        float p1 = a21 * s.W3[l];
#pragma unroll
        for (int off = 16; off > 0; off >>= 1) {
            p0 += __shfl_down_sync(0xffffffffu, p0, off);
            p1 += __shfl_down_sync(0xffffffffu, p1, off);
        }
        if (l == 0) { out[e0] = p0 + s.b3; out[e1] = p1 + s.b3; }
        __syncwarp();
    }
}

// ---------------- launch ----------------
extern "C" void kernel_launch(void* const* d_in, const int* in_sizes, int n_in,
                              void* d_out, int out_size) {
    const float* x        = (const float*)d_in[0];
    const int*   ei       = (const int*)  d_in[1];
    const float* eattr    = (const float*)d_in[2];
    const float* u        = (const float*)d_in[3];
    const float* eseq     = (const float*)d_in[4];
    const float* useq     = (const float*)d_in[5];
    const float* W_proj   = (const float*)d_in[6];
    const float* b_proj   = (const float*)d_in[7];
    const float* W_gcn    = (const float*)d_in[8];
    const float* b_gcn    = (const float*)d_in[9];
    const float* Wq       = (const float*)d_in[10];
    const float* bq       = (const float*)d_in[11];
    const float* Wk       = (const float*)d_in[12];
    const float* bk       = (const float*)d_in[13];
    const float* Wv       = (const float*)d_in[14];
    const float* bv       = (const float*)d_in[15];
    const float* Wo       = (const float*)d_in[16];
    const float* bo       = (const float*)d_in[17];
    const float* ln1g     = (const float*)d_in[18];
    const float* ln1b     = (const float*)d_in[19];
    const float* W_ff1    = (const float*)d_in[20];
    const float* b_ff1    = (const float*)d_in[21];
    const float* W_ff2    = (const float*)d_in[22];
    const float* b_ff2    = (const float*)d_in[23];
    const float* ln2g     = (const float*)d_in[24];
    const float* ln2b     = (const float*)d_in[25];
    const float* Wd1      = (const float*)d_in[26];
    const float* bd1      = (const float*)d_in[27];
    const float* Wd2      = (const float*)d_in[28];
    const float* bd2      = (const float*)d_in[29];
    const float* Wd3      = (const float*)d_in[30];
    const float* bd3      = (const float*)d_in[31];
    float* out = (float*)d_out;

    cudaFuncSetAttribute(k_gcnqkv, cudaFuncAttributeMaxDynamicSharedMemorySize, (int)sizeof(SG));
    cudaFuncSetAttribute(k_attnff, cudaFuncAttributeMaxDynamicSharedMemorySize, (int)sizeof(SAF));
    cudaFuncSetAttribute(k_dec,    cudaFuncAttributeMaxDynamicSharedMemorySize, (int)sizeof(SDec4));

    k_zero_counts<<<(NN + 255) / 256, 256>>>();
    k_count<<<(MM + 255) / 256, 256>>>(ei);
    k_blockscan<<<NBLK, 1024>>>();
    k_scan2<<<1, 128>>>();
    k_apply<<<(NN + 255) / 256, 256>>>();
    k_fill<<<(MM + 255) / 256, 256>>>(ei);
    k_projck<<<NN / 4, 256>>>(x, W_proj, b_proj, u, useq);
    k_gcnqkv<<<1184, 384, sizeof(SG)>>>(W_gcn, b_gcn, Wk, bk, Wv, bv);
    k_attnff<<<592, 384, sizeof(SAF)>>>(Wq, bq, Wo, bo, ln1g, ln1b, W_ff1, b_ff1,
                                        W_ff2, b_ff2, ln2g, ln2b, Wd1, bd1);
    k_dec<<<2048, 256, sizeof(SDec4)>>>(ei, eattr, eseq, Wd1, Wd2, bd2, Wd3, bd3, out);
}

// round 15
// speedup vs baseline: 1.9041x; 1.0437x over previous
#include <cuda_runtime.h>
#include <cuda_fp16.h>
#include <math.h>

#define NN 100000
#define MM 800000
#define KK 6
#define HH 64
#define NHD 4
#define DHD 16
#define NBLK 98   // ceil(NN/1024)
#define WSTR 66   // padded transposed-weight row stride (floats)

typedef unsigned long long ull;

// ---------------- packed f32x2 helpers (sm_103a FFMA2 path) ----------------
__device__ __forceinline__ ull pack2(float lo, float hi) {
    ull r;
    asm("mov.b64 %0, {%1, %2};" : "=l"(r) : "f"(lo), "f"(hi));
    return r;
}
__device__ __forceinline__ void ffma2(ull& d, ull a, ull b) {
    asm("fma.rn.f32x2 %0, %1, %2, %0;" : "+l"(d) : "l"(a), "l"(b));
}
__device__ __forceinline__ float2 unpack2(ull v) {
    float lo, hi;
    asm("mov.b64 {%0, %1}, %2;" : "=f"(lo), "=f"(hi) : "l"(v));
    return make_float2(lo, hi);
}
__device__ __forceinline__ float hsum2(ull v) {
    float2 p = unpack2(v);
    return p.x + p.y;
}
// streaming 16-bit store (evict-first: kv is write-once/read-once)
__device__ __forceinline__ void sth_cs(__half* p, float v) {
    unsigned short u = __half_as_ushort(__float2half(v));
    asm volatile("st.global.cs.u16 [%0], %1;" :: "l"(p), "h"(u) : "memory");
}

// ---------------- scratch (device globals; allocation-free) ----------------
__device__ __half g_hh[NN * KK * HH];     // hs = tanh(proj)*dinv, fp16 (76.8 MB)
__device__ __half g_kvh[NN * KK * 128];   // per (n,k): [k(64)|v(64)] fp16 (153.6 MB)
__device__ float g_h2r5[NN * HH];         // post-GCN relu, row k=5 (residual + q input)
__device__ __half g_pah[NN * HH];         // h_final @ Wd1[0:64], fp16 (12.8 MB)
__device__ __half g_pbh[NN * HH];         // h_final @ Wd1[64:128] + b1, fp16
__device__ float g_dinv[NN];
__device__ int   g_counts[NN];
__device__ int   g_scan[NN];
__device__ int   g_blocksum[128];
__device__ int   g_blockoff[128];
__device__ int   g_rowstart[NN + 1];
__device__ int   g_cursor[NN];
__device__ int   g_srclist[MM];

// ---------------- small utility kernels ----------------
__global__ void k_zero_counts() {
    int i = blockIdx.x * blockDim.x + threadIdx.x;
    if (i < NN) g_counts[i] = 0;
}

__global__ void k_count(const int* __restrict__ ei) {
    int e = blockIdx.x * blockDim.x + threadIdx.x;
    if (e < MM) atomicAdd(&g_counts[ei[MM + e]], 1);
}

// ---------------- coalesced 3-phase scan ----------------
__global__ __launch_bounds__(1024) void k_blockscan() {
    __shared__ int warpsums[32];
    int t = threadIdx.x, lane = t & 31, w = t >> 5;
    int i = blockIdx.x * 1024 + t;
    int v0 = (i < NN) ? g_counts[i] : 0;
    if (i < NN) g_dinv[i] = rsqrtf((float)v0 + 1.0f);
    int v = v0;
#pragma unroll
    for (int off = 1; off < 32; off <<= 1) {
        int x = __shfl_up_sync(0xffffffffu, v, off);
        if (lane >= off) v += x;
    }
    if (lane == 31) warpsums[w] = v;
    __syncthreads();
    if (w == 0) {
        int s = warpsums[lane];
#pragma unroll
        for (int off = 1; off < 32; off <<= 1) {
            int x = __shfl_up_sync(0xffffffffu, s, off);
            if (lane >= off) s += x;
        }
        warpsums[lane] = s;
    }
    __syncthreads();
    int incl = v + (w > 0 ? warpsums[w - 1] : 0);
    if (i < NN) g_scan[i] = incl;
    if (t == 1023) g_blocksum[blockIdx.x] = incl;
}

__global__ void k_scan2() {
    __shared__ int warpsums[4];
    int t = threadIdx.x, lane = t & 31, w = t >> 5;
    int v0 = (t < NBLK) ? g_blocksum[t] : 0;
    int v = v0;
#pragma unroll
    for (int off = 1; off < 32; off <<= 1) {
        int x = __shfl_up_sync(0xffffffffu, v, off);
        if (lane >= off) v += x;
    }
    if (lane == 31) warpsums[w] = v;
    __syncthreads();
    int base = 0;
    for (int j = 0; j < w; j++) base += warpsums[j];
    int incl = v + base;
    if (t < NBLK) g_blockoff[t] = incl - v0;
    if (t == NBLK - 1) g_rowstart[NN] = incl;
}

__global__ void k_apply() {
    int i = blockIdx.x * blockDim.x + threadIdx.x;
    if (i < NN) {
        int excl = g_scan[i] - g_counts[i] + g_blockoff[i >> 10];
        g_rowstart[i] = excl;
        g_cursor[i]   = excl;
    }
}

__global__ void k_fill(const int* __restrict__ ei) {
    int e = blockIdx.x * blockDim.x + threadIdx.x;
    if (e < MM) {
        int d = ei[MM + e];
        int p = atomicAdd(&g_cursor[d], 1);
        g_srclist[p] = ei[e];
    }
}

// ---------------- projection (+ inline ck): hs = tanh(dot12 + ck)*dinv, fp16 --------
__global__ __launch_bounds__(256) void k_projck(
    const float* __restrict__ x, const float* __restrict__ W_proj,
    const float* __restrict__ b_proj, const float* __restrict__ u,
    const float* __restrict__ u_seq) {
    __shared__ float Wp12[12 * HH];
    __shared__ float cks[KK * HH];
    int t = threadIdx.x;
    for (int i = t; i < 12 * HH; i += 256) Wp12[i] = W_proj[i];
    if (t < HH) {
        int c = t;
        float base = b_proj[c];
#pragma unroll
        for (int j = 0; j < 11; j++) base += u[j] * W_proj[(12 + j) * HH + c];
#pragma unroll
        for (int k = 0; k < KK; k++) {
            float val = base;
#pragma unroll
            for (int j = 0; j < 5; j++) val += u_seq[k * 5 + j] * W_proj[(23 + j) * HH + c];
            cks[k * HH + c] = val;
        }
    }
    __syncthreads();
    int g = t >> 6, c = t & 63;
    int n = blockIdx.x * 4 + g;
    float dn = g_dinv[n];
    float s = 0.f;
#pragma unroll
    for (int j = 0; j < 12; j++) s += __ldg(&x[n * 12 + j]) * Wp12[j * HH + c];
    int base = n * (KK * HH) + c;
#pragma unroll
    for (int k = 0; k < KK; k++)
        g_hh[base + k * HH] = __float2half(tanhf(s + cks[k * HH + c]) * dn);
}

// ---------------- fused AGGREGATE + GCN + KV (warp per node) ----------------
struct __align__(16) SG {
    float Wgt[HH * WSTR];       // Wgt[c*66+j] = W_gcn[j][c]
    float Wkvt[128 * WSTR];     // Wkvt[c*66+j] = [Wk|Wv][j][c]
    float arow[12][KK][HH];
    float h2s[12][KK][HH];
    float bg[HH], bkv[128];
};

__global__ __launch_bounds__(384) void k_gcnqkv(
    const float* __restrict__ W_gcn, const float* __restrict__ b_gcn,
    const float* __restrict__ Wk, const float* __restrict__ bk,
    const float* __restrict__ Wv, const float* __restrict__ bv) {
    extern __shared__ char smem_raw[];
    SG& s = *reinterpret_cast<SG*>(smem_raw);
    int t = threadIdx.x, w = t >> 5, l = t & 31;
    for (int i = t; i < HH * HH; i += 384) {
        int j = i >> 6, c = i & 63;
        s.Wgt[c * WSTR + j] = W_gcn[i];
        s.Wkvt[c * WSTR + j] = Wk[i];
        s.Wkvt[(c + 64) * WSTR + j] = Wv[i];
    }
    if (t < HH) { s.bg[t] = b_gcn[t]; s.bkv[t] = bk[t]; s.bkv[64 + t] = bv[t]; }
    __syncthreads();
    const int c0 = l, c1 = l + 32;
    const __half2* hh2 = (const __half2*)g_hh;
    for (int n = blockIdx.x * 12 + w; n < NN; n += gridDim.x * 12) {
        // stage 0: aggregate (4-way unrolled gather)
        {
            float dn = g_dinv[n];
            int s0 = g_rowstart[n], s1 = g_rowstart[n + 1];
            float2 acc[KK];
#pragma unroll
            for (int r = 0; r < KK; r++)
                acc[r] = __half22float2(hh2[(n * KK + r) * 32 + l]);
            int i = s0;
            for (; i + 3 < s1; i += 4) {
                const __half2* pa = hh2 + g_srclist[i]     * (KK * 32) + l;
                const __half2* pb = hh2 + g_srclist[i + 1] * (KK * 32) + l;
                const __half2* pc = hh2 + g_srclist[i + 2] * (KK * 32) + l;
                const __half2* pd = hh2 + g_srclist[i + 3] * (KK * 32) + l;
#pragma unroll
                for (int r = 0; r < KK; r++) {
                    float2 va = __half22float2(pa[r * 32]);
                    float2 vb = __half22float2(pb[r * 32]);
                    float2 vc = __half22float2(pc[r * 32]);
                    float2 vd = __half22float2(pd[r * 32]);
                    acc[r].x += (va.x + vb.x) + (vc.x + vd.x);
                    acc[r].y += (va.y + vb.y) + (vc.y + vd.y);
                }
            }
            for (; i < s1; i++) {
                const __half2* pa = hh2 + g_srclist[i] * (KK * 32) + l;
#pragma unroll
                for (int r = 0; r < KK; r++) {
                    float2 va = __half22float2(pa[r * 32]);
                    acc[r].x += va.x;
                    acc[r].y += va.y;
                }
            }
#pragma unroll
            for (int r = 0; r < KK; r++) {
                s.arow[w][r][2 * l]     = acc[r].x * dn;
                s.arow[w][r][2 * l + 1] = acc[r].y * dn;
            }
        }
        __syncwarp();
        // stage 1: h2 = relu(agg @ Wg + bg)
        {
            ull acc[KK][2];
#pragma unroll
            for (int r = 0; r < KK; r++) { acc[r][0] = 0ull; acc[r][1] = 0ull; }
#pragma unroll
            for (int j2 = 0; j2 < 32; j2++) {
                ull w0 = *(const ull*)&s.Wgt[c0 * WSTR + 2 * j2];
                ull w1 = *(const ull*)&s.Wgt[c1 * WSTR + 2 * j2];
#pragma unroll
                for (int r = 0; r < KK; r++) {
                    ull av = *(const ull*)&s.arow[w][r][2 * j2];
                    ffma2(acc[r][0], av, w0);
                    ffma2(acc[r][1], av, w1);
                }
            }
#pragma unroll
            for (int r = 0; r < KK; r++) {
                float h0 = fmaxf(hsum2(acc[r][0]) + s.bg[c0], 0.f);
                float h1 = fmaxf(hsum2(acc[r][1]) + s.bg[c1], 0.f);
                s.h2s[w][r][c0] = h0;
                s.h2s[w][r][c1] = h1;
                if (r == KK - 1) {
                    g_h2r5[n * HH + c0] = h0;
                    g_h2r5[n * HH + c1] = h1;
                }
            }
        }
        __syncwarp();
        // stage 2: kv = h2 @ [Wk|Wv] + b -> fp16 global, direct coalesced half stores
        {
            ull acc[KK][4];
#pragma unroll
            for (int r = 0; r < KK; r++)
#pragma unroll
                for (int q = 0; q < 4; q++) acc[r][q] = 0ull;
#pragma unroll
            for (int j2 = 0; j2 < 32; j2++) {
                ull w0 = *(const ull*)&s.Wkvt[(l)      * WSTR + 2 * j2];
                ull w1 = *(const ull*)&s.Wkvt[(l + 32) * WSTR + 2 * j2];
                ull w2 = *(const ull*)&s.Wkvt[(l + 64) * WSTR + 2 * j2];
                ull w3 = *(const ull*)&s.Wkvt[(l + 96) * WSTR + 2 * j2];
#pragma unroll
                for (int r = 0; r < KK; r++) {
                    ull hv = *(const ull*)&s.h2s[w][r][2 * j2];
                    ffma2(acc[r][0], hv, w0);
                    ffma2(acc[r][1], hv, w1);
                    ffma2(acc[r][2], hv, w2);
                    ffma2(acc[r][3], hv, w3);
                }
            }
#pragma unroll
            for (int r = 0; r < KK; r++) {
                __half* kvp = &g_kvh[(n * KK + r) * 128];
                sth_cs(kvp + l,      hsum2(acc[r][0]) + s.bkv[l]);
                sth_cs(kvp + l + 32, hsum2(acc[r][1]) + s.bkv[l + 32]);
                sth_cs(kvp + l + 64, hsum2(acc[r][2]) + s.bkv[l + 64]);
                sth_cs(kvp + l + 96, hsum2(acc[r][3]) + s.bkv[l + 96]);
            }
        }
    }
}

// ---- fused Q + attention + LN1 + FF + LN2 + decoder-precompute (warp per node) ----
struct __align__(16) SAF {
    float Wqt[HH * WSTR];
    float Wot[HH * WSTR];
    float W1t[128 * WSTR];
    float W2t[HH * 130];
    float Wat[HH * WSTR];
    float Wbt[HH * WSTR];
    float kv[12][KK * 128];
    float qv[12][HH];
    float ao[12][HH];
    float hm[12][HH];
    float z1[12][2 * HH];
    float aw[12][NHD * KK];
    float bq[HH], bo[HH], g1[HH], b1[HH], bb2[HH], g2[HH], be2[HH], b1d[HH];
    float bb1[2 * HH];
};

__global__ __launch_bounds__(384) void k_attnff(
    const float* __restrict__ Wq, const float* __restrict__ bq,
    const float* __restrict__ Wo, const float* __restrict__ bo,
    const float* __restrict__ ln1g, const float* __restrict__ ln1b,
    const float* __restrict__ W_ff1, const float* __restrict__ b_ff1,
    const float* __restrict__ W_ff2, const float* __restrict__ b_ff2,
    const float* __restrict__ ln2g, const float* __restrict__ ln2b,
    const float* __restrict__ Wd1, const float* __restrict__ bd1) {
    extern __shared__ char smem_raw[];
    SAF& s = *reinterpret_cast<SAF*>(smem_raw);
    int t = threadIdx.x, w = t >> 5, l = t & 31;
    for (int i = t; i < HH * HH; i += 384) {
        int j = i >> 6, c = i & 63;
        s.Wqt[c * WSTR + j] = Wq[i];
        s.Wot[c * WSTR + j] = Wo[i];
        s.Wat[c * WSTR + j] = Wd1[i];
        s.Wbt[c * WSTR + j] = Wd1[HH * HH + i];
    }
    for (int i = t; i < HH * 128; i += 384) {
        int j = i >> 7, c = i & 127;
        s.W1t[c * WSTR + j] = W_ff1[i];
    }
    for (int i = t; i < 128 * HH; i += 384) {
        int j = i >> 6, c = i & 63;
        s.W2t[c * 130 + j] = W_ff2[i];
    }
    if (t < HH) {
        s.bq[t] = bq[t]; s.bo[t] = bo[t]; s.g1[t] = ln1g[t]; s.b1[t] = ln1b[t];
        s.bb2[t] = b_ff2[t]; s.g2[t] = ln2g[t]; s.be2[t] = ln2b[t];
        s.b1d[t] = bd1[t];
    }
    if (t < 2 * HH) s.bb1[t] = b_ff1[t];
    __syncthreads();
    const int c0 = l, c1 = l + 32;
    int c2 = 2 * l, c4 = 4 * l;
    for (int n = blockIdx.x * 12 + w; n < NN; n += gridDim.x * 12) {
        // load h2row5 (residual + q input) and kv (fp16 streaming -> fp32 smem)
        float r50 = g_h2r5[n * HH + c0];
        float r51 = g_h2r5[n * HH + c1];
        s.hm[w][c0] = r50; s.hm[w][c1] = r51;
#pragma unroll
        for (int r = 0; r < KK; r++) {
            ull raw = __ldcs((const ull*)&g_kvh[(n * KK + r) * 128 + c4]);
            __half2 h0 = *(__half2*)&raw;
            __half2 h1 = *((__half2*)&raw + 1);
            float2 f0 = __half22float2(h0), f1 = __half22float2(h1);
            *(float4*)&s.kv[w][r * 128 + c4] = make_float4(f0.x, f0.y, f1.x, f1.y);
        }
        __syncwarp();
        // q = h2row5 @ Wq + bq
        {
            ull q0 = 0ull, q1 = 0ull;
#pragma unroll
            for (int j2 = 0; j2 < 32; j2++) {
                ull hv = *(const ull*)&s.hm[w][2 * j2];
                ull w0 = *(const ull*)&s.Wqt[c0 * WSTR + 2 * j2];
                ull w1 = *(const ull*)&s.Wqt[c1 * WSTR + 2 * j2];
                ffma2(q0, hv, w0);
                ffma2(q1, hv, w1);
            }
            s.qv[w][c0] = hsum2(q0) + s.bq[c0];
            s.qv[w][c1] = hsum2(q1) + s.bq[c1];
        }
        __syncwarp();
        // scores
        float sc = 0.f;
        int hh = l / KK, kk = l - hh * KK;
        if (l < NHD * KK) {
#pragma unroll
            for (int d = 0; d < DHD; d++)
                sc += s.qv[w][hh * DHD + d] * s.kv[w][kk * 128 + hh * DHD + d];
            sc *= 0.25f;
        }
        float mysc[KK];
#pragma unroll
        for (int j = 0; j < KK; j++)
            mysc[j] = __shfl_sync(0xffffffffu, sc, (l & 3) * KK + j);
        if (l < NHD) {
            float mx = mysc[0];
#pragma unroll
            for (int j = 1; j < KK; j++) mx = fmaxf(mx, mysc[j]);
            float sum = 0.f;
#pragma unroll
            for (int j = 0; j < KK; j++) { mysc[j] = expf(mysc[j] - mx); sum += mysc[j]; }
            float inv = 1.0f / sum;
#pragma unroll
            for (int j = 0; j < KK; j++) s.aw[w][l * KK + j] = mysc[j] * inv;
        }
        __syncwarp();
        // AV
        int hd = l >> 3;
        float a0 = 0.f, a1 = 0.f;
#pragma unroll
        for (int j = 0; j < KK; j++) {
            float wgt = s.aw[w][hd * KK + j];
            float2 vv = *(const float2*)&s.kv[w][j * 128 + 64 + c2];
            a0 += wgt * vv.x; a1 += wgt * vv.y;
        }
        s.ao[w][c2] = a0; s.ao[w][c2 + 1] = a1;
        __syncwarp();
        // Wo GEMV + residual + LN1
        ull o0 = 0ull, o1 = 0ull;
#pragma unroll
        for (int j2 = 0; j2 < 32; j2++) {
            ull av = *(const ull*)&s.ao[w][2 * j2];
            ull w0 = *(const ull*)&s.Wot[c0 * WSTR + 2 * j2];
            ull w1 = *(const ull*)&s.Wot[c1 * WSTR + 2 * j2];
            ffma2(o0, av, w0);
            ffma2(o1, av, w1);
        }
        float y0 = r50 + hsum2(o0) + s.bo[c0];
        float y1 = r51 + hsum2(o1) + s.bo[c1];
        float s1 = y0 + y1, s2 = y0 * y0 + y1 * y1;
#pragma unroll
        for (int off = 16; off > 0; off >>= 1) {
            s1 += __shfl_xor_sync(0xffffffffu, s1, off);
            s2 += __shfl_xor_sync(0xffffffffu, s2, off);
        }
        float m = s1 * (1.0f / HH);
        float var = s2 * (1.0f / HH) - m * m;
        float rstd = rsqrtf(var + 1e-5f);
        float hm0 = (y0 - m) * rstd * s.g1[c0] + s.b1[c0];
        float hm1 = (y1 - m) * rstd * s.g1[c1] + s.b1[c1];
        __syncwarp();
        s.hm[w][c0] = hm0; s.hm[w][c1] = hm1;
        __syncwarp();
        // FF1
        {
            ull f0 = 0ull, f1 = 0ull, f2 = 0ull, f3 = 0ull;
#pragma unroll
            for (int j2 = 0; j2 < 32; j2++) {
                ull hv = *(const ull*)&s.hm[w][2 * j2];
                ull w0 = *(const ull*)&s.W1t[(l)      * WSTR + 2 * j2];
                ull w1 = *(const ull*)&s.W1t[(l + 32) * WSTR + 2 * j2];
                ull w2 = *(const ull*)&s.W1t[(l + 64) * WSTR + 2 * j2];
                ull w3 = *(const ull*)&s.W1t[(l + 96) * WSTR + 2 * j2];
                ffma2(f0, hv, w0);
                ffma2(f1, hv, w1);
                ffma2(f2, hv, w2);
                ffma2(f3, hv, w3);
            }
            s.z1[w][l]      = fmaxf(hsum2(f0) + s.bb1[l], 0.f);
            s.z1[w][l + 32] = fmaxf(hsum2(f1) + s.bb1[l + 32], 0.f);
            s.z1[w][l + 64] = fmaxf(hsum2(f2) + s.bb1[l + 64], 0.f);
            s.z1[w][l + 96] = fmaxf(hsum2(f3) + s.bb1[l + 96], 0.f);
        }
        __syncwarp();
        // FF2 + residual + LN2
        ull g0 = 0ull, g1a = 0ull;
#pragma unroll
        for (int j2 = 0; j2 < 64; j2++) {
            ull zv = *(const ull*)&s.z1[w][2 * j2];
            ull w0 = *(const ull*)&s.W2t[c0 * 130 + 2 * j2];
            ull w1 = *(const ull*)&s.W2t[c1 * 130 + 2 * j2];
            ffma2(g0, zv, w0);
            ffma2(g1a, zv, w1);
        }
        float u0 = hm0 + hsum2(g0) + s.bb2[c0];
        float u1 = hm1 + hsum2(g1a) + s.bb2[c1];
        float t1 = u0 + u1, t2 = u0 * u0 + u1 * u1;
#pragma unroll
        for (int off = 16; off > 0; off >>= 1) {
            t1 += __shfl_xor_sync(0xffffffffu, t1, off);
            t2 += __shfl_xor_sync(0xffffffffu, t2, off);
        }
        float m2 = t1 * (1.0f / HH);
        float var2 = t2 * (1.0f / HH) - m2 * m2;
        float rstd2 = rsqrtf(var2 + 1e-5f);
        float hf0 = (u0 - m2) * rstd2 * s.g2[c0] + s.be2[c0];
        float hf1 = (u1 - m2) * rstd2 * s.g2[c1] + s.be2[c1];
        __syncwarp();
        // decoder precompute (share hf via z1 buffer)
        s.z1[w][c0] = hf0; s.z1[w][c1] = hf1;
        __syncwarp();
        ull pa0 = 0ull, pa1 = 0ull, pb0 = 0ull, pb1 = 0ull;
#pragma unroll
        for (int j2 = 0; j2 < 32; j2++) {
            ull v = *(const ull*)&s.z1[w][2 * j2];
            ull wa0 = *(const ull*)&s.Wat[c0 * WSTR + 2 * j2];
            ull wa1 = *(const ull*)&s.Wat[c1 * WSTR + 2 * j2];
            ull wb0 = *(const ull*)&s.Wbt[c0 * WSTR + 2 * j2];
            ull wb1 = *(const ull*)&s.Wbt[c1 * WSTR + 2 * j2];
            ffma2(pa0, v, wa0);
            ffma2(pa1, v, wa1);
            ffma2(pb0, v, wb0);
            ffma2(pb1, v, wb1);
        }
        g_pah[n * HH + c0] = __float2half(hsum2(pa0));
        g_pah[n * HH + c1] = __float2half(hsum2(pa1));
        g_pbh[n * HH + c0] = __float2half(hsum2(pb0) + s.b1d[c0]);
        g_pbh[n * HH + c1] = __float2half(hsum2(pb1) + s.b1d[c1]);
        __syncwarp();
    }
}

// ------- edge decoder (factorized, FFMA2 W2, fp16 gathers, 4 edges per iteration) ----
struct __align__(16) SDec5 {
    float z[8][4][HH];    // offset 0 (8B-aligned) — required for LDS.64
    float2 W2p[32][32];
    float W1c[5 * HH];
    float W1d[4 * HH];
    float W3[32];
    float b2[32];
    float b3;
};

__global__ __launch_bounds__(256) void k_dec(
    const int* __restrict__ ei,
    const float* __restrict__ edge_attr, const float* __restrict__ edge_seq,
    const float* __restrict__ Wd1,
    const float* __restrict__ Wd2, const float* __restrict__ bd2,
    const float* __restrict__ Wd3, const float* __restrict__ bd3,
    float* __restrict__ out) {
    extern __shared__ char smem_raw[];
    SDec5& s = *reinterpret_cast<SDec5*>(smem_raw);
    int t = threadIdx.x, w = t >> 5, l = t & 31;
    for (int i = t; i < 5 * HH; i += 256) s.W1c[i] = Wd1[(2 * HH) * HH + i];
    for (int i = t; i < 4 * HH; i += 256) s.W1d[i] = Wd1[(2 * HH + 5) * HH + i];
    for (int i = t; i < 1024; i += 256) {
        int j = i >> 5, ll = i & 31;
        s.W2p[j][ll] = make_float2(Wd2[(2 * j) * 32 + ll], Wd2[(2 * j + 1) * 32 + ll]);
    }
    if (t < 32) { s.W3[t] = Wd3[t]; s.b2[t] = bd2[t]; }
    if (t == 0) s.b3 = bd3[0];
    __syncthreads();
    int c = 2 * l;
    const __half2* pa2 = (const __half2*)g_pah;
    const __half2* pb2 = (const __half2*)g_pbh;
    const int NG = MM / 4;   // 200000 groups of 4 edges
    for (int p = blockIdx.x * 8 + w; p < NG; p += gridDim.x * 8) {
        int e0 = 4 * p;
        // 8 independent random gathers in flight
        float zx[4], zy[4];
#pragma unroll
        for (int q = 0; q < 4; q++) {
            int src = ei[e0 + q], dst = ei[MM + e0 + q];
            float2 pav = __half22float2(pa2[src * 32 + l]);
            float2 pbv = __half22float2(pb2[dst * 32 + l]);
            zx[q] = pav.x + pbv.x;
            zy[q] = pav.y + pbv.y;
        }
#pragma unroll
        for (int j = 0; j < 5; j++) {
            float2 wv = *(const float2*)&s.W1c[j * HH + c];
#pragma unroll
            for (int q = 0; q < 4; q++) {
                float ev = __ldg(&edge_attr[(e0 + q) * 5 + j]);
                zx[q] += ev * wv.x; zy[q] += ev * wv.y;
            }
        }
#pragma unroll
        for (int j = 0; j < 4; j++) {
            float2 wv = *(const float2*)&s.W1d[j * HH + c];
#pragma unroll
            for (int q = 0; q < 4; q++) {
                float ev = __ldg(&edge_seq[(e0 + q) * (KK * 4) + (KK - 1) * 4 + j]);
                zx[q] += ev * wv.x; zy[q] += ev * wv.y;
            }
        }
#pragma unroll
        for (int q = 0; q < 4; q++) {
            s.z[w][q][c]     = fmaxf(zx[q], 0.f);
            s.z[w][q][c + 1] = fmaxf(zy[q], 0.f);
        }
        __syncwarp();
        // W2 GEMV: one weight load serves 4 edges; 4 independent chains
        ull acc0 = pack2(s.b2[l], 0.f);
        ull acc1 = acc0, acc2 = acc0, acc3 = acc0;
#pragma unroll
        for (int j = 0; j < 32; j++) {
            ull w2 = *(const ull*)&s.W2p[j][l];
            ffma2(acc0, *(const ull*)&s.z[w][0][2 * j], w2);
            ffma2(acc1, *(const ull*)&s.z[w][1][2 * j], w2);
            ffma2(acc2, *(const ull*)&s.z[w][2][2 * j], w2);
            ffma2(acc3, *(const ull*)&s.z[w][3][2 * j], w2);
        }
        float p0 = fmaxf(hsum2(acc0), 0.f) * s.W3[l];
        float p1 = fmaxf(hsum2(acc1), 0.f) * s.W3[l];
        float p2 = fmaxf(hsum2(acc2), 0.f) * s.W3[l];
        float p3 = fmaxf(hsum2(acc3), 0.f) * s.W3[l];
#pragma unroll
        for (int off = 16; off > 0; off >>= 1) {
            p0 += __shfl_down_sync(0xffffffffu, p0, off);
            p1 += __shfl_down_sync(0xffffffffu, p1, off);
            p2 += __shfl_down_sync(0xffffffffu, p2, off);
            p3 += __shfl_down_sync(0xffffffffu, p3, off);
        }
        if (l == 0) {
            out[e0]     = p0 + s.b3;
            out[e0 + 1] = p1 + s.b3;
            out[e0 + 2] = p2 + s.b3;
            out[e0 + 3] = p3 + s.b3;
        }
        __syncwarp();
    }
}

// ---------------- launch ----------------
extern "C" void kernel_launch(void* const* d_in, const int* in_sizes, int n_in,
                              void* d_out, int out_size) {
    const float* x        = (const float*)d_in[0];
    const int*   ei       = (const int*)  d_in[1];
    const float* eattr    = (const float*)d_in[2];
    const float* u        = (const float*)d_in[3];
    const float* eseq     = (const float*)d_in[4];
    const float* useq     = (const float*)d_in[5];
    const float* W_proj   = (const float*)d_in[6];
    const float* b_proj   = (const float*)d_in[7];
    const float* W_gcn    = (const float*)d_in[8];
    const float* b_gcn    = (const float*)d_in[9];
    const float* Wq       = (const float*)d_in[10];
    const float* bq       = (const float*)d_in[11];
    const float* Wk       = (const float*)d_in[12];
    const float* bk       = (const float*)d_in[13];
    const float* Wv       = (const float*)d_in[14];
    const float* bv       = (const float*)d_in[15];
    const float* Wo       = (const float*)d_in[16];
    const float* bo       = (const float*)d_in[17];
    const float* ln1g     = (const float*)d_in[18];
    const float* ln1b     = (const float*)d_in[19];
    const float* W_ff1    = (const float*)d_in[20];
    const float* b_ff1    = (const float*)d_in[21];
    const float* W_ff2    = (const float*)d_in[22];
    const float* b_ff2    = (const float*)d_in[23];
    const float* ln2g     = (const float*)d_in[24];
    const float* ln2b     = (const float*)d_in[25];
    const float* Wd1      = (const float*)d_in[26];
    const float* bd1      = (const float*)d_in[27];
    const float* Wd2      = (const float*)d_in[28];
    const float* bd2      = (const float*)d_in[29];
    const float* Wd3      = (const float*)d_in[30];
    const float* bd3      = (const float*)d_in[31];
    float* out = (float*)d_out;

    cudaFuncSetAttribute(k_gcnqkv, cudaFuncAttributeMaxDynamicSharedMemorySize, (int)sizeof(SG));
    cudaFuncSetAttribute(k_attnff, cudaFuncAttributeMaxDynamicSharedMemorySize, (int)sizeof(SAF));
    cudaFuncSetAttribute(k_dec,    cudaFuncAttributeMaxDynamicSharedMemorySize, (int)sizeof(SDec5));

    k_zero_counts<<<(NN + 255) / 256, 256>>>();
    k_count<<<(MM + 255) / 256, 256>>>(ei);
    k_blockscan<<<NBLK, 1024>>>();
    k_scan2<<<1, 128>>>();
    k_apply<<<(NN + 255) / 256, 256>>>();
    k_fill<<<(MM + 255) / 256, 256>>>(ei);
    k_projck<<<NN / 4, 256>>>(x, W_proj, b_proj, u, useq);
    k_gcnqkv<<<1184, 384, sizeof(SG)>>>(W_gcn, b_gcn, Wk, bk, Wv, bv);
    k_attnff<<<592, 384, sizeof(SAF)>>>(Wq, bq, Wo, bo, ln1g, ln1b, W_ff1, b_ff1,
                                        W_ff2, b_ff2, ln2g, ln2b, Wd1, bd1);
    k_dec<<<2048, 256, sizeof(SDec5)>>>(ei, eattr, eseq, Wd1, Wd2, bd2, Wd3, bd3, out);
}

// round 16
// speedup vs baseline: 2.2574x; 1.1856x over previous
#include <cuda_runtime.h>
#include <cuda_fp16.h>
#include <math.h>

#define NN 100000
#define MM 800000
#define KK 6
#define HH 64
#define NHD 4
#define DHD 16
#define NBLK 98   // ceil(NN/1024)
#define WSTR 66   // padded transposed-weight row stride (floats)

typedef unsigned long long ull;

// ---------------- packed f32x2 helpers (sm_103a FFMA2 path) ----------------
__device__ __forceinline__ ull pack2(float lo, float hi) {
    ull r;
    asm("mov.b64 %0, {%1, %2};" : "=l"(r) : "f"(lo), "f"(hi));
    return r;
}
__device__ __forceinline__ void ffma2(ull& d, ull a, ull b) {
    asm("fma.rn.f32x2 %0, %1, %2, %0;" : "+l"(d) : "l"(a), "l"(b));
}
__device__ __forceinline__ float2 unpack2(ull v) {
    float lo, hi;
    asm("mov.b64 {%0, %1}, %2;" : "=f"(lo), "=f"(hi) : "l"(v));
    return make_float2(lo, hi);
}
__device__ __forceinline__ float hsum2(ull v) {
    float2 p = unpack2(v);
    return p.x + p.y;
}
// streaming 16-bit store (evict-first: kv is write-once/read-once)
__device__ __forceinline__ void sth_cs(__half* p, float v) {
    unsigned short u = __half_as_ushort(__float2half(v));
    asm volatile("st.global.cs.u16 [%0], %1;" :: "l"(p), "h"(u) : "memory");
}

// ---------------- scratch (device globals; allocation-free) ----------------
__device__ __half g_hh[NN * KK * HH];     // hs = tanh(proj)*dinv, fp16 (76.8 MB)
__device__ __half g_kvh[NN * KK * 128];   // per (n,k): [k(64)|v(64)] fp16 (153.6 MB)
__device__ float g_h2r5[NN * HH];         // post-GCN relu, row k=5 (residual + q input)
__device__ __half g_pah[NN * HH];         // h_final @ Wd1[0:64], fp16 (12.8 MB)
__device__ __half g_pbh[NN * HH];         // h_final @ Wd1[64:128] + b1, fp16
__device__ float g_dinv[NN];
__device__ int   g_counts[NN];
__device__ int   g_scan[NN];
__device__ int   g_blocksum[128];
__device__ int   g_blockoff[128];
__device__ int   g_rowstart[NN + 1];
__device__ int   g_cursor[NN];
__device__ int   g_srclist[MM];

// ---------------- small utility kernels ----------------
__global__ void k_zero_counts() {
    int i = blockIdx.x * blockDim.x + threadIdx.x;
    if (i < NN) g_counts[i] = 0;
}

__global__ void k_count(const int* __restrict__ ei) {
    int e = blockIdx.x * blockDim.x + threadIdx.x;
    if (e < MM) atomicAdd(&g_counts[ei[MM + e]], 1);
}

// ---------------- coalesced 3-phase scan ----------------
__global__ __launch_bounds__(1024) void k_blockscan() {
    __shared__ int warpsums[32];
    int t = threadIdx.x, lane = t & 31, w = t >> 5;
    int i = blockIdx.x * 1024 + t;
    int v0 = (i < NN) ? g_counts[i] : 0;
    if (i < NN) g_dinv[i] = rsqrtf((float)v0 + 1.0f);
    int v = v0;
#pragma unroll
    for (int off = 1; off < 32; off <<= 1) {
        int x = __shfl_up_sync(0xffffffffu, v, off);
        if (lane >= off) v += x;
    }
    if (lane == 31) warpsums[w] = v;
    __syncthreads();
    if (w == 0) {
        int s = warpsums[lane];
#pragma unroll
        for (int off = 1; off < 32; off <<= 1) {
            int x = __shfl_up_sync(0xffffffffu, s, off);
            if (lane >= off) s += x;
        }
        warpsums[lane] = s;
    }
    __syncthreads();
    int incl = v + (w > 0 ? warpsums[w - 1] : 0);
    if (i < NN) g_scan[i] = incl;
    if (t == 1023) g_blocksum[blockIdx.x] = incl;
}

__global__ void k_scan2() {
    __shared__ int warpsums[4];
    int t = threadIdx.x, lane = t & 31, w = t >> 5;
    int v0 = (t < NBLK) ? g_blocksum[t] : 0;
    int v = v0;
#pragma unroll
    for (int off = 1; off < 32; off <<= 1) {
        int x = __shfl_up_sync(0xffffffffu, v, off);
        if (lane >= off) v += x;
    }
    if (lane == 31) warpsums[w] = v;
    __syncthreads();
    int base = 0;
    for (int j = 0; j < w; j++) base += warpsums[j];
    int incl = v + base;
    if (t < NBLK) g_blockoff[t] = incl - v0;
    if (t == NBLK - 1) g_rowstart[NN] = incl;
}

__global__ void k_apply() {
    int i = blockIdx.x * blockDim.x + threadIdx.x;
    if (i < NN) {
        int excl = g_scan[i] - g_counts[i] + g_blockoff[i >> 10];
        g_rowstart[i] = excl;
        g_cursor[i]   = excl;
    }
}

__global__ void k_fill(const int* __restrict__ ei) {
    int e = blockIdx.x * blockDim.x + threadIdx.x;
    if (e < MM) {
        int d = ei[MM + e];
        int p = atomicAdd(&g_cursor[d], 1);
        g_srclist[p] = ei[e];
    }
}

// ---------------- projection (+ inline ck): hs = tanh(dot12 + ck)*dinv, fp16 --------
__global__ __launch_bounds__(256) void k_projck(
    const float* __restrict__ x, const float* __restrict__ W_proj,
    const float* __restrict__ b_proj, const float* __restrict__ u,
    const float* __restrict__ u_seq) {
    __shared__ float Wp12[12 * HH];
    __shared__ float cks[KK * HH];
    int t = threadIdx.x;
    for (int i = t; i < 12 * HH; i += 256) Wp12[i] = W_proj[i];
    if (t < HH) {
        int c = t;
        float base = b_proj[c];
#pragma unroll
        for (int j = 0; j < 11; j++) base += u[j] * W_proj[(12 + j) * HH + c];
#pragma unroll
        for (int k = 0; k < KK; k++) {
            float val = base;
#pragma unroll
            for (int j = 0; j < 5; j++) val += u_seq[k * 5 + j] * W_proj[(23 + j) * HH + c];
            cks[k * HH + c] = val;
        }
    }
    __syncthreads();
    int g = t >> 6, c = t & 63;
    int n = blockIdx.x * 4 + g;
    float dn = g_dinv[n];
    float s = 0.f;
#pragma unroll
    for (int j = 0; j < 12; j++) s += __ldg(&x[n * 12 + j]) * Wp12[j * HH + c];
    int base = n * (KK * HH) + c;
#pragma unroll
    for (int k = 0; k < KK; k++)
        g_hh[base + k * HH] = __float2half(tanhf(s + cks[k * HH + c]) * dn);
}

// ---------------- fused AGGREGATE + GCN + KV (warp per node) ----------------
struct __align__(16) SG {
    float Wgt[HH * WSTR];       // Wgt[c*66+j] = W_gcn[j][c]
    float Wkvt[128 * WSTR];     // Wkvt[c*66+j] = [Wk|Wv][j][c]
    float arow[12][KK][HH];
    float h2s[12][KK][HH];
    float bg[HH], bkv[128];
};

__global__ __launch_bounds__(384) void k_gcnqkv(
    const float* __restrict__ W_gcn, const float* __restrict__ b_gcn,
    const float* __restrict__ Wk, const float* __restrict__ bk,
    const float* __restrict__ Wv, const float* __restrict__ bv) {
    extern __shared__ char smem_raw[];
    SG& s = *reinterpret_cast<SG*>(smem_raw);
    int t = threadIdx.x, w = t >> 5, l = t & 31;
    for (int i = t; i < HH * HH; i += 384) {
        int j = i >> 6, c = i & 63;
        s.Wgt[c * WSTR + j] = W_gcn[i];
        s.Wkvt[c * WSTR + j] = Wk[i];
        s.Wkvt[(c + 64) * WSTR + j] = Wv[i];
    }
    if (t < HH) { s.bg[t] = b_gcn[t]; s.bkv[t] = bk[t]; s.bkv[64 + t] = bv[t]; }
    __syncthreads();
    const int c0 = l, c1 = l + 32;
    const __half2* hh2 = (const __half2*)g_hh;
    for (int n = blockIdx.x * 12 + w; n < NN; n += gridDim.x * 12) {
        // stage 0: aggregate (4-way unrolled gather)
        {
            float dn = g_dinv[n];
            int s0 = g_rowstart[n], s1 = g_rowstart[n + 1];
            float2 acc[KK];
#pragma unroll
            for (int r = 0; r < KK; r++)
                acc[r] = __half22float2(hh2[(n * KK + r) * 32 + l]);
            int i = s0;
            for (; i + 3 < s1; i += 4) {
                const __half2* pa = hh2 + g_srclist[i]     * (KK * 32) + l;
                const __half2* pb = hh2 + g_srclist[i + 1] * (KK * 32) + l;
                const __half2* pc = hh2 + g_srclist[i + 2] * (KK * 32) + l;
                const __half2* pd = hh2 + g_srclist[i + 3] * (KK * 32) + l;
#pragma unroll
                for (int r = 0; r < KK; r++) {
                    float2 va = __half22float2(pa[r * 32]);
                    float2 vb = __half22float2(pb[r * 32]);
                    float2 vc = __half22float2(pc[r * 32]);
                    float2 vd = __half22float2(pd[r * 32]);
                    acc[r].x += (va.x + vb.x) + (vc.x + vd.x);
                    acc[r].y += (va.y + vb.y) + (vc.y + vd.y);
                }
            }
            for (; i < s1; i++) {
                const __half2* pa = hh2 + g_srclist[i] * (KK * 32) + l;
#pragma unroll
                for (int r = 0; r < KK; r++) {
                    float2 va = __half22float2(pa[r * 32]);
                    acc[r].x += va.x;
                    acc[r].y += va.y;
                }
            }
#pragma unroll
            for (int r = 0; r < KK; r++) {
                s.arow[w][r][2 * l]     = acc[r].x * dn;
                s.arow[w][r][2 * l + 1] = acc[r].y * dn;
            }
        }
        __syncwarp();
        // stage 1: h2 = relu(agg @ Wg + bg)
        {
            ull acc[KK][2];
#pragma unroll
            for (int r = 0; r < KK; r++) { acc[r][0] = 0ull; acc[r][1] = 0ull; }
#pragma unroll
            for (int j2 = 0; j2 < 32; j2++) {
                ull w0 = *(const ull*)&s.Wgt[c0 * WSTR + 2 * j2];
                ull w1 = *(const ull*)&s.Wgt[c1 * WSTR + 2 * j2];
#pragma unroll
                for (int r = 0; r < KK; r++) {
                    ull av = *(const ull*)&s.arow[w][r][2 * j2];
                    ffma2(acc[r][0], av, w0);
                    ffma2(acc[r][1], av, w1);
                }
            }
#pragma unroll
            for (int r = 0; r < KK; r++) {
                float h0 = fmaxf(hsum2(acc[r][0]) + s.bg[c0], 0.f);
                float h1 = fmaxf(hsum2(acc[r][1]) + s.bg[c1], 0.f);
                s.h2s[w][r][c0] = h0;
                s.h2s[w][r][c1] = h1;
                if (r == KK - 1) {
                    g_h2r5[n * HH + c0] = h0;
                    g_h2r5[n * HH + c1] = h1;
                }
            }
        }
        __syncwarp();
        // stage 2: kv = h2 @ [Wk|Wv] + b -> fp16 global, direct coalesced half stores
        {
            ull acc[KK][4];
#pragma unroll
            for (int r = 0; r < KK; r++)
#pragma unroll
                for (int q = 0; q < 4; q++) acc[r][q] = 0ull;
#pragma unroll
            for (int j2 = 0; j2 < 32; j2++) {
                ull w0 = *(const ull*)&s.Wkvt[(l)      * WSTR + 2 * j2];
                ull w1 = *(const ull*)&s.Wkvt[(l + 32) * WSTR + 2 * j2];
                ull w2 = *(const ull*)&s.Wkvt[(l + 64) * WSTR + 2 * j2];
                ull w3 = *(const ull*)&s.Wkvt[(l + 96) * WSTR + 2 * j2];
#pragma unroll
                for (int r = 0; r < KK; r++) {
                    ull hv = *(const ull*)&s.h2s[w][r][2 * j2];
                    ffma2(acc[r][0], hv, w0);
                    ffma2(acc[r][1], hv, w1);
                    ffma2(acc[r][2], hv, w2);
                    ffma2(acc[r][3], hv, w3);
                }
            }
#pragma unroll
            for (int r = 0; r < KK; r++) {
                __half* kvp = &g_kvh[(n * KK + r) * 128];
                sth_cs(kvp + l,      hsum2(acc[r][0]) + s.bkv[l]);
                sth_cs(kvp + l + 32, hsum2(acc[r][1]) + s.bkv[l + 32]);
                sth_cs(kvp + l + 64, hsum2(acc[r][2]) + s.bkv[l + 64]);
                sth_cs(kvp + l + 96, hsum2(acc[r][3]) + s.bkv[l + 96]);
            }
        }
    }
}

// -- fused Q + attention + LN1 + FF + LN2 + decoder-precompute (warp per 2 nodes) ----
struct __align__(16) SAF2 {
    float Wqt[HH * WSTR];
    float Wot[HH * WSTR];
    float W1t[128 * WSTR];
    float W2t[HH * 130];
    float Wat[HH * WSTR];
    float Wbt[HH * WSTR];
    __half kvh[12][2][KK * 128];   // fp16 kv staging (raw from global)
    float hm[12][2][HH];
    float z1[12][2][2 * HH];
    float qv[12][2][HH];
    float ao[12][2][HH];
    float aw[12][2][NHD * KK];
    float bq[HH], bo[HH], g1[HH], b1[HH], bb2[HH], g2[HH], be2[HH], b1d[HH];
    float bb1[2 * HH];
};

__global__ __launch_bounds__(384) void k_attnff(
    const float* __restrict__ Wq, const float* __restrict__ bq,
    const float* __restrict__ Wo, const float* __restrict__ bo,
    const float* __restrict__ ln1g, const float* __restrict__ ln1b,
    const float* __restrict__ W_ff1, const float* __restrict__ b_ff1,
    const float* __restrict__ W_ff2, const float* __restrict__ b_ff2,
    const float* __restrict__ ln2g, const float* __restrict__ ln2b,
    const float* __restrict__ Wd1, const float* __restrict__ bd1) {
    extern __shared__ char smem_raw[];
    SAF2& s = *reinterpret_cast<SAF2*>(smem_raw);
    int t = threadIdx.x, w = t >> 5, l = t & 31;
    for (int i = t; i < HH * HH; i += 384) {
        int j = i >> 6, c = i & 63;
        s.Wqt[c * WSTR + j] = Wq[i];
        s.Wot[c * WSTR + j] = Wo[i];
        s.Wat[c * WSTR + j] = Wd1[i];
        s.Wbt[c * WSTR + j] = Wd1[HH * HH + i];
    }
    for (int i = t; i < HH * 128; i += 384) {
        int j = i >> 7, c = i & 127;
        s.W1t[c * WSTR + j] = W_ff1[i];
    }
    for (int i = t; i < 128 * HH; i += 384) {
        int j = i >> 6, c = i & 63;
        s.W2t[c * 130 + j] = W_ff2[i];
    }
    if (t < HH) {
        s.bq[t] = bq[t]; s.bo[t] = bo[t]; s.g1[t] = ln1g[t]; s.b1[t] = ln1b[t];
        s.bb2[t] = b_ff2[t]; s.g2[t] = ln2g[t]; s.be2[t] = ln2b[t];
        s.b1d[t] = bd1[t];
    }
    if (t < 2 * HH) s.bb1[t] = b_ff1[t];
    __syncthreads();
    const int c0 = l, c1 = l + 32;
    int c2 = 2 * l, c4 = 4 * l;
    const int NP = NN / 2;   // 50000 node pairs
    for (int p = blockIdx.x * 12 + w; p < NP; p += gridDim.x * 12) {
        int n0 = 2 * p, n1 = 2 * p + 1;
        // load h2row5 (residual + q input) for both nodes; kv raw fp16 -> smem
        float rA0 = g_h2r5[n0 * HH + c0], rA1 = g_h2r5[n0 * HH + c1];
        float rB0 = g_h2r5[n1 * HH + c0], rB1 = g_h2r5[n1 * HH + c1];
        s.hm[w][0][c0] = rA0; s.hm[w][0][c1] = rA1;
        s.hm[w][1][c0] = rB0; s.hm[w][1][c1] = rB1;
#pragma unroll
        for (int r = 0; r < KK; r++) {
            ull raw0 = __ldcs((const ull*)&g_kvh[(n0 * KK + r) * 128 + c4]);
            ull raw1 = __ldcs((const ull*)&g_kvh[(n1 * KK + r) * 128 + c4]);
            *(ull*)&s.kvh[w][0][r * 128 + c4] = raw0;
            *(ull*)&s.kvh[w][1][r * 128 + c4] = raw1;
        }
        __syncwarp();
        // q GEMV paired: 4 chains (2 nodes x 2 cols), weights loaded once
        {
            ull qA0 = 0ull, qA1 = 0ull, qB0 = 0ull, qB1 = 0ull;
#pragma unroll
            for (int j2 = 0; j2 < 32; j2++) {
                ull w0 = *(const ull*)&s.Wqt[c0 * WSTR + 2 * j2];
                ull w1 = *(const ull*)&s.Wqt[c1 * WSTR + 2 * j2];
                ull hv0 = *(const ull*)&s.hm[w][0][2 * j2];
                ull hv1 = *(const ull*)&s.hm[w][1][2 * j2];
                ffma2(qA0, hv0, w0);
                ffma2(qA1, hv0, w1);
                ffma2(qB0, hv1, w0);
                ffma2(qB1, hv1, w1);
            }
            s.qv[w][0][c0] = hsum2(qA0) + s.bq[c0];
            s.qv[w][0][c1] = hsum2(qA1) + s.bq[c1];
            s.qv[w][1][c0] = hsum2(qB0) + s.bq[c0];
            s.qv[w][1][c1] = hsum2(qB1) + s.bq[c1];
        }
        __syncwarp();
        // scores (both nodes), softmax
        {
            float sc0 = 0.f, sc1 = 0.f;
            int hh = l / KK, kk = l - hh * KK;
            if (l < NHD * KK) {
#pragma unroll
                for (int d = 0; d < DHD; d++) {
                    sc0 += s.qv[w][0][hh * DHD + d] * __half2float(s.kvh[w][0][kk * 128 + hh * DHD + d]);
                    sc1 += s.qv[w][1][hh * DHD + d] * __half2float(s.kvh[w][1][kk * 128 + hh * DHD + d]);
                }
                sc0 *= 0.25f; sc1 *= 0.25f;
            }
            float my0[KK], my1[KK];
#pragma unroll
            for (int j = 0; j < KK; j++) {
                my0[j] = __shfl_sync(0xffffffffu, sc0, (l & 3) * KK + j);
                my1[j] = __shfl_sync(0xffffffffu, sc1, (l & 3) * KK + j);
            }
            if (l < NHD) {
                float mx0 = my0[0], mx1 = my1[0];
#pragma unroll
                for (int j = 1; j < KK; j++) { mx0 = fmaxf(mx0, my0[j]); mx1 = fmaxf(mx1, my1[j]); }
                float sm0 = 0.f, sm1 = 0.f;
#pragma unroll
                for (int j = 0; j < KK; j++) {
                    my0[j] = expf(my0[j] - mx0); sm0 += my0[j];
                    my1[j] = expf(my1[j] - mx1); sm1 += my1[j];
                }
                float iv0 = 1.0f / sm0, iv1 = 1.0f / sm1;
#pragma unroll
                for (int j = 0; j < KK; j++) {
                    s.aw[w][0][l * KK + j] = my0[j] * iv0;
                    s.aw[w][1][l * KK + j] = my1[j] * iv1;
                }
            }
        }
        __syncwarp();
        // AV (both nodes)
        {
            int hd = l >> 3;
            float a00 = 0.f, a01 = 0.f, a10 = 0.f, a11 = 0.f;
#pragma unroll
            for (int j = 0; j < KK; j++) {
                float w0 = s.aw[w][0][hd * KK + j];
                float w1 = s.aw[w][1][hd * KK + j];
                float2 v0 = __half22float2(*(const __half2*)&s.kvh[w][0][j * 128 + 64 + c2]);
                float2 v1 = __half22float2(*(const __half2*)&s.kvh[w][1][j * 128 + 64 + c2]);
                a00 += w0 * v0.x; a01 += w0 * v0.y;
                a10 += w1 * v1.x; a11 += w1 * v1.y;
            }
            s.ao[w][0][c2] = a00; s.ao[w][0][c2 + 1] = a01;
            s.ao[w][1][c2] = a10; s.ao[w][1][c2 + 1] = a11;
        }
        __syncwarp();
        // Wo GEMV paired + residual + LN1 (interleaved shuffle chains)
        float hmA0, hmA1, hmB0, hmB1;
        {
            ull oA0 = 0ull, oA1 = 0ull, oB0 = 0ull, oB1 = 0ull;
#pragma unroll
            for (int j2 = 0; j2 < 32; j2++) {
                ull w0 = *(const ull*)&s.Wot[c0 * WSTR + 2 * j2];
                ull w1 = *(const ull*)&s.Wot[c1 * WSTR + 2 * j2];
                ull a0 = *(const ull*)&s.ao[w][0][2 * j2];
                ull a1 = *(const ull*)&s.ao[w][1][2 * j2];
                ffma2(oA0, a0, w0);
                ffma2(oA1, a0, w1);
                ffma2(oB0, a1, w0);
                ffma2(oB1, a1, w1);
            }
            float yA0 = rA0 + hsum2(oA0) + s.bo[c0];
            float yA1 = rA1 + hsum2(oA1) + s.bo[c1];
            float yB0 = rB0 + hsum2(oB0) + s.bo[c0];
            float yB1 = rB1 + hsum2(oB1) + s.bo[c1];
            float sA1 = yA0 + yA1, sA2 = yA0 * yA0 + yA1 * yA1;
            float sB1 = yB0 + yB1, sB2 = yB0 * yB0 + yB1 * yB1;
#pragma unroll
            for (int off = 16; off > 0; off >>= 1) {
                sA1 += __shfl_xor_sync(0xffffffffu, sA1, off);
                sA2 += __shfl_xor_sync(0xffffffffu, sA2, off);
                sB1 += __shfl_xor_sync(0xffffffffu, sB1, off);
                sB2 += __shfl_xor_sync(0xffffffffu, sB2, off);
            }
            float mA = sA1 * (1.0f / HH);
            float rsA = rsqrtf(sA2 * (1.0f / HH) - mA * mA + 1e-5f);
            float mB = sB1 * (1.0f / HH);
            float rsB = rsqrtf(sB2 * (1.0f / HH) - mB * mB + 1e-5f);
            hmA0 = (yA0 - mA) * rsA * s.g1[c0] + s.b1[c0];
            hmA1 = (yA1 - mA) * rsA * s.g1[c1] + s.b1[c1];
            hmB0 = (yB0 - mB) * rsB * s.g1[c0] + s.b1[c0];
            hmB1 = (yB1 - mB) * rsB * s.g1[c1] + s.b1[c1];
        }
        __syncwarp();
        s.hm[w][0][c0] = hmA0; s.hm[w][0][c1] = hmA1;
        s.hm[w][1][c0] = hmB0; s.hm[w][1][c1] = hmB1;
        __syncwarp();
        // FF1 paired: 8 chains (2 nodes x 4 cols)
        {
            ull fA0 = 0ull, fA1 = 0ull, fA2 = 0ull, fA3 = 0ull;
            ull fB0 = 0ull, fB1 = 0ull, fB2 = 0ull, fB3 = 0ull;
#pragma unroll
            for (int j2 = 0; j2 < 32; j2++) {
                ull w0 = *(const ull*)&s.W1t[(l)      * WSTR + 2 * j2];
                ull w1 = *(const ull*)&s.W1t[(l + 32) * WSTR + 2 * j2];
                ull w2 = *(const ull*)&s.W1t[(l + 64) * WSTR + 2 * j2];
                ull w3 = *(const ull*)&s.W1t[(l + 96) * WSTR + 2 * j2];
                ull h0 = *(const ull*)&s.hm[w][0][2 * j2];
                ull h1 = *(const ull*)&s.hm[w][1][2 * j2];
                ffma2(fA0, h0, w0); ffma2(fA1, h0, w1); ffma2(fA2, h0, w2); ffma2(fA3, h0, w3);
                ffma2(fB0, h1, w0); ffma2(fB1, h1, w1); ffma2(fB2, h1, w2); ffma2(fB3, h1, w3);
            }
            s.z1[w][0][l]      = fmaxf(hsum2(fA0) + s.bb1[l], 0.f);
            s.z1[w][0][l + 32] = fmaxf(hsum2(fA1) + s.bb1[l + 32], 0.f);
            s.z1[w][0][l + 64] = fmaxf(hsum2(fA2) + s.bb1[l + 64], 0.f);
            s.z1[w][0][l + 96] = fmaxf(hsum2(fA3) + s.bb1[l + 96], 0.f);
            s.z1[w][1][l]      = fmaxf(hsum2(fB0) + s.bb1[l], 0.f);
            s.z1[w][1][l + 32] = fmaxf(hsum2(fB1) + s.bb1[l + 32], 0.f);
            s.z1[w][1][l + 64] = fmaxf(hsum2(fB2) + s.bb1[l + 64], 0.f);
            s.z1[w][1][l + 96] = fmaxf(hsum2(fB3) + s.bb1[l + 96], 0.f);
        }
        __syncwarp();
        // FF2 paired + residual + LN2 (interleaved)
        float hfA0, hfA1, hfB0, hfB1;
        {
            ull gA0 = 0ull, gA1 = 0ull, gB0 = 0ull, gB1 = 0ull;
#pragma unroll
            for (int j2 = 0; j2 < 64; j2++) {
                ull w0 = *(const ull*)&s.W2t[c0 * 130 + 2 * j2];
                ull w1 = *(const ull*)&s.W2t[c1 * 130 + 2 * j2];
                ull z0 = *(const ull*)&s.z1[w][0][2 * j2];
                ull z1v = *(const ull*)&s.z1[w][1][2 * j2];
                ffma2(gA0, z0, w0);
                ffma2(gA1, z0, w1);
                ffma2(gB0, z1v, w0);
                ffma2(gB1, z1v, w1);
            }
            float uA0 = hmA0 + hsum2(gA0) + s.bb2[c0];
            float uA1 = hmA1 + hsum2(gA1) + s.bb2[c1];
            float uB0 = hmB0 + hsum2(gB0) + s.bb2[c0];
            float uB1 = hmB1 + hsum2(gB1) + s.bb2[c1];
            float sA1 = uA0 + uA1, sA2 = uA0 * uA0 + uA1 * uA1;
            float sB1 = uB0 + uB1, sB2 = uB0 * uB0 + uB1 * uB1;
#pragma unroll
            for (int off = 16; off > 0; off >>= 1) {
                sA1 += __shfl_xor_sync(0xffffffffu, sA1, off);
                sA2 += __shfl_xor_sync(0xffffffffu, sA2, off);
                sB1 += __shfl_xor_sync(0xffffffffu, sB1, off);
                sB2 += __shfl_xor_sync(0xffffffffu, sB2, off);
            }
            float mA = sA1 * (1.0f / HH);
            float rsA = rsqrtf(sA2 * (1.0f / HH) - mA * mA + 1e-5f);
            float mB = sB1 * (1.0f / HH);
            float rsB = rsqrtf(sB2 * (1.0f / HH) - mB * mB + 1e-5f);
            hfA0 = (uA0 - mA) * rsA * s.g2[c0] + s.be2[c0];
            hfA1 = (uA1 - mA) * rsA * s.g2[c1] + s.be2[c1];
            hfB0 = (uB0 - mB) * rsB * s.g2[c0] + s.be2[c0];
            hfB1 = (uB1 - mB) * rsB * s.g2[c1] + s.be2[c1];
        }
        __syncwarp();
        // decoder precompute paired (share hf via z1 buffers)
        s.z1[w][0][c0] = hfA0; s.z1[w][0][c1] = hfA1;
        s.z1[w][1][c0] = hfB0; s.z1[w][1][c1] = hfB1;
        __syncwarp();
        {
            ull paA0 = 0ull, paA1 = 0ull, pbA0 = 0ull, pbA1 = 0ull;
            ull paB0 = 0ull, paB1 = 0ull, pbB0 = 0ull, pbB1 = 0ull;
#pragma unroll
            for (int j2 = 0; j2 < 32; j2++) {
                ull wa0 = *(const ull*)&s.Wat[c0 * WSTR + 2 * j2];
                ull wa1 = *(const ull*)&s.Wat[c1 * WSTR + 2 * j2];
                ull wb0 = *(const ull*)&s.Wbt[c0 * WSTR + 2 * j2];
                ull wb1 = *(const ull*)&s.Wbt[c1 * WSTR + 2 * j2];
                ull v0 = *(const ull*)&s.z1[w][0][2 * j2];
                ull v1 = *(const ull*)&s.z1[w][1][2 * j2];
                ffma2(paA0, v0, wa0); ffma2(paA1, v0, wa1);
                ffma2(pbA0, v0, wb0); ffma2(pbA1, v0, wb1);
                ffma2(paB0, v1, wa0); ffma2(paB1, v1, wa1);
                ffma2(pbB0, v1, wb0); ffma2(pbB1, v1, wb1);
            }
            g_pah[n0 * HH + c0] = __float2half(hsum2(paA0));
            g_pah[n0 * HH + c1] = __float2half(hsum2(paA1));
            g_pbh[n0 * HH + c0] = __float2half(hsum2(pbA0) + s.b1d[c0]);
            g_pbh[n0 * HH + c1] = __float2half(hsum2(pbA1) + s.b1d[c1]);
            g_pah[n1 * HH + c0] = __float2half(hsum2(paB0));
            g_pah[n1 * HH + c1] = __float2half(hsum2(paB1));
            g_pbh[n1 * HH + c0] = __float2half(hsum2(pbB0) + s.b1d[c0]);
            g_pbh[n1 * HH + c1] = __float2half(hsum2(pbB1) + s.b1d[c1]);
        }
        __syncwarp();
    }
}

// ------- edge decoder (factorized, FFMA2 W2, fp16 gathers, 4 edges per iteration) ----
struct __align__(16) SDec5 {
    float z[8][4][HH];    // offset 0 (8B-aligned) — required for LDS.64
    float2 W2p[32][32];
    float W1c[5 * HH];
    float W1d[4 * HH];
    float W3[32];
    float b2[32];
    float b3;
};

__global__ __launch_bounds__(256) void k_dec(
    const int* __restrict__ ei,
    const float* __restrict__ edge_attr, const float* __restrict__ edge_seq,
    const float* __restrict__ Wd1,
    const float* __restrict__ Wd2, const float* __restrict__ bd2,
    const float* __restrict__ Wd3, const float* __restrict__ bd3,
    float* __restrict__ out) {
    extern __shared__ char smem_raw[];
    SDec5& s = *reinterpret_cast<SDec5*>(smem_raw);
    int t = threadIdx.x, w = t >> 5, l = t & 31;
    for (int i = t; i < 5 * HH; i += 256) s.W1c[i] = Wd1[(2 * HH) * HH + i];
    for (int i = t; i < 4 * HH; i += 256) s.W1d[i] = Wd1[(2 * HH + 5) * HH + i];
    for (int i = t; i < 1024; i += 256) {
        int j = i >> 5, ll = i & 31;
        s.W2p[j][ll] = make_float2(Wd2[(2 * j) * 32 + ll], Wd2[(2 * j + 1) * 32 + ll]);
    }
    if (t < 32) { s.W3[t] = Wd3[t]; s.b2[t] = bd2[t]; }
    if (t == 0) s.b3 = bd3[0];
    __syncthreads();
    int c = 2 * l;
    const __half2* pa2 = (const __half2*)g_pah;
    const __half2* pb2 = (const __half2*)g_pbh;
    const int NG = MM / 4;   // 200000 groups of 4 edges
    for (int p = blockIdx.x * 8 + w; p < NG; p += gridDim.x * 8) {
        int e0 = 4 * p;
        float zx[4], zy[4];
#pragma unroll
        for (int q = 0; q < 4; q++) {
            int src = ei[e0 + q], dst = ei[MM + e0 + q];
            float2 pav = __half22float2(pa2[src * 32 + l]);
            float2 pbv = __half22float2(pb2[dst * 32 + l]);
            zx[q] = pav.x + pbv.x;
            zy[q] = pav.y + pbv.y;
        }
#pragma unroll
        for (int j = 0; j < 5; j++) {
            float2 wv = *(const float2*)&s.W1c[j * HH + c];
#pragma unroll
            for (int q = 0; q < 4; q++) {
                float ev = __ldg(&edge_attr[(e0 + q) * 5 + j]);
                zx[q] += ev * wv.x; zy[q] += ev * wv.y;
            }
        }
#pragma unroll
        for (int j = 0; j < 4; j++) {
            float2 wv = *(const float2*)&s.W1d[j * HH + c];
#pragma unroll
            for (int q = 0; q < 4; q++) {
                float ev = __ldg(&edge_seq[(e0 + q) * (KK * 4) + (KK - 1) * 4 + j]);
                zx[q] += ev * wv.x; zy[q] += ev * wv.y;
            }
        }
#pragma unroll
        for (int q = 0; q < 4; q++) {
            s.z[w][q][c]     = fmaxf(zx[q], 0.f);
            s.z[w][q][c + 1] = fmaxf(zy[q], 0.f);
        }
        __syncwarp();
        ull acc0 = pack2(s.b2[l], 0.f);
        ull acc1 = acc0, acc2 = acc0, acc3 = acc0;
#pragma unroll
        for (int j = 0; j < 32; j++) {
            ull w2 = *(const ull*)&s.W2p[j][l];
            ffma2(acc0, *(const ull*)&s.z[w][0][2 * j], w2);
            ffma2(acc1, *(const ull*)&s.z[w][1][2 * j], w2);
            ffma2(acc2, *(const ull*)&s.z[w][2][2 * j], w2);
            ffma2(acc3, *(const ull*)&s.z[w][3][2 * j], w2);
        }
        float p0 = fmaxf(hsum2(acc0), 0.f) * s.W3[l];
        float p1 = fmaxf(hsum2(acc1), 0.f) * s.W3[l];
        float p2 = fmaxf(hsum2(acc2), 0.f) * s.W3[l];
        float p3 = fmaxf(hsum2(acc3), 0.f) * s.W3[l];
#pragma unroll
        for (int off = 16; off > 0; off >>= 1) {
            p0 += __shfl_down_sync(0xffffffffu, p0, off);
            p1 += __shfl_down_sync(0xffffffffu, p1, off);
            p2 += __shfl_down_sync(0xffffffffu, p2, off);
            p3 += __shfl_down_sync(0xffffffffu, p3, off);
        }
        if (l == 0) {
            out[e0]     = p0 + s.b3;
            out[e0 + 1] = p1 + s.b3;
            out[e0 + 2] = p2 + s.b3;
            out[e0 + 3] = p3 + s.b3;
        }
        __syncwarp();
    }
}

// ---------------- launch ----------------
extern "C" void kernel_launch(void* const* d_in, const int* in_sizes, int n_in,
                              void* d_out, int out_size) {
    const float* x        = (const float*)d_in[0];
    const int*   ei       = (const int*)  d_in[1];
    const float* eattr    = (const float*)d_in[2];
    const float* u        = (const float*)d_in[3];
    const float* eseq     = (const float*)d_in[4];
    const float* useq     = (const float*)d_in[5];
    const float* W_proj   = (const float*)d_in[6];
    const float* b_proj   = (const float*)d_in[7];
    const float* W_gcn    = (const float*)d_in[8];
    const float* b_gcn    = (const float*)d_in[9];
    const float* Wq       = (const float*)d_in[10];
    const float* bq       = (const float*)d_in[11];
    const float* Wk       = (const float*)d_in[12];
    const float* bk       = (const float*)d_in[13];
    const float* Wv       = (const float*)d_in[14];
    const float* bv       = (const float*)d_in[15];
    const float* Wo       = (const float*)d_in[16];
    const float* bo       = (const float*)d_in[17];
    const float* ln1g     = (const float*)d_in[18];
    const float* ln1b     = (const float*)d_in[19];
    const float* W_ff1    = (const float*)d_in[20];
    const float* b_ff1    = (const float*)d_in[21];
    const float* W_ff2    = (const float*)d_in[22];
    const float* b_ff2    = (const float*)d_in[23];
    const float* ln2g     = (const float*)d_in[24];
    const float* ln2b     = (const float*)d_in[25];
    const float* Wd1      = (const float*)d_in[26];
    const float* bd1      = (const float*)d_in[27];
    const float* Wd2      = (const float*)d_in[28];
    const float* bd2      = (const float*)d_in[29];
    const float* Wd3      = (const float*)d_in[30];
    const float* bd3      = (const float*)d_in[31];
    float* out = (float*)d_out;

    cudaFuncSetAttribute(k_gcnqkv, cudaFuncAttributeMaxDynamicSharedMemorySize, (int)sizeof(SG));
    cudaFuncSetAttribute(k_attnff, cudaFuncAttributeMaxDynamicSharedMemorySize, (int)sizeof(SAF2));
    cudaFuncSetAttribute(k_dec,    cudaFuncAttributeMaxDynamicSharedMemorySize, (int)sizeof(SDec5));

    k_zero_counts<<<(NN + 255) / 256, 256>>>();
    k_count<<<(MM + 255) / 256, 256>>>(ei);
    k_blockscan<<<NBLK, 1024>>>();
    k_scan2<<<1, 128>>>();
    k_apply<<<(NN + 255) / 256, 256>>>();
    k_fill<<<(MM + 255) / 256, 256>>>(ei);
    k_projck<<<NN / 4, 256>>>(x, W_proj, b_proj, u, useq);
    k_gcnqkv<<<1184, 384, sizeof(SG)>>>(W_gcn, b_gcn, Wk, bk, Wv, bv);
    k_attnff<<<592, 384, sizeof(SAF2)>>>(Wq, bq, Wo, bo, ln1g, ln1b, W_ff1, b_ff1,
                                         W_ff2, b_ff2, ln2g, ln2b, Wd1, bd1);
    k_dec<<<2048, 256, sizeof(SDec5)>>>(ei, eattr, eseq, Wd1, Wd2, bd2, Wd3, bd3, out);
}